// round 1
// baseline (speedup 1.0000x reference)
#include <cuda_runtime.h>
#include <cuda_bf16.h>
#include <math.h>

// ---------------------------------------------------------------------------
// Problem constants (fixed by the reference: B=2, S=2048, D=1024, H=16)
// ---------------------------------------------------------------------------
#define BATCH   2
#define SEQ     2048
#define DMODEL  1024
#define NHEADS  16
#define DHEAD   64
#define WINDOW  256
#define MROWS   (BATCH * SEQ)   // 4096

// Scratch (allocation-free rule: __device__ globals)
__device__ float g_q [MROWS * DMODEL];
__device__ float g_k [MROWS * DMODEL];
__device__ float g_v [MROWS * DMODEL];
__device__ float g_ao[MROWS * DMODEL];

// ---------------------------------------------------------------------------
// SGEMM: C[M,N] = A[M,K] @ B[K,N] + bias[N]
// 128x128 block tile, BK=16, 256 threads, 8x8 per-thread microtile.
// M % 128 == 0, N % 128 == 0, K % 16 == 0 (true for all 4 uses).
// ---------------------------------------------------------------------------
__global__ __launch_bounds__(256) void sgemm_bias(
    const float* __restrict__ A, const float* __restrict__ B,
    const float* __restrict__ bias, float* __restrict__ C,
    int M, int N, int K)
{
    const int BM = 128, BN = 128, BK = 16;
    __shared__ float As[BK][BM + 4];
    __shared__ float Bs[BK][BN + 4];

    const int tid  = threadIdx.x;
    const int brow = blockIdx.y * BM;
    const int bcol = blockIdx.x * BN;
    const int tm   = (tid / 16) * 8;
    const int tn   = (tid % 16) * 8;

    const float* Aptr = A + (size_t)brow * K;
    const float* Bptr = B + bcol;

    float acc[8][8];
#pragma unroll
    for (int i = 0; i < 8; i++)
#pragma unroll
        for (int j = 0; j < 8; j++) acc[i][j] = 0.f;

    for (int kt = 0; kt < K; kt += BK) {
        // A tile: 128 rows x 16 cols = 512 float4 -> 2 per thread, store transposed
#pragma unroll
        for (int u = 0; u < 2; u++) {
            int f  = tid + u * 256;
            int ar = f >> 2;
            int ac = (f & 3) * 4;
            float4 a4 = *(const float4*)(Aptr + (size_t)ar * K + kt + ac);
            As[ac + 0][ar] = a4.x;
            As[ac + 1][ar] = a4.y;
            As[ac + 2][ar] = a4.z;
            As[ac + 3][ar] = a4.w;
        }
        // B tile: 16 rows x 128 cols = 512 float4 -> 2 per thread
#pragma unroll
        for (int u = 0; u < 2; u++) {
            int f  = tid + u * 256;
            int br = f >> 5;
            int bc = (f & 31) * 4;
            float4 b4 = *(const float4*)(Bptr + (size_t)(kt + br) * N + bc);
            *(float4*)&Bs[br][bc] = b4;
        }
        __syncthreads();

#pragma unroll
        for (int kk = 0; kk < BK; kk++) {
            float a[8], b[8];
            *(float4*)&a[0] = *(const float4*)&As[kk][tm];
            *(float4*)&a[4] = *(const float4*)&As[kk][tm + 4];
            *(float4*)&b[0] = *(const float4*)&Bs[kk][tn];
            *(float4*)&b[4] = *(const float4*)&Bs[kk][tn + 4];
#pragma unroll
            for (int i = 0; i < 8; i++)
#pragma unroll
                for (int j = 0; j < 8; j++)
                    acc[i][j] += a[i] * b[j];
        }
        __syncthreads();
    }

    // epilogue: += bias, vectorized stores
#pragma unroll
    for (int i = 0; i < 8; i++) {
        size_t crow = (size_t)(brow + tm + i);
#pragma unroll
        for (int j = 0; j < 8; j += 4) {
            float4 o;
            o.x = acc[i][j + 0] + bias[bcol + tn + j + 0];
            o.y = acc[i][j + 1] + bias[bcol + tn + j + 1];
            o.z = acc[i][j + 2] + bias[bcol + tn + j + 2];
            o.w = acc[i][j + 3] + bias[bcol + tn + j + 3];
            *(float4*)&C[crow * N + bcol + tn + j] = o;
        }
    }
}

// ---------------------------------------------------------------------------
// Banded (sliding-window=256) attention, fp32 flash-style.
// grid = (S/64, H, B), block = 256 threads.
// Each block: 64 queries of one (b,h); iterates <=5 key-chunks of 64.
// Thread t: local query q = t/4; group g = t&3 covers keys [16g,16g+16) for
// scores and head-dims [16g,16g+16) for the PV accumulation.
// Q/K/V layout: [b*S + s][D] with head offset h*64 (projection output layout).
// ---------------------------------------------------------------------------
__global__ __launch_bounds__(256) void attn_kernel(
    const float* __restrict__ Q, const float* __restrict__ K,
    const float* __restrict__ V, float* __restrict__ O)
{
    extern __shared__ float sm[];
    float (*Qs)[65] = (float(*)[65])(sm);
    float (*Ks)[65] = (float(*)[65])(sm + 64 * 65);
    float (*Vs)[65] = (float(*)[65])(sm + 2 * 64 * 65);
    float (*Ps)[65] = (float(*)[65])(sm + 3 * 64 * 65);

    const int qt = blockIdx.x;
    const int h  = blockIdx.y;
    const int b  = blockIdx.z;
    const int q0 = qt * 64;

    const int tid = threadIdx.x;
    const int q   = tid >> 2;            // local query 0..63
    const int grp = tid & 3;             // 0..3
    const int k0l = grp * 16;            // key sub-range for scores
    const int dh0 = grp * 16;            // dh sub-range for PV accum
    const float scale = 0.125f;          // 1/sqrt(64)

    // load Q tile (coalesced: consecutive tid -> consecutive d)
    for (int i = tid; i < 64 * 64; i += 256) {
        int r = i >> 6, c = i & 63;
        Qs[r][c] = Q[((size_t)(b * SEQ + q0 + r)) * DMODEL + h * DHEAD + c];
    }

    float m = -1e30f, l = 0.f;
    float accv[16];
#pragma unroll
    for (int j = 0; j < 16; j++) accv[j] = 0.f;

    const int kb_lo = max(0, q0 - (WINDOW - 1)) >> 6;
    const int gq = q0 + q;

    for (int kb = kb_lo; kb <= qt; kb++) {
        __syncthreads();   // protect smem from previous iteration's readers (also covers Q load)
        const int kbase = kb * 64;
        for (int i = tid; i < 64 * 64; i += 256) {
            int r = i >> 6, c = i & 63;
            size_t gi = ((size_t)(b * SEQ + kbase + r)) * DMODEL + h * DHEAD + c;
            Ks[r][c] = K[gi];
            Vs[r][c] = V[gi];
        }
        __syncthreads();

        // scores: s[j] = Q[q,:] . K[k0l+j,:]   (outer-product order: 1 Q load / 16 FMA)
        float s[16];
#pragma unroll
        for (int j = 0; j < 16; j++) s[j] = 0.f;
#pragma unroll 8
        for (int d = 0; d < 64; d++) {
            float qd = Qs[q][d];
#pragma unroll
            for (int j = 0; j < 16; j++) s[j] += qd * Ks[k0l + j][d];
        }

        // mask + chunk max
        float cmax = -1e30f;
#pragma unroll
        for (int j = 0; j < 16; j++) {
            int dd = gq - (kbase + k0l + j);
            bool ok = (dd >= 0) && (dd < WINDOW);
            s[j] = ok ? s[j] * scale : -1e30f;
            cmax = fmaxf(cmax, s[j]);
        }
        cmax = fmaxf(cmax, __shfl_xor_sync(0xffffffffu, cmax, 1));
        cmax = fmaxf(cmax, __shfl_xor_sync(0xffffffffu, cmax, 2));

        float mnew  = fmaxf(m, cmax);
        float alpha = __expf(m - mnew);   // if both -1e30: alpha=1 but l=acc=0, harmless
        float csum  = 0.f;
#pragma unroll
        for (int j = 0; j < 16; j++) {
            float p = (s[j] > -1e29f) ? __expf(s[j] - mnew) : 0.f;
            s[j] = p;
            csum += p;
        }
        csum += __shfl_xor_sync(0xffffffffu, csum, 1);
        csum += __shfl_xor_sync(0xffffffffu, csum, 2);
        l = l * alpha + csum;
        m = mnew;

#pragma unroll
        for (int j = 0; j < 16; j++) Ps[q][k0l + j] = s[j];
#pragma unroll
        for (int j = 0; j < 16; j++) accv[j] *= alpha;
        __syncthreads();

        // PV: accv[j] += sum_k P[q][k] * V[k][dh0+j]
#pragma unroll 4
        for (int k = 0; k < 64; k++) {
            float p = Ps[q][k];
#pragma unroll
            for (int j = 0; j < 16; j++) accv[j] += p * Vs[k][dh0 + j];
        }
    }

    const float inv = 1.f / l;
    size_t obase = ((size_t)(b * SEQ + q0 + q)) * DMODEL + h * DHEAD + dh0;
#pragma unroll
    for (int j = 0; j < 16; j++) O[obase + j] = accv[j] * inv;
}

// ---------------------------------------------------------------------------
// Launch
// ---------------------------------------------------------------------------
extern "C" void kernel_launch(void* const* d_in, const int* in_sizes, int n_in,
                              void* d_out, int out_size)
{
    const float* X  = (const float*)d_in[0];
    const float* Wq = (const float*)d_in[1];
    const float* bq = (const float*)d_in[2];
    const float* Wk = (const float*)d_in[3];
    const float* bk = (const float*)d_in[4];
    const float* Wv = (const float*)d_in[5];
    const float* bv = (const float*)d_in[6];
    const float* Wo = (const float*)d_in[7];
    const float* bo = (const float*)d_in[8];
    float* out = (float*)d_out;

    float *q, *k, *v, *ao;
    cudaGetSymbolAddress((void**)&q,  g_q);
    cudaGetSymbolAddress((void**)&k,  g_k);
    cudaGetSymbolAddress((void**)&v,  g_v);
    cudaGetSymbolAddress((void**)&ao, g_ao);

    static bool attr_set = false;
    if (!attr_set) {
        cudaFuncSetAttribute(attn_kernel,
                             cudaFuncAttributeMaxDynamicSharedMemorySize,
                             4 * 64 * 65 * (int)sizeof(float));
        attr_set = true;
    }

    dim3 gg(DMODEL / 128, MROWS / 128);   // (8, 32)
    dim3 bb(256);

    sgemm_bias<<<gg, bb>>>(X,  Wq, bq, q,  MROWS, DMODEL, DMODEL);
    sgemm_bias<<<gg, bb>>>(X,  Wk, bk, k,  MROWS, DMODEL, DMODEL);
    sgemm_bias<<<gg, bb>>>(X,  Wv, bv, v,  MROWS, DMODEL, DMODEL);

    dim3 ga(SEQ / 64, NHEADS, BATCH);     // (32, 16, 2)
    attn_kernel<<<ga, bb, 4 * 64 * 65 * sizeof(float)>>>(q, k, v, ao);

    sgemm_bias<<<gg, bb>>>(ao, Wo, bo, out, MROWS, DMODEL, DMODEL);
}

// round 3
// speedup vs baseline: 2.6669x; 2.6669x over previous
#include <cuda_runtime.h>
#include <cuda_bf16.h>
#include <cstdint>
#include <math.h>

// ---------------------------------------------------------------------------
// Problem constants (B=2, S=2048, D=1024, H=16)
// ---------------------------------------------------------------------------
#define BATCH   2
#define SEQ     2048
#define DMODEL  1024
#define NHEADS  16
#define DHEAD   64
#define WINDOW  256
#define MROWS   (BATCH * SEQ)   // 4096

// ---------------------------------------------------------------------------
// Scratch (__device__ globals; allocation-free rule)
// ---------------------------------------------------------------------------
__device__ float          g_q   [MROWS * DMODEL];
__device__ float          g_k   [MROWS * DMODEL];
__device__ float          g_v   [MROWS * DMODEL];
__device__ float          g_ao  [MROWS * DMODEL];
__device__ __nv_bfloat16  g_xhi [MROWS * DMODEL];
__device__ __nv_bfloat16  g_xlo [MROWS * DMODEL];
__device__ __nv_bfloat16  g_aohi[MROWS * DMODEL];
__device__ __nv_bfloat16  g_aolo[MROWS * DMODEL];
__device__ __nv_bfloat16  g_wthi[4 * DMODEL * DMODEL];  // transposed weights [N][K]
__device__ __nv_bfloat16  g_wtlo[4 * DMODEL * DMODEL];

// ---------------------------------------------------------------------------
// PTX helpers — base sm_100 ISA only (mma.sync / ldmatrix / cp.async)
// ---------------------------------------------------------------------------
__device__ __forceinline__ uint32_t smem_u32(const void* p) {
    uint32_t a;
    asm("{ .reg .u64 t; cvta.to.shared.u64 t, %1; cvt.u32.u64 %0, t; }" : "=r"(a) : "l"(p));
    return a;
}

#define CP_ASYNC16(dst, src) \
    asm volatile("cp.async.cg.shared.global [%0], [%1], 16;" :: "r"(dst), "l"(src))
#define CP_COMMIT() asm volatile("cp.async.commit_group;" ::: "memory")
#define CP_WAIT(n)  asm volatile("cp.async.wait_group %0;" :: "n"(n) : "memory")

#define LDSM_X4(r0, r1, r2, r3, addr) \
    asm volatile("ldmatrix.sync.aligned.m8n8.x4.shared.b16 {%0,%1,%2,%3}, [%4];" \
        : "=r"(r0), "=r"(r1), "=r"(r2), "=r"(r3) : "r"(addr))

#define MMA16816(d, a0, a1, a2, a3, b0, b1) \
    asm volatile("mma.sync.aligned.m16n8k16.row.col.f32.bf16.bf16.f32 " \
        "{%0,%1,%2,%3}, {%4,%5,%6,%7}, {%8,%9}, {%0,%1,%2,%3};" \
        : "+f"((d)[0]), "+f"((d)[1]), "+f"((d)[2]), "+f"((d)[3]) \
        : "r"(a0), "r"(a1), "r"(a2), "r"(a3), "r"(b0), "r"(b1))

// ---------------------------------------------------------------------------
// fp32 -> (hi, lo) bf16 split, elementwise
// ---------------------------------------------------------------------------
__global__ __launch_bounds__(256) void split_kernel(
    const float* __restrict__ in, __nv_bfloat16* __restrict__ hi,
    __nv_bfloat16* __restrict__ lo, int n4)
{
    int i = blockIdx.x * blockDim.x + threadIdx.x;
    if (i >= n4) return;
    float4 v = ((const float4*)in)[i];
    float f[4] = {v.x, v.y, v.z, v.w};
    __nv_bfloat16 h[4], l[4];
#pragma unroll
    for (int j = 0; j < 4; j++) {
        h[j] = __float2bfloat16(f[j]);
        l[j] = __float2bfloat16(f[j] - __bfloat162float(h[j]));
    }
    ((__nv_bfloat162*)hi)[2*i]   = __nv_bfloat162(h[0], h[1]);
    ((__nv_bfloat162*)hi)[2*i+1] = __nv_bfloat162(h[2], h[3]);
    ((__nv_bfloat162*)lo)[2*i]   = __nv_bfloat162(l[0], l[1]);
    ((__nv_bfloat162*)lo)[2*i+1] = __nv_bfloat162(l[2], l[3]);
}

// ---------------------------------------------------------------------------
// W [K x N] fp32 -> transposed split bf16 [N x K]
// ---------------------------------------------------------------------------
__global__ __launch_bounds__(256) void transpose_split(
    const float* __restrict__ in, __nv_bfloat16* __restrict__ oh,
    __nv_bfloat16* __restrict__ ol)
{
    __shared__ float t[32][33];
    int bx = blockIdx.x * 32, by = blockIdx.y * 32;
    int tx = threadIdx.x, ty = threadIdx.y;
#pragma unroll
    for (int j = ty; j < 32; j += 8)
        t[j][tx] = in[(size_t)(by + j) * DMODEL + bx + tx];
    __syncthreads();
#pragma unroll
    for (int j = ty; j < 32; j += 8) {
        float v = t[tx][j];                 // = in[by+tx][bx+j]
        __nv_bfloat16 h = __float2bfloat16(v);
        __nv_bfloat16 l = __float2bfloat16(v - __bfloat162float(h));
        size_t o = (size_t)(bx + j) * DMODEL + by + tx;
        oh[o] = h; ol[o] = l;
    }
}

// ---------------------------------------------------------------------------
// Split-bf16 mma.sync GEMM: C[M,N] = (Ahi+Alo)[M,K] @ (Bhi+Blo)^T + bias
//   A: [M][K] bf16 K-major; Bt: [N][K] bf16 K-major.
//   128x128 CTA tile, BK=32, 256 threads (8 warps of 64x32 warp tiles),
//   2-stage cp.async pipeline. 3 mma passes: AhiBhi + AhiBlo + AloBhi.
// Smem per stage: 4 tiles of 128 rows x 80B (32 bf16 + 16B pad) = 40960 B.
// ---------------------------------------------------------------------------
#define G_RS      80          // row stride bytes (32 bf16 = 64B + 16B pad)
#define G_TILE_B  (128 * G_RS)
#define G_STAGE_B (4 * G_TILE_B)
#define G_SMEM_B  (2 * G_STAGE_B)

__global__ __launch_bounds__(256, 2) void gemm_mma(
    const __nv_bfloat16* __restrict__ Ahi, const __nv_bfloat16* __restrict__ Alo,
    const __nv_bfloat16* __restrict__ Bhi, const __nv_bfloat16* __restrict__ Blo,
    const float* __restrict__ bias, float* __restrict__ C, int M, int N, int K)
{
    extern __shared__ char smem[];
    const uint32_t sb = smem_u32(smem);
    const int tid = threadIdx.x, lane = tid & 31, wid = tid >> 5;
    const int brow = blockIdx.y * 128, bcol = blockIdx.x * 128;
    const int wm0 = (wid & 1) * 64;   // 2 warps along M
    const int wn0 = (wid >> 1) * 32;  // 4 warps along N

    float acc[4][4][4];
#pragma unroll
    for (int mi = 0; mi < 4; mi++)
#pragma unroll
        for (int ni = 0; ni < 4; ni++)
#pragma unroll
            for (int e = 0; e < 4; e++) acc[mi][ni][e] = 0.f;

    // per-thread load slots: f in [0,512): row = f>>2, 16B-chunk = f&3
    const int r0l = tid >> 2, c16a = (tid & 3) * 8;       // u=0
    const int r1l = (tid + 256) >> 2;                     // u=1 (same c16)

    const int nchunks = K / 32;

    auto issue_load = [&](int st, int kt) {
        uint32_t s0 = sb + st * G_STAGE_B;
        const __nv_bfloat16* ga;
        uint32_t d;
#pragma unroll
        for (int u = 0; u < 2; u++) {
            int row = u ? r1l : r0l;
            uint32_t so = row * G_RS + (c16a * 2) + (u ? 0 : 0);
            ga = Ahi + (size_t)(brow + row) * K + kt + c16a;
            d = s0 + 0 * G_TILE_B + so;           CP_ASYNC16(d, ga);
            ga = Alo + (size_t)(brow + row) * K + kt + c16a;
            d = s0 + 1 * G_TILE_B + so;           CP_ASYNC16(d, ga);
            ga = Bhi + (size_t)(bcol + row) * K + kt + c16a;
            d = s0 + 2 * G_TILE_B + so;           CP_ASYNC16(d, ga);
            ga = Blo + (size_t)(bcol + row) * K + kt + c16a;
            d = s0 + 3 * G_TILE_B + so;           CP_ASYNC16(d, ga);
        }
    };

    issue_load(0, 0);
    CP_COMMIT();

    for (int ch = 0; ch < nchunks; ch++) {
        if (ch + 1 < nchunks) {
            issue_load((ch + 1) & 1, (ch + 1) * 32);
            CP_COMMIT();
            CP_WAIT(1);
        } else {
            CP_WAIT(0);
        }
        __syncthreads();

        const uint32_t s0  = sb + (ch & 1) * G_STAGE_B;
        const uint32_t sAh = s0;
        const uint32_t sAl = s0 + G_TILE_B;
        const uint32_t sBh = s0 + 2 * G_TILE_B;
        const uint32_t sBl = s0 + 3 * G_TILE_B;

#pragma unroll
        for (int ks = 0; ks < 2; ks++) {
            const uint32_t kb = ks * 32;   // byte offset of k16 step

            // B fragments: 4 n-tiles (two x4 loads each for hi and lo)
            uint32_t bh[4][2], bl[4][2];
#pragma unroll
            for (int np = 0; np < 2; np++) {
                uint32_t ro = (wn0 + np * 16 + (lane & 7) + ((lane >> 4) & 1) * 8) * G_RS
                              + kb + ((lane >> 3) & 1) * 16;
                LDSM_X4(bh[np*2][0], bh[np*2][1], bh[np*2+1][0], bh[np*2+1][1], sBh + ro);
                LDSM_X4(bl[np*2][0], bl[np*2][1], bl[np*2+1][0], bl[np*2+1][1], sBl + ro);
            }

#pragma unroll
            for (int mi = 0; mi < 4; mi++) {
                uint32_t ro = (wm0 + mi * 16 + (lane & 15)) * G_RS + kb + (lane >> 4) * 16;
                uint32_t ah[4], al[4];
                LDSM_X4(ah[0], ah[1], ah[2], ah[3], sAh + ro);
                LDSM_X4(al[0], al[1], al[2], al[3], sAl + ro);
#pragma unroll
                for (int ni = 0; ni < 4; ni++) {
                    MMA16816(acc[mi][ni], ah[0], ah[1], ah[2], ah[3], bh[ni][0], bh[ni][1]);
                    MMA16816(acc[mi][ni], al[0], al[1], al[2], al[3], bh[ni][0], bh[ni][1]);
                    MMA16816(acc[mi][ni], ah[0], ah[1], ah[2], ah[3], bl[ni][0], bl[ni][1]);
                }
            }
        }
        __syncthreads();
    }

    // epilogue: each mma tile: rows lane/4 (+8), col pair 2*(lane%4)
#pragma unroll
    for (int mi = 0; mi < 4; mi++) {
#pragma unroll
        for (int ni = 0; ni < 4; ni++) {
            int r = brow + wm0 + mi * 16 + (lane >> 2);
            int c = bcol + wn0 + ni * 8 + (lane & 3) * 2;
            float bx = bias[c], by = bias[c + 1];
            float2 o0 = make_float2(acc[mi][ni][0] + bx, acc[mi][ni][1] + by);
            float2 o1 = make_float2(acc[mi][ni][2] + bx, acc[mi][ni][3] + by);
            *(float2*)&C[(size_t)r * N + c]       = o0;
            *(float2*)&C[(size_t)(r + 8) * N + c] = o1;
        }
    }
}

// ---------------------------------------------------------------------------
// Banded attention, fp32, 4x4 register microtile.
// grid = (S/64, H, B), block = 256.
// ---------------------------------------------------------------------------
#define AP 68   // padded row stride (floats), 16B-aligned

__global__ __launch_bounds__(256) void attn_kernel(
    const float* __restrict__ Q, const float* __restrict__ K,
    const float* __restrict__ V, float* __restrict__ O)
{
    extern __shared__ float sm[];
    float (*Qs)[AP] = (float(*)[AP])(sm);               // [q][d]
    float (*Kt)[AP] = (float(*)[AP])(sm + 64 * AP);     // [d][k]  (transposed)
    float (*Vs)[AP] = (float(*)[AP])(sm + 2 * 64 * AP); // [k][d]
    float (*Pt)[AP] = (float(*)[AP])(sm + 3 * 64 * AP); // [k][q]  (transposed)

    const int qt = blockIdx.x, h = blockIdx.y, b = blockIdx.z;
    const int q0 = qt * 64;
    const int tid = threadIdx.x;
    const int tq4 = (tid >> 4) * 4;   // first of 4 queries
    const int tk4 = (tid & 15) * 4;   // first of 4 keys / head-dims
    const float scale = 0.125f;

    for (int i = tid; i < 64 * 64; i += 256) {
        int r = i >> 6, c = i & 63;
        Qs[r][c] = Q[((size_t)(b * SEQ + q0 + r)) * DMODEL + h * DHEAD + c];
    }

    float m[4], l[4], acc[4][4];
#pragma unroll
    for (int qi = 0; qi < 4; qi++) {
        m[qi] = -1e30f; l[qi] = 0.f;
#pragma unroll
        for (int di = 0; di < 4; di++) acc[qi][di] = 0.f;
    }

    const int kb_lo = max(0, q0 - (WINDOW - 1)) >> 6;

    for (int kb = kb_lo; kb <= qt; kb++) {
        __syncthreads();
        const int kbase = kb * 64;
        for (int i = tid; i < 64 * 64; i += 256) {
            int r = i >> 6, c = i & 63;
            size_t gi = ((size_t)(b * SEQ + kbase + r)) * DMODEL + h * DHEAD + c;
            Kt[c][r] = K[gi];
            Vs[r][c] = V[gi];
        }
        __syncthreads();

        float s[4][4];
#pragma unroll
        for (int qi = 0; qi < 4; qi++)
#pragma unroll
            for (int ki = 0; ki < 4; ki++) s[qi][ki] = 0.f;
#pragma unroll 4
        for (int d = 0; d < 64; d++) {
            float4 kv = *(const float4*)&Kt[d][tk4];
            float qa0 = Qs[tq4 + 0][d], qa1 = Qs[tq4 + 1][d];
            float qa2 = Qs[tq4 + 2][d], qa3 = Qs[tq4 + 3][d];
            s[0][0] += qa0 * kv.x; s[0][1] += qa0 * kv.y; s[0][2] += qa0 * kv.z; s[0][3] += qa0 * kv.w;
            s[1][0] += qa1 * kv.x; s[1][1] += qa1 * kv.y; s[1][2] += qa1 * kv.z; s[1][3] += qa1 * kv.w;
            s[2][0] += qa2 * kv.x; s[2][1] += qa2 * kv.y; s[2][2] += qa2 * kv.z; s[2][3] += qa2 * kv.w;
            s[3][0] += qa3 * kv.x; s[3][1] += qa3 * kv.y; s[3][2] += qa3 * kv.z; s[3][3] += qa3 * kv.w;
        }

#pragma unroll
        for (int qi = 0; qi < 4; qi++) {
            const int gq = q0 + tq4 + qi;
            float cmax = -1e30f;
#pragma unroll
            for (int ki = 0; ki < 4; ki++) {
                int dd = gq - (kbase + tk4 + ki);
                bool ok = (dd >= 0) && (dd < WINDOW);
                s[qi][ki] = ok ? s[qi][ki] * scale : -1e30f;
                cmax = fmaxf(cmax, s[qi][ki]);
            }
            cmax = fmaxf(cmax, __shfl_xor_sync(0xffffffffu, cmax, 1));
            cmax = fmaxf(cmax, __shfl_xor_sync(0xffffffffu, cmax, 2));
            cmax = fmaxf(cmax, __shfl_xor_sync(0xffffffffu, cmax, 4));
            cmax = fmaxf(cmax, __shfl_xor_sync(0xffffffffu, cmax, 8));

            float mnew  = fmaxf(m[qi], cmax);
            float alpha = __expf(m[qi] - mnew);
            float csum = 0.f;
#pragma unroll
            for (int ki = 0; ki < 4; ki++) {
                float p = (s[qi][ki] > -1e29f) ? __expf(s[qi][ki] - mnew) : 0.f;
                s[qi][ki] = p;
                csum += p;
            }
            csum += __shfl_xor_sync(0xffffffffu, csum, 1);
            csum += __shfl_xor_sync(0xffffffffu, csum, 2);
            csum += __shfl_xor_sync(0xffffffffu, csum, 4);
            csum += __shfl_xor_sync(0xffffffffu, csum, 8);
            l[qi] = l[qi] * alpha + csum;
            m[qi] = mnew;
#pragma unroll
            for (int di = 0; di < 4; di++) acc[qi][di] *= alpha;
        }

#pragma unroll
        for (int ki = 0; ki < 4; ki++) {
            float4 w = make_float4(s[0][ki], s[1][ki], s[2][ki], s[3][ki]);
            *(float4*)&Pt[tk4 + ki][tq4] = w;
        }
        __syncthreads();

#pragma unroll 4
        for (int kk = 0; kk < 64; kk++) {
            float4 p  = *(const float4*)&Pt[kk][tq4];
            float4 vv = *(const float4*)&Vs[kk][tk4];
            acc[0][0] += p.x * vv.x; acc[0][1] += p.x * vv.y; acc[0][2] += p.x * vv.z; acc[0][3] += p.x * vv.w;
            acc[1][0] += p.y * vv.x; acc[1][1] += p.y * vv.y; acc[1][2] += p.y * vv.z; acc[1][3] += p.y * vv.w;
            acc[2][0] += p.z * vv.x; acc[2][1] += p.z * vv.y; acc[2][2] += p.z * vv.z; acc[2][3] += p.z * vv.w;
            acc[3][0] += p.w * vv.x; acc[3][1] += p.w * vv.y; acc[3][2] += p.w * vv.z; acc[3][3] += p.w * vv.w;
        }
    }

#pragma unroll
    for (int qi = 0; qi < 4; qi++) {
        const float inv = 1.f / l[qi];
        float4 o = make_float4(acc[qi][0] * inv, acc[qi][1] * inv, acc[qi][2] * inv, acc[qi][3] * inv);
        *(float4*)&O[((size_t)(b * SEQ + q0 + tq4 + qi)) * DMODEL + h * DHEAD + tk4] = o;
    }
}

// ---------------------------------------------------------------------------
// Launch
// ---------------------------------------------------------------------------
extern "C" void kernel_launch(void* const* d_in, const int* in_sizes, int n_in,
                              void* d_out, int out_size)
{
    const float* X  = (const float*)d_in[0];
    const float* Wq = (const float*)d_in[1];
    const float* bq = (const float*)d_in[2];
    const float* Wk = (const float*)d_in[3];
    const float* bk = (const float*)d_in[4];
    const float* Wv = (const float*)d_in[5];
    const float* bv = (const float*)d_in[6];
    const float* Wo = (const float*)d_in[7];
    const float* bo = (const float*)d_in[8];
    float* out = (float*)d_out;

    float *q, *k, *v, *ao;
    __nv_bfloat16 *xhi, *xlo, *aohi, *aolo, *wthi, *wtlo;
    cudaGetSymbolAddress((void**)&q,    g_q);
    cudaGetSymbolAddress((void**)&k,    g_k);
    cudaGetSymbolAddress((void**)&v,    g_v);
    cudaGetSymbolAddress((void**)&ao,   g_ao);
    cudaGetSymbolAddress((void**)&xhi,  g_xhi);
    cudaGetSymbolAddress((void**)&xlo,  g_xlo);
    cudaGetSymbolAddress((void**)&aohi, g_aohi);
    cudaGetSymbolAddress((void**)&aolo, g_aolo);
    cudaGetSymbolAddress((void**)&wthi, g_wthi);
    cudaGetSymbolAddress((void**)&wtlo, g_wtlo);

    cudaFuncSetAttribute(attn_kernel, cudaFuncAttributeMaxDynamicSharedMemorySize,
                         4 * 64 * AP * (int)sizeof(float));
    cudaFuncSetAttribute(gemm_mma, cudaFuncAttributeMaxDynamicSharedMemorySize, G_SMEM_B);

    const int DD = DMODEL * DMODEL;

    // 1. split X -> bf16 hi/lo
    split_kernel<<<(MROWS * DMODEL / 4 + 255) / 256, 256>>>(X, xhi, xlo, MROWS * DMODEL / 4);

    // 2. transpose+split the 4 weight matrices
    dim3 tb(32, 8), tg(32, 32);
    transpose_split<<<tg, tb>>>(Wq, wthi + 0 * DD, wtlo + 0 * DD);
    transpose_split<<<tg, tb>>>(Wk, wthi + 1 * DD, wtlo + 1 * DD);
    transpose_split<<<tg, tb>>>(Wv, wthi + 2 * DD, wtlo + 2 * DD);
    transpose_split<<<tg, tb>>>(Wo, wthi + 3 * DD, wtlo + 3 * DD);

    // 3. Q/K/V projections (tensor cores via mma.sync)
    dim3 gg(DMODEL / 128, MROWS / 128);  // (8, 32)
    gemm_mma<<<gg, 256, G_SMEM_B>>>(xhi, xlo, wthi + 0 * DD, wtlo + 0 * DD, bq, q, MROWS, DMODEL, DMODEL);
    gemm_mma<<<gg, 256, G_SMEM_B>>>(xhi, xlo, wthi + 1 * DD, wtlo + 1 * DD, bk, k, MROWS, DMODEL, DMODEL);
    gemm_mma<<<gg, 256, G_SMEM_B>>>(xhi, xlo, wthi + 2 * DD, wtlo + 2 * DD, bv, v, MROWS, DMODEL, DMODEL);

    // 4. banded attention
    dim3 ga(SEQ / 64, NHEADS, BATCH);
    attn_kernel<<<ga, 256, 4 * 64 * AP * sizeof(float)>>>(q, k, v, ao);

    // 5. split attention output, O projection
    split_kernel<<<(MROWS * DMODEL / 4 + 255) / 256, 256>>>(ao, aohi, aolo, MROWS * DMODEL / 4);
    gemm_mma<<<gg, 256, G_SMEM_B>>>(aohi, aolo, wthi + 3 * DD, wtlo + 3 * DD, bo, out, MROWS, DMODEL, DMODEL);
}

// round 4
// speedup vs baseline: 3.3154x; 1.2432x over previous
#include <cuda_runtime.h>
#include <cuda_bf16.h>
#include <cstdint>
#include <math.h>

// ---------------------------------------------------------------------------
// Problem constants (B=2, S=2048, D=1024, H=16)
// ---------------------------------------------------------------------------
#define BATCH   2
#define SEQ     2048
#define DMODEL  1024
#define NHEADS  16
#define DHEAD   64
#define WINDOW  256
#define MROWS   (BATCH * SEQ)   // 4096

// ---------------------------------------------------------------------------
// Scratch (__device__ globals; allocation-free rule)
// ---------------------------------------------------------------------------
__device__ __nv_bfloat16  g_xhi [MROWS * DMODEL];
__device__ __nv_bfloat16  g_xlo [MROWS * DMODEL];
__device__ __nv_bfloat16  g_qhi [MROWS * DMODEL];
__device__ __nv_bfloat16  g_qlo [MROWS * DMODEL];
__device__ __nv_bfloat16  g_khi [MROWS * DMODEL];
__device__ __nv_bfloat16  g_klo [MROWS * DMODEL];
__device__ __nv_bfloat16  g_vhi [MROWS * DMODEL];
__device__ __nv_bfloat16  g_vlo [MROWS * DMODEL];
__device__ __nv_bfloat16  g_aohi[MROWS * DMODEL];
__device__ __nv_bfloat16  g_aolo[MROWS * DMODEL];
__device__ __nv_bfloat16  g_wthi[4 * DMODEL * DMODEL];  // transposed weights [N][K]
__device__ __nv_bfloat16  g_wtlo[4 * DMODEL * DMODEL];

// ---------------------------------------------------------------------------
// PTX helpers — base sm_100 ISA only (mma.sync / ldmatrix / cp.async)
// ---------------------------------------------------------------------------
__device__ __forceinline__ uint32_t smem_u32(const void* p) {
    uint32_t a;
    asm("{ .reg .u64 t; cvta.to.shared.u64 t, %1; cvt.u32.u64 %0, t; }" : "=r"(a) : "l"(p));
    return a;
}

#define CP_ASYNC16(dst, src) \
    asm volatile("cp.async.cg.shared.global [%0], [%1], 16;" :: "r"(dst), "l"(src))
#define CP_COMMIT() asm volatile("cp.async.commit_group;" ::: "memory")
#define CP_WAIT(n)  asm volatile("cp.async.wait_group %0;" :: "n"(n) : "memory")

#define LDSM_X4(r0, r1, r2, r3, addr) \
    asm volatile("ldmatrix.sync.aligned.m8n8.x4.shared.b16 {%0,%1,%2,%3}, [%4];" \
        : "=r"(r0), "=r"(r1), "=r"(r2), "=r"(r3) : "r"(addr))

#define LDSM_X4_T(r0, r1, r2, r3, addr) \
    asm volatile("ldmatrix.sync.aligned.m8n8.x4.trans.shared.b16 {%0,%1,%2,%3}, [%4];" \
        : "=r"(r0), "=r"(r1), "=r"(r2), "=r"(r3) : "r"(addr))

#define MMA16816(d, a0, a1, a2, a3, b0, b1) \
    asm volatile("mma.sync.aligned.m16n8k16.row.col.f32.bf16.bf16.f32 " \
        "{%0,%1,%2,%3}, {%4,%5,%6,%7}, {%8,%9}, {%0,%1,%2,%3};" \
        : "+f"((d)[0]), "+f"((d)[1]), "+f"((d)[2]), "+f"((d)[3]) \
        : "r"(a0), "r"(a1), "r"(a2), "r"(a3), "r"(b0), "r"(b1))

// split a float pair into packed bf16x2 hi and lo (residual) fragments
__device__ __forceinline__ void split2(float x, float y, uint32_t& hi, uint32_t& lo) {
    __nv_bfloat16 hx = __float2bfloat16(x), hy = __float2bfloat16(y);
    __nv_bfloat162 h2(hx, hy);
    float rx = x - __bfloat162float(hx), ry = y - __bfloat162float(hy);
    __nv_bfloat162 l2(__float2bfloat16(rx), __float2bfloat16(ry));
    hi = *(uint32_t*)&h2;
    lo = *(uint32_t*)&l2;
}

// ---------------------------------------------------------------------------
// fp32 -> (hi, lo) bf16 split, elementwise
// ---------------------------------------------------------------------------
__global__ __launch_bounds__(256) void split_kernel(
    const float* __restrict__ in, __nv_bfloat16* __restrict__ hi,
    __nv_bfloat16* __restrict__ lo, int n4)
{
    int i = blockIdx.x * blockDim.x + threadIdx.x;
    if (i >= n4) return;
    float4 v = ((const float4*)in)[i];
    float f[4] = {v.x, v.y, v.z, v.w};
    __nv_bfloat16 h[4], l[4];
#pragma unroll
    for (int j = 0; j < 4; j++) {
        h[j] = __float2bfloat16(f[j]);
        l[j] = __float2bfloat16(f[j] - __bfloat162float(h[j]));
    }
    ((__nv_bfloat162*)hi)[2*i]   = __nv_bfloat162(h[0], h[1]);
    ((__nv_bfloat162*)hi)[2*i+1] = __nv_bfloat162(h[2], h[3]);
    ((__nv_bfloat162*)lo)[2*i]   = __nv_bfloat162(l[0], l[1]);
    ((__nv_bfloat162*)lo)[2*i+1] = __nv_bfloat162(l[2], l[3]);
}

// ---------------------------------------------------------------------------
// W [K x N] fp32 -> transposed split bf16 [N x K]
// ---------------------------------------------------------------------------
__global__ __launch_bounds__(256) void transpose_split(
    const float* __restrict__ in, __nv_bfloat16* __restrict__ oh,
    __nv_bfloat16* __restrict__ ol)
{
    __shared__ float t[32][33];
    int bx = blockIdx.x * 32, by = blockIdx.y * 32;
    int tx = threadIdx.x, ty = threadIdx.y;
#pragma unroll
    for (int j = ty; j < 32; j += 8)
        t[j][tx] = in[(size_t)(by + j) * DMODEL + bx + tx];
    __syncthreads();
#pragma unroll
    for (int j = ty; j < 32; j += 8) {
        float v = t[tx][j];                 // = in[by+tx][bx+j]
        __nv_bfloat16 h = __float2bfloat16(v);
        __nv_bfloat16 l = __float2bfloat16(v - __bfloat162float(h));
        size_t o = (size_t)(bx + j) * DMODEL + by + tx;
        oh[o] = h; ol[o] = l;
    }
}

// ---------------------------------------------------------------------------
// Split-bf16 mma.sync GEMM: C = (Ahi+Alo)[M,K] @ (Bhi+Blo)^T + bias
// 128x128 CTA tile, BK=32, 256 threads, 2-stage cp.async pipeline.
// SPLIT=true: write bf16 hi/lo outputs; SPLIT=false: write fp32.
// ---------------------------------------------------------------------------
#define G_RS      80          // row stride bytes (32 bf16 = 64B + 16B pad)
#define G_TILE_B  (128 * G_RS)
#define G_STAGE_B (4 * G_TILE_B)
#define G_SMEM_B  (2 * G_STAGE_B)

template<bool SPLIT>
__global__ __launch_bounds__(256, 2) void gemm_mma(
    const __nv_bfloat16* __restrict__ Ahi, const __nv_bfloat16* __restrict__ Alo,
    const __nv_bfloat16* __restrict__ Bhi, const __nv_bfloat16* __restrict__ Blo,
    const float* __restrict__ bias, float* __restrict__ C,
    __nv_bfloat16* __restrict__ Chi, __nv_bfloat16* __restrict__ Clo,
    int M, int N, int K)
{
    extern __shared__ char smem[];
    const uint32_t sb = smem_u32(smem);
    const int tid = threadIdx.x, lane = tid & 31, wid = tid >> 5;
    const int brow = blockIdx.y * 128, bcol = blockIdx.x * 128;
    const int wm0 = (wid & 1) * 64;   // 2 warps along M
    const int wn0 = (wid >> 1) * 32;  // 4 warps along N

    float acc[4][4][4];
#pragma unroll
    for (int mi = 0; mi < 4; mi++)
#pragma unroll
        for (int ni = 0; ni < 4; ni++)
#pragma unroll
            for (int e = 0; e < 4; e++) acc[mi][ni][e] = 0.f;

    const int r0l = tid >> 2, c16a = (tid & 3) * 8;
    const int r1l = (tid + 256) >> 2;

    const int nchunks = K / 32;

    auto issue_load = [&](int st, int kt) {
        uint32_t s0 = sb + st * G_STAGE_B;
        const __nv_bfloat16* ga;
        uint32_t d;
#pragma unroll
        for (int u = 0; u < 2; u++) {
            int row = u ? r1l : r0l;
            uint32_t so = row * G_RS + (c16a * 2);
            ga = Ahi + (size_t)(brow + row) * K + kt + c16a;
            d = s0 + 0 * G_TILE_B + so;           CP_ASYNC16(d, ga);
            ga = Alo + (size_t)(brow + row) * K + kt + c16a;
            d = s0 + 1 * G_TILE_B + so;           CP_ASYNC16(d, ga);
            ga = Bhi + (size_t)(bcol + row) * K + kt + c16a;
            d = s0 + 2 * G_TILE_B + so;           CP_ASYNC16(d, ga);
            ga = Blo + (size_t)(bcol + row) * K + kt + c16a;
            d = s0 + 3 * G_TILE_B + so;           CP_ASYNC16(d, ga);
        }
    };

    issue_load(0, 0);
    CP_COMMIT();

    for (int ch = 0; ch < nchunks; ch++) {
        if (ch + 1 < nchunks) {
            issue_load((ch + 1) & 1, (ch + 1) * 32);
            CP_COMMIT();
            CP_WAIT(1);
        } else {
            CP_WAIT(0);
        }
        __syncthreads();

        const uint32_t s0  = sb + (ch & 1) * G_STAGE_B;
        const uint32_t sAh = s0;
        const uint32_t sAl = s0 + G_TILE_B;
        const uint32_t sBh = s0 + 2 * G_TILE_B;
        const uint32_t sBl = s0 + 3 * G_TILE_B;

#pragma unroll
        for (int ks = 0; ks < 2; ks++) {
            const uint32_t kb = ks * 32;

            uint32_t bh[4][2], bl[4][2];
#pragma unroll
            for (int np = 0; np < 2; np++) {
                uint32_t ro = (wn0 + np * 16 + (lane & 7) + ((lane >> 4) & 1) * 8) * G_RS
                              + kb + ((lane >> 3) & 1) * 16;
                LDSM_X4(bh[np*2][0], bh[np*2][1], bh[np*2+1][0], bh[np*2+1][1], sBh + ro);
                LDSM_X4(bl[np*2][0], bl[np*2][1], bl[np*2+1][0], bl[np*2+1][1], sBl + ro);
            }

#pragma unroll
            for (int mi = 0; mi < 4; mi++) {
                uint32_t ro = (wm0 + mi * 16 + (lane & 15)) * G_RS + kb + (lane >> 4) * 16;
                uint32_t ah[4], al[4];
                LDSM_X4(ah[0], ah[1], ah[2], ah[3], sAh + ro);
                LDSM_X4(al[0], al[1], al[2], al[3], sAl + ro);
#pragma unroll
                for (int ni = 0; ni < 4; ni++) {
                    MMA16816(acc[mi][ni], ah[0], ah[1], ah[2], ah[3], bh[ni][0], bh[ni][1]);
                    MMA16816(acc[mi][ni], al[0], al[1], al[2], al[3], bh[ni][0], bh[ni][1]);
                    MMA16816(acc[mi][ni], ah[0], ah[1], ah[2], ah[3], bl[ni][0], bl[ni][1]);
                }
            }
        }
        __syncthreads();
    }

    // epilogue
#pragma unroll
    for (int mi = 0; mi < 4; mi++) {
#pragma unroll
        for (int ni = 0; ni < 4; ni++) {
            int r = brow + wm0 + mi * 16 + (lane >> 2);
            int c = bcol + wn0 + ni * 8 + (lane & 3) * 2;
            float bx = bias[c], by = bias[c + 1];
            float v0 = acc[mi][ni][0] + bx, v1 = acc[mi][ni][1] + by;
            float v2 = acc[mi][ni][2] + bx, v3 = acc[mi][ni][3] + by;
            if (SPLIT) {
                uint32_t h0, l0, h1, l1;
                split2(v0, v1, h0, l0);
                split2(v2, v3, h1, l1);
                *(uint32_t*)&Chi[(size_t)r * N + c]       = h0;
                *(uint32_t*)&Clo[(size_t)r * N + c]       = l0;
                *(uint32_t*)&Chi[(size_t)(r + 8) * N + c] = h1;
                *(uint32_t*)&Clo[(size_t)(r + 8) * N + c] = l1;
            } else {
                *(float2*)&C[(size_t)r * N + c]       = make_float2(v0, v1);
                *(float2*)&C[(size_t)(r + 8) * N + c] = make_float2(v2, v3);
            }
        }
    }
}

// ---------------------------------------------------------------------------
// Tensor-core banded attention (split-bf16, FA2-style).
// grid = (S/64, H, B), block = 128 (4 warps x 16 q-rows).
// K/V chunks of 64 keys, <=5 per q-tile, 2-stage cp.async pipeline.
// Consumes split-bf16 Q/K/V; emits split-bf16 attention output.
// ---------------------------------------------------------------------------
#define AT_RS    144                 // smem row stride bytes (72 bf16)
#define AT_TILE  (64 * AT_RS)        // 9216 B
#define AT_SQH   0
#define AT_SQL   AT_TILE
#define AT_ST0   (2 * AT_TILE)
#define AT_STB   (4 * AT_TILE)       // Kh, Kl, Vh, Vl per stage
#define AT_SMEM  (2 * AT_TILE + 2 * AT_STB)   // 92160 B

__global__ __launch_bounds__(128) void attn_tc(
    const __nv_bfloat16* __restrict__ Qh, const __nv_bfloat16* __restrict__ Ql,
    const __nv_bfloat16* __restrict__ Kh, const __nv_bfloat16* __restrict__ Kl,
    const __nv_bfloat16* __restrict__ Vh, const __nv_bfloat16* __restrict__ Vl,
    __nv_bfloat16* __restrict__ Oh, __nv_bfloat16* __restrict__ Ol)
{
    extern __shared__ char smem[];
    const uint32_t sb = smem_u32(smem);
    const int qt = blockIdx.x, h = blockIdx.y, b = blockIdx.z;
    const int q0 = qt * 64;
    const int tid = threadIdx.x, lane = tid & 31, w = tid >> 5;
    const float scale = 0.125f;

    // loader: thread t covers row t>>1, 64B half (t&1) of the 128B row
    const int lrow = tid >> 1;
    const int lhalf = (tid & 1) * 64;            // byte offset in smem row
    const int gcol = h * DHEAD + (lhalf >> 1);   // element offset in global row

    const int kb_lo = max(0, q0 - (WINDOW - 1)) >> 6;
    const int nch = qt - kb_lo + 1;

    // prologue: Q + first K/V chunk
    {
        size_t g = ((size_t)(b * SEQ + q0 + lrow)) * DMODEL + gcol;
        uint32_t so = lrow * AT_RS + lhalf;
#pragma unroll
        for (int i = 0; i < 4; i++) {
            CP_ASYNC16(sb + AT_SQH + so + i * 16, Qh + g + i * 8);
            CP_ASYNC16(sb + AT_SQL + so + i * 16, Ql + g + i * 8);
        }
        size_t gk = ((size_t)(b * SEQ + kb_lo * 64 + lrow)) * DMODEL + gcol;
        uint32_t s0 = sb + AT_ST0;
#pragma unroll
        for (int i = 0; i < 4; i++) {
            CP_ASYNC16(s0 + 0 * AT_TILE + so + i * 16, Kh + gk + i * 8);
            CP_ASYNC16(s0 + 1 * AT_TILE + so + i * 16, Kl + gk + i * 8);
            CP_ASYNC16(s0 + 2 * AT_TILE + so + i * 16, Vh + gk + i * 8);
            CP_ASYNC16(s0 + 3 * AT_TILE + so + i * 16, Vl + gk + i * 8);
        }
        CP_COMMIT();
    }

    float m0 = -1e30f, m1 = -1e30f, l0 = 0.f, l1 = 0.f;
    float oacc[8][4];
#pragma unroll
    for (int t = 0; t < 8; t++)
#pragma unroll
        for (int e = 0; e < 4; e++) oacc[t][e] = 0.f;

    const int r0g = q0 + w * 16 + (lane >> 2);
    const int r1g = r0g + 8;

    for (int i = 0; i < nch; i++) {
        const int kb = kb_lo + i;
        if (i + 1 < nch) {
            size_t gk = ((size_t)(b * SEQ + (kb + 1) * 64 + lrow)) * DMODEL + gcol;
            uint32_t s0 = sb + AT_ST0 + ((i + 1) & 1) * AT_STB;
            uint32_t so = lrow * AT_RS + lhalf;
#pragma unroll
            for (int u = 0; u < 4; u++) {
                CP_ASYNC16(s0 + 0 * AT_TILE + so + u * 16, Kh + gk + u * 8);
                CP_ASYNC16(s0 + 1 * AT_TILE + so + u * 16, Kl + gk + u * 8);
                CP_ASYNC16(s0 + 2 * AT_TILE + so + u * 16, Vh + gk + u * 8);
                CP_ASYNC16(s0 + 3 * AT_TILE + so + u * 16, Vl + gk + u * 8);
            }
            CP_COMMIT();
            CP_WAIT(1);
        } else {
            CP_WAIT(0);
        }
        __syncthreads();

        const uint32_t s0  = sb + AT_ST0 + (i & 1) * AT_STB;
        const uint32_t sKh = s0;
        const uint32_t sKl = s0 + AT_TILE;
        const uint32_t sVh = s0 + 2 * AT_TILE;
        const uint32_t sVl = s0 + 3 * AT_TILE;

        // ---- S = Q K^T (3-pass split bf16) ----
        float sacc[8][4];
#pragma unroll
        for (int t = 0; t < 8; t++)
#pragma unroll
            for (int e = 0; e < 4; e++) sacc[t][e] = 0.f;

#pragma unroll
        for (int ks = 0; ks < 4; ks++) {
            const uint32_t kbb = ks * 32;
            uint32_t aro = (w * 16 + (lane & 15)) * AT_RS + kbb + (lane >> 4) * 16;
            uint32_t ah[4], al[4];
            LDSM_X4(ah[0], ah[1], ah[2], ah[3], sb + AT_SQH + aro);
            LDSM_X4(al[0], al[1], al[2], al[3], sb + AT_SQL + aro);
#pragma unroll
            for (int np = 0; np < 4; np++) {
                uint32_t ro = (np * 16 + (lane & 7) + ((lane >> 4) & 1) * 8) * AT_RS
                              + kbb + ((lane >> 3) & 1) * 16;
                uint32_t bh[4], bl[4];
                LDSM_X4(bh[0], bh[1], bh[2], bh[3], sKh + ro);
                LDSM_X4(bl[0], bl[1], bl[2], bl[3], sKl + ro);
                MMA16816(sacc[2*np],   ah[0], ah[1], ah[2], ah[3], bh[0], bh[1]);
                MMA16816(sacc[2*np],   al[0], al[1], al[2], al[3], bh[0], bh[1]);
                MMA16816(sacc[2*np],   ah[0], ah[1], ah[2], ah[3], bl[0], bl[1]);
                MMA16816(sacc[2*np+1], ah[0], ah[1], ah[2], ah[3], bh[2], bh[3]);
                MMA16816(sacc[2*np+1], al[0], al[1], al[2], al[3], bh[2], bh[3]);
                MMA16816(sacc[2*np+1], ah[0], ah[1], ah[2], ah[3], bl[2], bl[3]);
            }
        }

        // ---- mask + online softmax ----
        const int kbase = kb * 64;
        float cmax0 = -1e30f, cmax1 = -1e30f;
#pragma unroll
        for (int t = 0; t < 8; t++) {
            const int c0 = kbase + t * 8 + 2 * (lane & 3);
            int d00 = r0g - c0, d01 = r0g - (c0 + 1);
            int d10 = r1g - c0, d11 = r1g - (c0 + 1);
            sacc[t][0] = (d00 >= 0 && d00 < WINDOW) ? sacc[t][0] * scale : -1e30f;
            sacc[t][1] = (d01 >= 0 && d01 < WINDOW) ? sacc[t][1] * scale : -1e30f;
            sacc[t][2] = (d10 >= 0 && d10 < WINDOW) ? sacc[t][2] * scale : -1e30f;
            sacc[t][3] = (d11 >= 0 && d11 < WINDOW) ? sacc[t][3] * scale : -1e30f;
            cmax0 = fmaxf(cmax0, fmaxf(sacc[t][0], sacc[t][1]));
            cmax1 = fmaxf(cmax1, fmaxf(sacc[t][2], sacc[t][3]));
        }
        cmax0 = fmaxf(cmax0, __shfl_xor_sync(0xffffffffu, cmax0, 1));
        cmax0 = fmaxf(cmax0, __shfl_xor_sync(0xffffffffu, cmax0, 2));
        cmax1 = fmaxf(cmax1, __shfl_xor_sync(0xffffffffu, cmax1, 1));
        cmax1 = fmaxf(cmax1, __shfl_xor_sync(0xffffffffu, cmax1, 2));

        float mn0 = fmaxf(m0, cmax0), mn1 = fmaxf(m1, cmax1);
        float a0 = __expf(m0 - mn0), a1 = __expf(m1 - mn1);
        float rs0 = 0.f, rs1 = 0.f;
#pragma unroll
        for (int t = 0; t < 8; t++) {
            sacc[t][0] = __expf(sacc[t][0] - mn0);
            sacc[t][1] = __expf(sacc[t][1] - mn0);
            sacc[t][2] = __expf(sacc[t][2] - mn1);
            sacc[t][3] = __expf(sacc[t][3] - mn1);
            rs0 += sacc[t][0] + sacc[t][1];
            rs1 += sacc[t][2] + sacc[t][3];
        }
        rs0 += __shfl_xor_sync(0xffffffffu, rs0, 1);
        rs0 += __shfl_xor_sync(0xffffffffu, rs0, 2);
        rs1 += __shfl_xor_sync(0xffffffffu, rs1, 1);
        rs1 += __shfl_xor_sync(0xffffffffu, rs1, 2);
        l0 = l0 * a0 + rs0;  m0 = mn0;
        l1 = l1 * a1 + rs1;  m1 = mn1;
#pragma unroll
        for (int t = 0; t < 8; t++) {
            oacc[t][0] *= a0; oacc[t][1] *= a0;
            oacc[t][2] *= a1; oacc[t][3] *= a1;
        }

        // ---- PV (3-pass split bf16; V fragments via ldmatrix.trans) ----
#pragma unroll
        for (int ks = 0; ks < 4; ks++) {
            uint32_t aph[4], apl[4];
            split2(sacc[2*ks][0],   sacc[2*ks][1],   aph[0], apl[0]);
            split2(sacc[2*ks][2],   sacc[2*ks][3],   aph[1], apl[1]);
            split2(sacc[2*ks+1][0], sacc[2*ks+1][1], aph[2], apl[2]);
            split2(sacc[2*ks+1][2], sacc[2*ks+1][3], aph[3], apl[3]);
#pragma unroll
            for (int np = 0; np < 4; np++) {
                uint32_t vro = (ks * 16 + (lane & 7) + ((lane >> 3) & 1) * 8) * AT_RS
                               + np * 32 + (lane >> 4) * 16;
                uint32_t vh[4], vl[4];
                LDSM_X4_T(vh[0], vh[1], vh[2], vh[3], sVh + vro);
                LDSM_X4_T(vl[0], vl[1], vl[2], vl[3], sVl + vro);
                MMA16816(oacc[2*np],   aph[0], aph[1], aph[2], aph[3], vh[0], vh[1]);
                MMA16816(oacc[2*np],   apl[0], apl[1], apl[2], apl[3], vh[0], vh[1]);
                MMA16816(oacc[2*np],   aph[0], aph[1], aph[2], aph[3], vl[0], vl[1]);
                MMA16816(oacc[2*np+1], aph[0], aph[1], aph[2], aph[3], vh[2], vh[3]);
                MMA16816(oacc[2*np+1], apl[0], apl[1], apl[2], apl[3], vh[2], vh[3]);
                MMA16816(oacc[2*np+1], aph[0], aph[1], aph[2], aph[3], vl[2], vl[3]);
            }
        }
        __syncthreads();   // protect stage from next iteration's loads
    }

    // ---- epilogue: divide by l, split to bf16 hi/lo, store ----
    const float inv0 = 1.f / l0, inv1 = 1.f / l1;
    const size_t row0 = (size_t)(b * SEQ + r0g) * DMODEL;
    const size_t row1 = (size_t)(b * SEQ + r1g) * DMODEL;
#pragma unroll
    for (int t = 0; t < 8; t++) {
        const int c = h * DHEAD + t * 8 + 2 * (lane & 3);
        uint32_t h0, lo0, h1, lo1;
        split2(oacc[t][0] * inv0, oacc[t][1] * inv0, h0, lo0);
        split2(oacc[t][2] * inv1, oacc[t][3] * inv1, h1, lo1);
        *(uint32_t*)&Oh[row0 + c] = h0;
        *(uint32_t*)&Ol[row0 + c] = lo0;
        *(uint32_t*)&Oh[row1 + c] = h1;
        *(uint32_t*)&Ol[row1 + c] = lo1;
    }
}

// ---------------------------------------------------------------------------
// Launch
// ---------------------------------------------------------------------------
extern "C" void kernel_launch(void* const* d_in, const int* in_sizes, int n_in,
                              void* d_out, int out_size)
{
    const float* X  = (const float*)d_in[0];
    const float* Wq = (const float*)d_in[1];
    const float* bq = (const float*)d_in[2];
    const float* Wk = (const float*)d_in[3];
    const float* bk = (const float*)d_in[4];
    const float* Wv = (const float*)d_in[5];
    const float* bv = (const float*)d_in[6];
    const float* Wo = (const float*)d_in[7];
    const float* bo = (const float*)d_in[8];
    float* out = (float*)d_out;

    __nv_bfloat16 *xhi, *xlo, *qhi, *qlo, *khi, *klo, *vhi, *vlo, *aohi, *aolo, *wthi, *wtlo;
    cudaGetSymbolAddress((void**)&xhi,  g_xhi);
    cudaGetSymbolAddress((void**)&xlo,  g_xlo);
    cudaGetSymbolAddress((void**)&qhi,  g_qhi);
    cudaGetSymbolAddress((void**)&qlo,  g_qlo);
    cudaGetSymbolAddress((void**)&khi,  g_khi);
    cudaGetSymbolAddress((void**)&klo,  g_klo);
    cudaGetSymbolAddress((void**)&vhi,  g_vhi);
    cudaGetSymbolAddress((void**)&vlo,  g_vlo);
    cudaGetSymbolAddress((void**)&aohi, g_aohi);
    cudaGetSymbolAddress((void**)&aolo, g_aolo);
    cudaGetSymbolAddress((void**)&wthi, g_wthi);
    cudaGetSymbolAddress((void**)&wtlo, g_wtlo);

    cudaFuncSetAttribute(attn_tc, cudaFuncAttributeMaxDynamicSharedMemorySize, AT_SMEM);
    cudaFuncSetAttribute(gemm_mma<true>,  cudaFuncAttributeMaxDynamicSharedMemorySize, G_SMEM_B);
    cudaFuncSetAttribute(gemm_mma<false>, cudaFuncAttributeMaxDynamicSharedMemorySize, G_SMEM_B);

    const int DD = DMODEL * DMODEL;

    // 1. split X -> bf16 hi/lo
    split_kernel<<<(MROWS * DMODEL / 4 + 255) / 256, 256>>>(X, xhi, xlo, MROWS * DMODEL / 4);

    // 2. transpose+split the 4 weight matrices
    dim3 tb(32, 8), tg(32, 32);
    transpose_split<<<tg, tb>>>(Wq, wthi + 0 * DD, wtlo + 0 * DD);
    transpose_split<<<tg, tb>>>(Wk, wthi + 1 * DD, wtlo + 1 * DD);
    transpose_split<<<tg, tb>>>(Wv, wthi + 2 * DD, wtlo + 2 * DD);
    transpose_split<<<tg, tb>>>(Wo, wthi + 3 * DD, wtlo + 3 * DD);

    // 3. Q/K/V projections -> split bf16 outputs
    dim3 gg(DMODEL / 128, MROWS / 128);
    gemm_mma<true><<<gg, 256, G_SMEM_B>>>(xhi, xlo, wthi + 0 * DD, wtlo + 0 * DD, bq,
                                          nullptr, qhi, qlo, MROWS, DMODEL, DMODEL);
    gemm_mma<true><<<gg, 256, G_SMEM_B>>>(xhi, xlo, wthi + 1 * DD, wtlo + 1 * DD, bk,
                                          nullptr, khi, klo, MROWS, DMODEL, DMODEL);
    gemm_mma<true><<<gg, 256, G_SMEM_B>>>(xhi, xlo, wthi + 2 * DD, wtlo + 2 * DD, bv,
                                          nullptr, vhi, vlo, MROWS, DMODEL, DMODEL);

    // 4. tensor-core banded attention -> split bf16 output
    dim3 ga(SEQ / 64, NHEADS, BATCH);
    attn_tc<<<ga, 128, AT_SMEM>>>(qhi, qlo, khi, klo, vhi, vlo, aohi, aolo);

    // 5. O projection -> fp32 final output
    gemm_mma<false><<<gg, 256, G_SMEM_B>>>(aohi, aolo, wthi + 3 * DD, wtlo + 3 * DD, bo,
                                           out, nullptr, nullptr, MROWS, DMODEL, DMODEL);
}

// round 5
// speedup vs baseline: 4.5525x; 1.3732x over previous
#include <cuda_runtime.h>
#include <cuda_fp16.h>
#include <cstdint>
#include <math.h>

// ---------------------------------------------------------------------------
// Problem constants (B=2, S=2048, D=1024, H=16)
// ---------------------------------------------------------------------------
#define BATCH   2
#define SEQ     2048
#define DMODEL  1024
#define NHEADS  16
#define DHEAD   64
#define WINDOW  256
#define MROWS   (BATCH * SEQ)   // 4096
#define DD      (DMODEL * DMODEL)

// ---------------------------------------------------------------------------
// Scratch (__device__ globals; allocation-free rule)
// ---------------------------------------------------------------------------
__device__ __half g_xhi [MROWS * DMODEL];
__device__ __half g_xlo [MROWS * DMODEL];
__device__ __half g_qhi [MROWS * DMODEL];
__device__ __half g_qlo [MROWS * DMODEL];
__device__ __half g_khi [MROWS * DMODEL];
__device__ __half g_vhi [MROWS * DMODEL];
__device__ __half g_aohi[MROWS * DMODEL];
__device__ __half g_aolo[MROWS * DMODEL];
__device__ __half g_wthi[4 * DD];   // transposed weights [N][K], fp16 hi
__device__ __half g_wtlo[DD];       // lo residual, Wo only

// ---------------------------------------------------------------------------
// PTX helpers — base sm_100 ISA only (mma.sync / ldmatrix / cp.async)
// ---------------------------------------------------------------------------
__device__ __forceinline__ uint32_t smem_u32(const void* p) {
    uint32_t a;
    asm("{ .reg .u64 t; cvta.to.shared.u64 t, %1; cvt.u32.u64 %0, t; }" : "=r"(a) : "l"(p));
    return a;
}

#define CP_ASYNC16(dst, src) \
    asm volatile("cp.async.cg.shared.global [%0], [%1], 16;" :: "r"(dst), "l"(src))
#define CP_COMMIT() asm volatile("cp.async.commit_group;" ::: "memory")
#define CP_WAIT(n)  asm volatile("cp.async.wait_group %0;" :: "n"(n) : "memory")

#define LDSM_X4(r0, r1, r2, r3, addr) \
    asm volatile("ldmatrix.sync.aligned.m8n8.x4.shared.b16 {%0,%1,%2,%3}, [%4];" \
        : "=r"(r0), "=r"(r1), "=r"(r2), "=r"(r3) : "r"(addr))

#define LDSM_X4_T(r0, r1, r2, r3, addr) \
    asm volatile("ldmatrix.sync.aligned.m8n8.x4.trans.shared.b16 {%0,%1,%2,%3}, [%4];" \
        : "=r"(r0), "=r"(r1), "=r"(r2), "=r"(r3) : "r"(addr))

#define MMA16816(d, a0, a1, a2, a3, b0, b1) \
    asm volatile("mma.sync.aligned.m16n8k16.row.col.f32.f16.f16.f32 " \
        "{%0,%1,%2,%3}, {%4,%5,%6,%7}, {%8,%9}, {%0,%1,%2,%3};" \
        : "+f"((d)[0]), "+f"((d)[1]), "+f"((d)[2]), "+f"((d)[3]) \
        : "r"(a0), "r"(a1), "r"(a2), "r"(a3), "r"(b0), "r"(b1))

// split a float pair into packed fp16x2 hi and lo (residual)
__device__ __forceinline__ void split2h(float x, float y, uint32_t& hi, uint32_t& lo) {
    __half hx = __float2half_rn(x), hy = __float2half_rn(y);
    __half2 h2(hx, hy);
    float rx = x - __half2float(hx), ry = y - __half2float(hy);
    __half2 l2(__float2half_rn(rx), __float2half_rn(ry));
    hi = *(uint32_t*)&h2;
    lo = *(uint32_t*)&l2;
}
__device__ __forceinline__ uint32_t pack2h(float x, float y) {
    __half2 h2(__float2half_rn(x), __float2half_rn(y));
    return *(uint32_t*)&h2;
}

// ---------------------------------------------------------------------------
// fp32 -> (hi, lo) fp16 split, elementwise
// ---------------------------------------------------------------------------
__global__ __launch_bounds__(256) void split_kernel(
    const float* __restrict__ in, __half* __restrict__ hi,
    __half* __restrict__ lo, int n4)
{
    int i = blockIdx.x * blockDim.x + threadIdx.x;
    if (i >= n4) return;
    float4 v = ((const float4*)in)[i];
    uint32_t h0, l0, h1, l1;
    split2h(v.x, v.y, h0, l0);
    split2h(v.z, v.w, h1, l1);
    ((uint32_t*)hi)[2*i]   = h0;
    ((uint32_t*)hi)[2*i+1] = h1;
    ((uint32_t*)lo)[2*i]   = l0;
    ((uint32_t*)lo)[2*i+1] = l1;
}

// ---------------------------------------------------------------------------
// All 4 weights: [K x N] fp32 -> transposed fp16 [N x K]; lo residual for Wo.
// grid (32, 32, 4), block (32, 8)
// ---------------------------------------------------------------------------
__global__ __launch_bounds__(256) void transpose_split4(
    const float* __restrict__ w0, const float* __restrict__ w1,
    const float* __restrict__ w2, const float* __restrict__ w3,
    __half* __restrict__ hi, __half* __restrict__ lo)
{
    __shared__ float t[32][33];
    const int z = blockIdx.z;
    const float* in = (z == 0) ? w0 : (z == 1) ? w1 : (z == 2) ? w2 : w3;
    __half* oh = hi + (size_t)z * DD;
    int bx = blockIdx.x * 32, by = blockIdx.y * 32;
    int tx = threadIdx.x, ty = threadIdx.y;
#pragma unroll
    for (int j = ty; j < 32; j += 8)
        t[j][tx] = in[(size_t)(by + j) * DMODEL + bx + tx];
    __syncthreads();
#pragma unroll
    for (int j = ty; j < 32; j += 8) {
        float v = t[tx][j];                 // = in[by+tx][bx+j]
        __half h = __float2half_rn(v);
        size_t o = (size_t)(bx + j) * DMODEL + by + tx;
        oh[o] = h;
        if (z == 3) lo[o] = __float2half_rn(v - __half2float(h));
    }
}

// ---------------------------------------------------------------------------
// QKV GEMM (2-pass fp16): C = (Ahi+Alo)[M,K] @ Bh^T + bias
// grid (N/128, M/128, 3): z selects W/bias/output. 3-stage cp.async pipeline.
// z==0 (Q): write hi+lo. z==1 (K), z==2 (V): write hi only.
// ---------------------------------------------------------------------------
#define G_RS       80          // row stride bytes (32 fp16 = 64B + 16B pad)
#define G_TILE_B   (128 * G_RS)          // 10240
#define Q_STAGE_B  (3 * G_TILE_B)        // Ah, Al, Bh
#define Q_SMEM_B   (3 * Q_STAGE_B)       // 92160

__global__ __launch_bounds__(256, 2) void gemm_qkv(
    const __half* __restrict__ Ahi, const __half* __restrict__ Alo,
    const __half* __restrict__ Wt,
    const float* __restrict__ bq, const float* __restrict__ bk,
    const float* __restrict__ bv,
    __half* __restrict__ Qhi, __half* __restrict__ Qlo,
    __half* __restrict__ Khi, __half* __restrict__ Vhi,
    int M, int N, int K)
{
    extern __shared__ char smem[];
    const uint32_t sb = smem_u32(smem);
    const int z = blockIdx.z;
    const __half* Bh = Wt + (size_t)z * DD;
    const float* bias = (z == 0) ? bq : (z == 1) ? bk : bv;
    __half* Chi = (z == 0) ? Qhi : (z == 1) ? Khi : Vhi;

    const int tid = threadIdx.x, lane = tid & 31, wid = tid >> 5;
    const int brow = blockIdx.y * 128, bcol = blockIdx.x * 128;
    const int wm0 = (wid & 1) * 64;
    const int wn0 = (wid >> 1) * 32;

    float acc[4][4][4];
#pragma unroll
    for (int mi = 0; mi < 4; mi++)
#pragma unroll
        for (int ni = 0; ni < 4; ni++)
#pragma unroll
            for (int e = 0; e < 4; e++) acc[mi][ni][e] = 0.f;

    const int r0l = tid >> 2, c16a = (tid & 3) * 8;
    const int r1l = (tid + 256) >> 2;
    const int nchunks = K / 32;

    auto issue_load = [&](int st, int kt) {
        uint32_t s0 = sb + st * Q_STAGE_B;
#pragma unroll
        for (int u = 0; u < 2; u++) {
            int row = u ? r1l : r0l;
            uint32_t so = row * G_RS + c16a * 2;
            CP_ASYNC16(s0 + 0 * G_TILE_B + so, Ahi + (size_t)(brow + row) * K + kt + c16a);
            CP_ASYNC16(s0 + 1 * G_TILE_B + so, Alo + (size_t)(brow + row) * K + kt + c16a);
            CP_ASYNC16(s0 + 2 * G_TILE_B + so, Bh  + (size_t)(bcol + row) * K + kt + c16a);
        }
    };

    issue_load(0, 0);  CP_COMMIT();
    issue_load(1, 32); CP_COMMIT();

    for (int ch = 0; ch < nchunks; ch++) {
        if (ch + 2 < nchunks) {
            issue_load((ch + 2) % 3, (ch + 2) * 32);
            CP_COMMIT();
            CP_WAIT(2);
        } else if (ch + 1 < nchunks) {
            CP_WAIT(1);
        } else {
            CP_WAIT(0);
        }
        __syncthreads();

        const uint32_t s0  = sb + (ch % 3) * Q_STAGE_B;
        const uint32_t sAh = s0;
        const uint32_t sAl = s0 + G_TILE_B;
        const uint32_t sBh = s0 + 2 * G_TILE_B;

#pragma unroll
        for (int ks = 0; ks < 2; ks++) {
            const uint32_t kb = ks * 32;
            uint32_t bh[4][2];
#pragma unroll
            for (int np = 0; np < 2; np++) {
                uint32_t ro = (wn0 + np * 16 + (lane & 7) + ((lane >> 4) & 1) * 8) * G_RS
                              + kb + ((lane >> 3) & 1) * 16;
                LDSM_X4(bh[np*2][0], bh[np*2][1], bh[np*2+1][0], bh[np*2+1][1], sBh + ro);
            }
#pragma unroll
            for (int mi = 0; mi < 4; mi++) {
                uint32_t ro = (wm0 + mi * 16 + (lane & 15)) * G_RS + kb + (lane >> 4) * 16;
                uint32_t ah[4], al[4];
                LDSM_X4(ah[0], ah[1], ah[2], ah[3], sAh + ro);
                LDSM_X4(al[0], al[1], al[2], al[3], sAl + ro);
#pragma unroll
                for (int ni = 0; ni < 4; ni++) {
                    MMA16816(acc[mi][ni], ah[0], ah[1], ah[2], ah[3], bh[ni][0], bh[ni][1]);
                    MMA16816(acc[mi][ni], al[0], al[1], al[2], al[3], bh[ni][0], bh[ni][1]);
                }
            }
        }
        __syncthreads();
    }

    // epilogue
    __half* Clo = Qlo;
#pragma unroll
    for (int mi = 0; mi < 4; mi++) {
#pragma unroll
        for (int ni = 0; ni < 4; ni++) {
            int r = brow + wm0 + mi * 16 + (lane >> 2);
            int c = bcol + wn0 + ni * 8 + (lane & 3) * 2;
            float bx = bias[c], by = bias[c + 1];
            float v0 = acc[mi][ni][0] + bx, v1 = acc[mi][ni][1] + by;
            float v2 = acc[mi][ni][2] + bx, v3 = acc[mi][ni][3] + by;
            if (z == 0) {
                uint32_t h0, l0, h1, l1;
                split2h(v0, v1, h0, l0);
                split2h(v2, v3, h1, l1);
                *(uint32_t*)&Chi[(size_t)r * N + c]       = h0;
                *(uint32_t*)&Clo[(size_t)r * N + c]       = l0;
                *(uint32_t*)&Chi[(size_t)(r + 8) * N + c] = h1;
                *(uint32_t*)&Clo[(size_t)(r + 8) * N + c] = l1;
            } else {
                *(uint32_t*)&Chi[(size_t)r * N + c]       = pack2h(v0, v1);
                *(uint32_t*)&Chi[(size_t)(r + 8) * N + c] = pack2h(v2, v3);
            }
        }
    }
}

// ---------------------------------------------------------------------------
// O-projection GEMM (3-pass fp16, both operands split): fp32 output.
// 128x128 CTA tile, BK=32, 2-stage pipeline. (Unchanged structure from R4.)
// ---------------------------------------------------------------------------
#define O_STAGE_B (4 * G_TILE_B)
#define O_SMEM_B  (2 * O_STAGE_B)

__global__ __launch_bounds__(256, 2) void gemm_o(
    const __half* __restrict__ Ahi, const __half* __restrict__ Alo,
    const __half* __restrict__ Bhi, const __half* __restrict__ Blo,
    const float* __restrict__ bias, float* __restrict__ C,
    int M, int N, int K)
{
    extern __shared__ char smem[];
    const uint32_t sb = smem_u32(smem);
    const int tid = threadIdx.x, lane = tid & 31, wid = tid >> 5;
    const int brow = blockIdx.y * 128, bcol = blockIdx.x * 128;
    const int wm0 = (wid & 1) * 64;
    const int wn0 = (wid >> 1) * 32;

    float acc[4][4][4];
#pragma unroll
    for (int mi = 0; mi < 4; mi++)
#pragma unroll
        for (int ni = 0; ni < 4; ni++)
#pragma unroll
            for (int e = 0; e < 4; e++) acc[mi][ni][e] = 0.f;

    const int r0l = tid >> 2, c16a = (tid & 3) * 8;
    const int r1l = (tid + 256) >> 2;
    const int nchunks = K / 32;

    auto issue_load = [&](int st, int kt) {
        uint32_t s0 = sb + st * O_STAGE_B;
#pragma unroll
        for (int u = 0; u < 2; u++) {
            int row = u ? r1l : r0l;
            uint32_t so = row * G_RS + c16a * 2;
            CP_ASYNC16(s0 + 0 * G_TILE_B + so, Ahi + (size_t)(brow + row) * K + kt + c16a);
            CP_ASYNC16(s0 + 1 * G_TILE_B + so, Alo + (size_t)(brow + row) * K + kt + c16a);
            CP_ASYNC16(s0 + 2 * G_TILE_B + so, Bhi + (size_t)(bcol + row) * K + kt + c16a);
            CP_ASYNC16(s0 + 3 * G_TILE_B + so, Blo + (size_t)(bcol + row) * K + kt + c16a);
        }
    };

    issue_load(0, 0);
    CP_COMMIT();

    for (int ch = 0; ch < nchunks; ch++) {
        if (ch + 1 < nchunks) {
            issue_load((ch + 1) & 1, (ch + 1) * 32);
            CP_COMMIT();
            CP_WAIT(1);
        } else {
            CP_WAIT(0);
        }
        __syncthreads();

        const uint32_t s0  = sb + (ch & 1) * O_STAGE_B;
        const uint32_t sAh = s0;
        const uint32_t sAl = s0 + G_TILE_B;
        const uint32_t sBh = s0 + 2 * G_TILE_B;
        const uint32_t sBl = s0 + 3 * G_TILE_B;

#pragma unroll
        for (int ks = 0; ks < 2; ks++) {
            const uint32_t kb = ks * 32;
            uint32_t bh[4][2], bl[4][2];
#pragma unroll
            for (int np = 0; np < 2; np++) {
                uint32_t ro = (wn0 + np * 16 + (lane & 7) + ((lane >> 4) & 1) * 8) * G_RS
                              + kb + ((lane >> 3) & 1) * 16;
                LDSM_X4(bh[np*2][0], bh[np*2][1], bh[np*2+1][0], bh[np*2+1][1], sBh + ro);
                LDSM_X4(bl[np*2][0], bl[np*2][1], bl[np*2+1][0], bl[np*2+1][1], sBl + ro);
            }
#pragma unroll
            for (int mi = 0; mi < 4; mi++) {
                uint32_t ro = (wm0 + mi * 16 + (lane & 15)) * G_RS + kb + (lane >> 4) * 16;
                uint32_t ah[4], al[4];
                LDSM_X4(ah[0], ah[1], ah[2], ah[3], sAh + ro);
                LDSM_X4(al[0], al[1], al[2], al[3], sAl + ro);
#pragma unroll
                for (int ni = 0; ni < 4; ni++) {
                    MMA16816(acc[mi][ni], ah[0], ah[1], ah[2], ah[3], bh[ni][0], bh[ni][1]);
                    MMA16816(acc[mi][ni], al[0], al[1], al[2], al[3], bh[ni][0], bh[ni][1]);
                    MMA16816(acc[mi][ni], ah[0], ah[1], ah[2], ah[3], bl[ni][0], bl[ni][1]);
                }
            }
        }
        __syncthreads();
    }

#pragma unroll
    for (int mi = 0; mi < 4; mi++) {
#pragma unroll
        for (int ni = 0; ni < 4; ni++) {
            int r = brow + wm0 + mi * 16 + (lane >> 2);
            int c = bcol + wn0 + ni * 8 + (lane & 3) * 2;
            float bx = bias[c], by = bias[c + 1];
            *(float2*)&C[(size_t)r * N + c] =
                make_float2(acc[mi][ni][0] + bx, acc[mi][ni][1] + by);
            *(float2*)&C[(size_t)(r + 8) * N + c] =
                make_float2(acc[mi][ni][2] + bx, acc[mi][ni][3] + by);
        }
    }
}

// ---------------------------------------------------------------------------
// Tensor-core banded attention (fp16, 2-pass QK and PV).
// grid = (S/64, H, B), block = 128 (4 warps x 16 q-rows).
// Q split hi/lo; K, V single fp16. Output split hi/lo for O-projection.
// ---------------------------------------------------------------------------
#define AT_RS    144                 // smem row stride bytes (72 fp16)
#define AT_TILE  (64 * AT_RS)        // 9216 B
#define AT_SQH   0
#define AT_SQL   AT_TILE
#define AT_ST0   (2 * AT_TILE)
#define AT_STB   (2 * AT_TILE)       // Kh, Vh per stage
#define AT_SMEM  (2 * AT_TILE + 2 * AT_STB)   // 55296 B

__global__ __launch_bounds__(128) void attn_tc(
    const __half* __restrict__ Qh, const __half* __restrict__ Ql,
    const __half* __restrict__ Kh, const __half* __restrict__ Vh,
    __half* __restrict__ Oh, __half* __restrict__ Ol)
{
    extern __shared__ char smem[];
    const uint32_t sb = smem_u32(smem);
    const int qt = blockIdx.x, h = blockIdx.y, b = blockIdx.z;
    const int q0 = qt * 64;
    const int tid = threadIdx.x, lane = tid & 31, w = tid >> 5;
    const float scale = 0.125f;

    const int lrow = tid >> 1;
    const int lhalf = (tid & 1) * 64;
    const int gcol = h * DHEAD + (lhalf >> 1);

    const int kb_lo = max(0, q0 - (WINDOW - 1)) >> 6;
    const int nch = qt - kb_lo + 1;

    // prologue: Q + first K/V chunk
    {
        size_t g = ((size_t)(b * SEQ + q0 + lrow)) * DMODEL + gcol;
        uint32_t so = lrow * AT_RS + lhalf;
#pragma unroll
        for (int i = 0; i < 4; i++) {
            CP_ASYNC16(sb + AT_SQH + so + i * 16, Qh + g + i * 8);
            CP_ASYNC16(sb + AT_SQL + so + i * 16, Ql + g + i * 8);
        }
        size_t gk = ((size_t)(b * SEQ + kb_lo * 64 + lrow)) * DMODEL + gcol;
        uint32_t s0 = sb + AT_ST0;
#pragma unroll
        for (int i = 0; i < 4; i++) {
            CP_ASYNC16(s0 + 0 * AT_TILE + so + i * 16, Kh + gk + i * 8);
            CP_ASYNC16(s0 + 1 * AT_TILE + so + i * 16, Vh + gk + i * 8);
        }
        CP_COMMIT();
    }

    float m0 = -1e30f, m1 = -1e30f, l0 = 0.f, l1 = 0.f;
    float oacc[8][4];
#pragma unroll
    for (int t = 0; t < 8; t++)
#pragma unroll
        for (int e = 0; e < 4; e++) oacc[t][e] = 0.f;

    const int r0g = q0 + w * 16 + (lane >> 2);
    const int r1g = r0g + 8;

    for (int i = 0; i < nch; i++) {
        const int kb = kb_lo + i;
        if (i + 1 < nch) {
            size_t gk = ((size_t)(b * SEQ + (kb + 1) * 64 + lrow)) * DMODEL + gcol;
            uint32_t s0 = sb + AT_ST0 + ((i + 1) & 1) * AT_STB;
            uint32_t so = lrow * AT_RS + lhalf;
#pragma unroll
            for (int u = 0; u < 4; u++) {
                CP_ASYNC16(s0 + 0 * AT_TILE + so + u * 16, Kh + gk + u * 8);
                CP_ASYNC16(s0 + 1 * AT_TILE + so + u * 16, Vh + gk + u * 8);
            }
            CP_COMMIT();
            CP_WAIT(1);
        } else {
            CP_WAIT(0);
        }
        __syncthreads();

        const uint32_t s0  = sb + AT_ST0 + (i & 1) * AT_STB;
        const uint32_t sKh = s0;
        const uint32_t sVh = s0 + AT_TILE;

        // ---- S = Q K^T (2-pass: Qhi*K + Qlo*K) ----
        float sacc[8][4];
#pragma unroll
        for (int t = 0; t < 8; t++)
#pragma unroll
            for (int e = 0; e < 4; e++) sacc[t][e] = 0.f;

#pragma unroll
        for (int ks = 0; ks < 4; ks++) {
            const uint32_t kbb = ks * 32;
            uint32_t aro = (w * 16 + (lane & 15)) * AT_RS + kbb + (lane >> 4) * 16;
            uint32_t ah[4], al[4];
            LDSM_X4(ah[0], ah[1], ah[2], ah[3], sb + AT_SQH + aro);
            LDSM_X4(al[0], al[1], al[2], al[3], sb + AT_SQL + aro);
#pragma unroll
            for (int np = 0; np < 4; np++) {
                uint32_t ro = (np * 16 + (lane & 7) + ((lane >> 4) & 1) * 8) * AT_RS
                              + kbb + ((lane >> 3) & 1) * 16;
                uint32_t bh[4];
                LDSM_X4(bh[0], bh[1], bh[2], bh[3], sKh + ro);
                MMA16816(sacc[2*np],   ah[0], ah[1], ah[2], ah[3], bh[0], bh[1]);
                MMA16816(sacc[2*np],   al[0], al[1], al[2], al[3], bh[0], bh[1]);
                MMA16816(sacc[2*np+1], ah[0], ah[1], ah[2], ah[3], bh[2], bh[3]);
                MMA16816(sacc[2*np+1], al[0], al[1], al[2], al[3], bh[2], bh[3]);
            }
        }

        // ---- mask + online softmax ----
        const int kbase = kb * 64;
        float cmax0 = -1e30f, cmax1 = -1e30f;
#pragma unroll
        for (int t = 0; t < 8; t++) {
            const int c0 = kbase + t * 8 + 2 * (lane & 3);
            int d00 = r0g - c0, d01 = r0g - (c0 + 1);
            int d10 = r1g - c0, d11 = r1g - (c0 + 1);
            sacc[t][0] = (d00 >= 0 && d00 < WINDOW) ? sacc[t][0] * scale : -1e30f;
            sacc[t][1] = (d01 >= 0 && d01 < WINDOW) ? sacc[t][1] * scale : -1e30f;
            sacc[t][2] = (d10 >= 0 && d10 < WINDOW) ? sacc[t][2] * scale : -1e30f;
            sacc[t][3] = (d11 >= 0 && d11 < WINDOW) ? sacc[t][3] * scale : -1e30f;
            cmax0 = fmaxf(cmax0, fmaxf(sacc[t][0], sacc[t][1]));
            cmax1 = fmaxf(cmax1, fmaxf(sacc[t][2], sacc[t][3]));
        }
        cmax0 = fmaxf(cmax0, __shfl_xor_sync(0xffffffffu, cmax0, 1));
        cmax0 = fmaxf(cmax0, __shfl_xor_sync(0xffffffffu, cmax0, 2));
        cmax1 = fmaxf(cmax1, __shfl_xor_sync(0xffffffffu, cmax1, 1));
        cmax1 = fmaxf(cmax1, __shfl_xor_sync(0xffffffffu, cmax1, 2));

        float mn0 = fmaxf(m0, cmax0), mn1 = fmaxf(m1, cmax1);
        float a0 = __expf(m0 - mn0), a1 = __expf(m1 - mn1);
        float rs0 = 0.f, rs1 = 0.f;
#pragma unroll
        for (int t = 0; t < 8; t++) {
            sacc[t][0] = __expf(sacc[t][0] - mn0);
            sacc[t][1] = __expf(sacc[t][1] - mn0);
            sacc[t][2] = __expf(sacc[t][2] - mn1);
            sacc[t][3] = __expf(sacc[t][3] - mn1);
            rs0 += sacc[t][0] + sacc[t][1];
            rs1 += sacc[t][2] + sacc[t][3];
        }
        rs0 += __shfl_xor_sync(0xffffffffu, rs0, 1);
        rs0 += __shfl_xor_sync(0xffffffffu, rs0, 2);
        rs1 += __shfl_xor_sync(0xffffffffu, rs1, 1);
        rs1 += __shfl_xor_sync(0xffffffffu, rs1, 2);
        l0 = l0 * a0 + rs0;  m0 = mn0;
        l1 = l1 * a1 + rs1;  m1 = mn1;
#pragma unroll
        for (int t = 0; t < 8; t++) {
            oacc[t][0] *= a0; oacc[t][1] *= a0;
            oacc[t][2] *= a1; oacc[t][3] *= a1;
        }

        // ---- PV (2-pass: Phi*V + Plo*V; V fragments via ldmatrix.trans) ----
#pragma unroll
        for (int ks = 0; ks < 4; ks++) {
            uint32_t aph[4], apl[4];
            split2h(sacc[2*ks][0],   sacc[2*ks][1],   aph[0], apl[0]);
            split2h(sacc[2*ks][2],   sacc[2*ks][3],   aph[1], apl[1]);
            split2h(sacc[2*ks+1][0], sacc[2*ks+1][1], aph[2], apl[2]);
            split2h(sacc[2*ks+1][2], sacc[2*ks+1][3], aph[3], apl[3]);
#pragma unroll
            for (int np = 0; np < 4; np++) {
                uint32_t vro = (ks * 16 + (lane & 7) + ((lane >> 3) & 1) * 8) * AT_RS
                               + np * 32 + (lane >> 4) * 16;
                uint32_t vh[4];
                LDSM_X4_T(vh[0], vh[1], vh[2], vh[3], sVh + vro);
                MMA16816(oacc[2*np],   aph[0], aph[1], aph[2], aph[3], vh[0], vh[1]);
                MMA16816(oacc[2*np],   apl[0], apl[1], apl[2], apl[3], vh[0], vh[1]);
                MMA16816(oacc[2*np+1], aph[0], aph[1], aph[2], aph[3], vh[2], vh[3]);
                MMA16816(oacc[2*np+1], apl[0], apl[1], apl[2], apl[3], vh[2], vh[3]);
            }
        }
        __syncthreads();
    }

    // ---- epilogue: divide by l, split to fp16 hi/lo, store ----
    const float inv0 = 1.f / l0, inv1 = 1.f / l1;
    const size_t row0 = (size_t)(b * SEQ + r0g) * DMODEL;
    const size_t row1 = (size_t)(b * SEQ + r1g) * DMODEL;
#pragma unroll
    for (int t = 0; t < 8; t++) {
        const int c = h * DHEAD + t * 8 + 2 * (lane & 3);
        uint32_t h0, lo0, h1, lo1;
        split2h(oacc[t][0] * inv0, oacc[t][1] * inv0, h0, lo0);
        split2h(oacc[t][2] * inv1, oacc[t][3] * inv1, h1, lo1);
        *(uint32_t*)&Oh[row0 + c] = h0;
        *(uint32_t*)&Ol[row0 + c] = lo0;
        *(uint32_t*)&Oh[row1 + c] = h1;
        *(uint32_t*)&Ol[row1 + c] = lo1;
    }
}

// ---------------------------------------------------------------------------
// Launch
// ---------------------------------------------------------------------------
extern "C" void kernel_launch(void* const* d_in, const int* in_sizes, int n_in,
                              void* d_out, int out_size)
{
    const float* X  = (const float*)d_in[0];
    const float* Wq = (const float*)d_in[1];
    const float* bq = (const float*)d_in[2];
    const float* Wk = (const float*)d_in[3];
    const float* bk = (const float*)d_in[4];
    const float* Wv = (const float*)d_in[5];
    const float* bv = (const float*)d_in[6];
    const float* Wo = (const float*)d_in[7];
    const float* bo = (const float*)d_in[8];
    float* out = (float*)d_out;

    __half *xhi, *xlo, *qhi, *qlo, *khi, *vhi, *aohi, *aolo, *wthi, *wtlo;
    cudaGetSymbolAddress((void**)&xhi,  g_xhi);
    cudaGetSymbolAddress((void**)&xlo,  g_xlo);
    cudaGetSymbolAddress((void**)&qhi,  g_qhi);
    cudaGetSymbolAddress((void**)&qlo,  g_qlo);
    cudaGetSymbolAddress((void**)&khi,  g_khi);
    cudaGetSymbolAddress((void**)&vhi,  g_vhi);
    cudaGetSymbolAddress((void**)&aohi, g_aohi);
    cudaGetSymbolAddress((void**)&aolo, g_aolo);
    cudaGetSymbolAddress((void**)&wthi, g_wthi);
    cudaGetSymbolAddress((void**)&wtlo, g_wtlo);

    cudaFuncSetAttribute(attn_tc,  cudaFuncAttributeMaxDynamicSharedMemorySize, AT_SMEM);
    cudaFuncSetAttribute(gemm_qkv, cudaFuncAttributeMaxDynamicSharedMemorySize, Q_SMEM_B);
    cudaFuncSetAttribute(gemm_o,   cudaFuncAttributeMaxDynamicSharedMemorySize, O_SMEM_B);

    // 1. split X -> fp16 hi/lo
    split_kernel<<<(MROWS * DMODEL / 4 + 255) / 256, 256>>>(X, xhi, xlo, MROWS * DMODEL / 4);

    // 2. all 4 weight transposes in one launch
    transpose_split4<<<dim3(32, 32, 4), dim3(32, 8)>>>(Wq, Wk, Wv, Wo, wthi, wtlo);

    // 3. fused Q/K/V projections (2-pass fp16)
    gemm_qkv<<<dim3(DMODEL / 128, MROWS / 128, 3), 256, Q_SMEM_B>>>(
        xhi, xlo, wthi, bq, bk, bv, qhi, qlo, khi, vhi, MROWS, DMODEL, DMODEL);

    // 4. tensor-core banded attention (2-pass)
    attn_tc<<<dim3(SEQ / 64, NHEADS, BATCH), 128, AT_SMEM>>>(qhi, qlo, khi, vhi, aohi, aolo);

    // 5. O projection (3-pass fp16) -> fp32 output
    gemm_o<<<dim3(DMODEL / 128, MROWS / 128), 256, O_SMEM_B>>>(
        aohi, aolo, wthi + 3 * DD, wtlo, bo, out, MROWS, DMODEL, DMODEL);
}

// round 6
// speedup vs baseline: 5.7674x; 1.2669x over previous
#include <cuda_runtime.h>
#include <cuda_fp16.h>
#include <cstdint>
#include <math.h>

// ---------------------------------------------------------------------------
// Problem constants (B=2, S=2048, D=1024, H=16)
// ---------------------------------------------------------------------------
#define BATCH   2
#define SEQ     2048
#define DMODEL  1024
#define NHEADS  16
#define DHEAD   64
#define WINDOW  256
#define MROWS   (BATCH * SEQ)   // 4096
#define DD      (DMODEL * DMODEL)

// ---------------------------------------------------------------------------
// Scratch (__device__ globals; allocation-free rule)
// ---------------------------------------------------------------------------
__device__ __half g_xhi [MROWS * DMODEL];
__device__ __half g_qhi [MROWS * DMODEL];
__device__ __half g_qlo [MROWS * DMODEL];
__device__ __half g_khi [MROWS * DMODEL];
__device__ __half g_vhi [MROWS * DMODEL];
__device__ __half g_aohi[MROWS * DMODEL];
__device__ __half g_aolo[MROWS * DMODEL];
__device__ __half g_wthi[4 * DD];   // transposed weights [N][K], fp16 hi
__device__ __half g_wtlo[DD];       // lo residual, Wo only

// ---------------------------------------------------------------------------
// PTX helpers — base sm_100 ISA only (mma.sync / ldmatrix / cp.async)
// ---------------------------------------------------------------------------
__device__ __forceinline__ uint32_t smem_u32(const void* p) {
    uint32_t a;
    asm("{ .reg .u64 t; cvta.to.shared.u64 t, %1; cvt.u32.u64 %0, t; }" : "=r"(a) : "l"(p));
    return a;
}

#define CP_ASYNC16(dst, src) \
    asm volatile("cp.async.cg.shared.global [%0], [%1], 16;" :: "r"(dst), "l"(src))
#define CP_COMMIT() asm volatile("cp.async.commit_group;" ::: "memory")
#define CP_WAIT(n)  asm volatile("cp.async.wait_group %0;" :: "n"(n) : "memory")

#define LDSM_X4(r0, r1, r2, r3, addr) \
    asm volatile("ldmatrix.sync.aligned.m8n8.x4.shared.b16 {%0,%1,%2,%3}, [%4];" \
        : "=r"(r0), "=r"(r1), "=r"(r2), "=r"(r3) : "r"(addr))

#define LDSM_X4_T(r0, r1, r2, r3, addr) \
    asm volatile("ldmatrix.sync.aligned.m8n8.x4.trans.shared.b16 {%0,%1,%2,%3}, [%4];" \
        : "=r"(r0), "=r"(r1), "=r"(r2), "=r"(r3) : "r"(addr))

#define MMA16816(d, a0, a1, a2, a3, b0, b1) \
    asm volatile("mma.sync.aligned.m16n8k16.row.col.f32.f16.f16.f32 " \
        "{%0,%1,%2,%3}, {%4,%5,%6,%7}, {%8,%9}, {%0,%1,%2,%3};" \
        : "+f"((d)[0]), "+f"((d)[1]), "+f"((d)[2]), "+f"((d)[3]) \
        : "r"(a0), "r"(a1), "r"(a2), "r"(a3), "r"(b0), "r"(b1))

// split a float pair into packed fp16x2 hi and lo (residual)
__device__ __forceinline__ void split2h(float x, float y, uint32_t& hi, uint32_t& lo) {
    __half hx = __float2half_rn(x), hy = __float2half_rn(y);
    __half2 h2(hx, hy);
    float rx = x - __half2float(hx), ry = y - __half2float(hy);
    __half2 l2(__float2half_rn(rx), __float2half_rn(ry));
    hi = *(uint32_t*)&h2;
    lo = *(uint32_t*)&l2;
}
__device__ __forceinline__ uint32_t pack2h(float x, float y) {
    __half2 h2(__float2half_rn(x), __float2half_rn(y));
    return *(uint32_t*)&h2;
}

// ---------------------------------------------------------------------------
// fp32 -> fp16 convert (X; 1-pass QKV needs no residual)
// ---------------------------------------------------------------------------
__global__ __launch_bounds__(256) void cvt_kernel(
    const float* __restrict__ in, __half* __restrict__ hi, int n4)
{
    int i = blockIdx.x * blockDim.x + threadIdx.x;
    if (i >= n4) return;
    float4 v = ((const float4*)in)[i];
    ((uint32_t*)hi)[2*i]   = pack2h(v.x, v.y);
    ((uint32_t*)hi)[2*i+1] = pack2h(v.z, v.w);
}

// ---------------------------------------------------------------------------
// All 4 weights: [K x N] fp32 -> transposed fp16 [N x K]; lo residual for Wo.
// grid (32, 32, 4), block (32, 8)
// ---------------------------------------------------------------------------
__global__ __launch_bounds__(256) void transpose_split4(
    const float* __restrict__ w0, const float* __restrict__ w1,
    const float* __restrict__ w2, const float* __restrict__ w3,
    __half* __restrict__ hi, __half* __restrict__ lo)
{
    __shared__ float t[32][33];
    const int z = blockIdx.z;
    const float* in = (z == 0) ? w0 : (z == 1) ? w1 : (z == 2) ? w2 : w3;
    __half* oh = hi + (size_t)z * DD;
    int bx = blockIdx.x * 32, by = blockIdx.y * 32;
    int tx = threadIdx.x, ty = threadIdx.y;
#pragma unroll
    for (int j = ty; j < 32; j += 8)
        t[j][tx] = in[(size_t)(by + j) * DMODEL + bx + tx];
    __syncthreads();
#pragma unroll
    for (int j = ty; j < 32; j += 8) {
        float v = t[tx][j];                 // = in[by+tx][bx+j]
        __half h = __float2half_rn(v);
        size_t o = (size_t)(bx + j) * DMODEL + by + tx;
        oh[o] = h;
        if (z == 3) lo[o] = __float2half_rn(v - __half2float(h));
    }
}

// ---------------------------------------------------------------------------
// QKV GEMM (1-pass fp16): C = Ah[M,K] @ Bh^T + bias
// grid (N/128, M/128, 3): z selects W/bias/output. 4-stage cp.async pipeline.
// z==0 (Q): write hi+lo split. z==1 (K), z==2 (V): write hi only.
// ---------------------------------------------------------------------------
#define G_RS       80          // row stride bytes (32 fp16 = 64B + 16B pad)
#define G_TILE_B   (128 * G_RS)          // 10240
#define Q_STAGE_B  (2 * G_TILE_B)        // Ah, Bh
#define Q_SMEM_B   (4 * Q_STAGE_B)       // 81920

__global__ __launch_bounds__(256, 2) void gemm_qkv(
    const __half* __restrict__ Ahi, const __half* __restrict__ Wt,
    const float* __restrict__ bq, const float* __restrict__ bk,
    const float* __restrict__ bv,
    __half* __restrict__ Qhi, __half* __restrict__ Qlo,
    __half* __restrict__ Khi, __half* __restrict__ Vhi,
    int M, int N, int K)
{
    extern __shared__ char smem[];
    const uint32_t sb = smem_u32(smem);
    const int z = blockIdx.z;
    const __half* Bh = Wt + (size_t)z * DD;
    const float* bias = (z == 0) ? bq : (z == 1) ? bk : bv;
    __half* Chi = (z == 0) ? Qhi : (z == 1) ? Khi : Vhi;

    const int tid = threadIdx.x, lane = tid & 31, wid = tid >> 5;
    const int brow = blockIdx.y * 128, bcol = blockIdx.x * 128;
    const int wm0 = (wid & 1) * 64;
    const int wn0 = (wid >> 1) * 32;

    float acc[4][4][4];
#pragma unroll
    for (int mi = 0; mi < 4; mi++)
#pragma unroll
        for (int ni = 0; ni < 4; ni++)
#pragma unroll
            for (int e = 0; e < 4; e++) acc[mi][ni][e] = 0.f;

    const int r0l = tid >> 2, c16a = (tid & 3) * 8;
    const int r1l = (tid + 256) >> 2;
    const int nchunks = K / 32;

    auto issue_load = [&](int st, int kt) {
        uint32_t s0 = sb + st * Q_STAGE_B;
#pragma unroll
        for (int u = 0; u < 2; u++) {
            int row = u ? r1l : r0l;
            uint32_t so = row * G_RS + c16a * 2;
            CP_ASYNC16(s0 + 0 * G_TILE_B + so, Ahi + (size_t)(brow + row) * K + kt + c16a);
            CP_ASYNC16(s0 + 1 * G_TILE_B + so, Bh  + (size_t)(bcol + row) * K + kt + c16a);
        }
    };

    issue_load(0, 0);  CP_COMMIT();
    issue_load(1, 32); CP_COMMIT();
    issue_load(2, 64); CP_COMMIT();

    for (int ch = 0; ch < nchunks; ch++) {
        if (ch + 3 < nchunks) {
            issue_load((ch + 3) & 3, (ch + 3) * 32);
            CP_COMMIT();
        }
        const int nf = nchunks - 1 - ch;   // future chunks still pending
        if (nf >= 3)      CP_WAIT(3);
        else if (nf == 2) CP_WAIT(2);
        else if (nf == 1) CP_WAIT(1);
        else              CP_WAIT(0);
        __syncthreads();

        const uint32_t s0  = sb + (ch & 3) * Q_STAGE_B;
        const uint32_t sAh = s0;
        const uint32_t sBh = s0 + G_TILE_B;

#pragma unroll
        for (int ks = 0; ks < 2; ks++) {
            const uint32_t kb = ks * 32;
            uint32_t bh[4][2];
#pragma unroll
            for (int np = 0; np < 2; np++) {
                uint32_t ro = (wn0 + np * 16 + (lane & 7) + ((lane >> 4) & 1) * 8) * G_RS
                              + kb + ((lane >> 3) & 1) * 16;
                LDSM_X4(bh[np*2][0], bh[np*2][1], bh[np*2+1][0], bh[np*2+1][1], sBh + ro);
            }
#pragma unroll
            for (int mi = 0; mi < 4; mi++) {
                uint32_t ro = (wm0 + mi * 16 + (lane & 15)) * G_RS + kb + (lane >> 4) * 16;
                uint32_t ah[4];
                LDSM_X4(ah[0], ah[1], ah[2], ah[3], sAh + ro);
#pragma unroll
                for (int ni = 0; ni < 4; ni++)
                    MMA16816(acc[mi][ni], ah[0], ah[1], ah[2], ah[3], bh[ni][0], bh[ni][1]);
            }
        }
        __syncthreads();
    }

    // epilogue
    __half* Clo = Qlo;
#pragma unroll
    for (int mi = 0; mi < 4; mi++) {
#pragma unroll
        for (int ni = 0; ni < 4; ni++) {
            int r = brow + wm0 + mi * 16 + (lane >> 2);
            int c = bcol + wn0 + ni * 8 + (lane & 3) * 2;
            float bx = bias[c], by = bias[c + 1];
            float v0 = acc[mi][ni][0] + bx, v1 = acc[mi][ni][1] + by;
            float v2 = acc[mi][ni][2] + bx, v3 = acc[mi][ni][3] + by;
            if (z == 0) {
                uint32_t h0, l0, h1, l1;
                split2h(v0, v1, h0, l0);
                split2h(v2, v3, h1, l1);
                *(uint32_t*)&Chi[(size_t)r * N + c]       = h0;
                *(uint32_t*)&Clo[(size_t)r * N + c]       = l0;
                *(uint32_t*)&Chi[(size_t)(r + 8) * N + c] = h1;
                *(uint32_t*)&Clo[(size_t)(r + 8) * N + c] = l1;
            } else {
                *(uint32_t*)&Chi[(size_t)r * N + c]       = pack2h(v0, v1);
                *(uint32_t*)&Chi[(size_t)(r + 8) * N + c] = pack2h(v2, v3);
            }
        }
    }
}

// ---------------------------------------------------------------------------
// O-projection GEMM (3-pass fp16, both operands split): fp32 output.
// 128x128 CTA tile, BK=32, 2-stage pipeline.
// ---------------------------------------------------------------------------
#define O_STAGE_B (4 * G_TILE_B)
#define O_SMEM_B  (2 * O_STAGE_B)

__global__ __launch_bounds__(256, 2) void gemm_o(
    const __half* __restrict__ Ahi, const __half* __restrict__ Alo,
    const __half* __restrict__ Bhi, const __half* __restrict__ Blo,
    const float* __restrict__ bias, float* __restrict__ C,
    int M, int N, int K)
{
    extern __shared__ char smem[];
    const uint32_t sb = smem_u32(smem);
    const int tid = threadIdx.x, lane = tid & 31, wid = tid >> 5;
    const int brow = blockIdx.y * 128, bcol = blockIdx.x * 128;
    const int wm0 = (wid & 1) * 64;
    const int wn0 = (wid >> 1) * 32;

    float acc[4][4][4];
#pragma unroll
    for (int mi = 0; mi < 4; mi++)
#pragma unroll
        for (int ni = 0; ni < 4; ni++)
#pragma unroll
            for (int e = 0; e < 4; e++) acc[mi][ni][e] = 0.f;

    const int r0l = tid >> 2, c16a = (tid & 3) * 8;
    const int r1l = (tid + 256) >> 2;
    const int nchunks = K / 32;

    auto issue_load = [&](int st, int kt) {
        uint32_t s0 = sb + st * O_STAGE_B;
#pragma unroll
        for (int u = 0; u < 2; u++) {
            int row = u ? r1l : r0l;
            uint32_t so = row * G_RS + c16a * 2;
            CP_ASYNC16(s0 + 0 * G_TILE_B + so, Ahi + (size_t)(brow + row) * K + kt + c16a);
            CP_ASYNC16(s0 + 1 * G_TILE_B + so, Alo + (size_t)(brow + row) * K + kt + c16a);
            CP_ASYNC16(s0 + 2 * G_TILE_B + so, Bhi + (size_t)(bcol + row) * K + kt + c16a);
            CP_ASYNC16(s0 + 3 * G_TILE_B + so, Blo + (size_t)(bcol + row) * K + kt + c16a);
        }
    };

    issue_load(0, 0);
    CP_COMMIT();

    for (int ch = 0; ch < nchunks; ch++) {
        if (ch + 1 < nchunks) {
            issue_load((ch + 1) & 1, (ch + 1) * 32);
            CP_COMMIT();
            CP_WAIT(1);
        } else {
            CP_WAIT(0);
        }
        __syncthreads();

        const uint32_t s0  = sb + (ch & 1) * O_STAGE_B;
        const uint32_t sAh = s0;
        const uint32_t sAl = s0 + G_TILE_B;
        const uint32_t sBh = s0 + 2 * G_TILE_B;
        const uint32_t sBl = s0 + 3 * G_TILE_B;

#pragma unroll
        for (int ks = 0; ks < 2; ks++) {
            const uint32_t kb = ks * 32;
            uint32_t bh[4][2], bl[4][2];
#pragma unroll
            for (int np = 0; np < 2; np++) {
                uint32_t ro = (wn0 + np * 16 + (lane & 7) + ((lane >> 4) & 1) * 8) * G_RS
                              + kb + ((lane >> 3) & 1) * 16;
                LDSM_X4(bh[np*2][0], bh[np*2][1], bh[np*2+1][0], bh[np*2+1][1], sBh + ro);
                LDSM_X4(bl[np*2][0], bl[np*2][1], bl[np*2+1][0], bl[np*2+1][1], sBl + ro);
            }
#pragma unroll
            for (int mi = 0; mi < 4; mi++) {
                uint32_t ro = (wm0 + mi * 16 + (lane & 15)) * G_RS + kb + (lane >> 4) * 16;
                uint32_t ah[4], al[4];
                LDSM_X4(ah[0], ah[1], ah[2], ah[3], sAh + ro);
                LDSM_X4(al[0], al[1], al[2], al[3], sAl + ro);
#pragma unroll
                for (int ni = 0; ni < 4; ni++) {
                    MMA16816(acc[mi][ni], ah[0], ah[1], ah[2], ah[3], bh[ni][0], bh[ni][1]);
                    MMA16816(acc[mi][ni], al[0], al[1], al[2], al[3], bh[ni][0], bh[ni][1]);
                    MMA16816(acc[mi][ni], ah[0], ah[1], ah[2], ah[3], bl[ni][0], bl[ni][1]);
                }
            }
        }
        __syncthreads();
    }

#pragma unroll
    for (int mi = 0; mi < 4; mi++) {
#pragma unroll
        for (int ni = 0; ni < 4; ni++) {
            int r = brow + wm0 + mi * 16 + (lane >> 2);
            int c = bcol + wn0 + ni * 8 + (lane & 3) * 2;
            float bx = bias[c], by = bias[c + 1];
            *(float2*)&C[(size_t)r * N + c] =
                make_float2(acc[mi][ni][0] + bx, acc[mi][ni][1] + by);
            *(float2*)&C[(size_t)(r + 8) * N + c] =
                make_float2(acc[mi][ni][2] + bx, acc[mi][ni][3] + by);
        }
    }
}

// ---------------------------------------------------------------------------
// Tensor-core banded attention (fp16, 2-pass QK and PV).
// grid = (S/64, H, B), block = 128 (4 warps x 16 q-rows).
// ---------------------------------------------------------------------------
#define AT_RS    144                 // smem row stride bytes (72 fp16)
#define AT_TILE  (64 * AT_RS)        // 9216 B
#define AT_SQH   0
#define AT_SQL   AT_TILE
#define AT_ST0   (2 * AT_TILE)
#define AT_STB   (2 * AT_TILE)       // Kh, Vh per stage
#define AT_SMEM  (2 * AT_TILE + 2 * AT_STB)   // 55296 B

__global__ __launch_bounds__(128) void attn_tc(
    const __half* __restrict__ Qh, const __half* __restrict__ Ql,
    const __half* __restrict__ Kh, const __half* __restrict__ Vh,
    __half* __restrict__ Oh, __half* __restrict__ Ol)
{
    extern __shared__ char smem[];
    const uint32_t sb = smem_u32(smem);
    const int qt = blockIdx.x, h = blockIdx.y, b = blockIdx.z;
    const int q0 = qt * 64;
    const int tid = threadIdx.x, lane = tid & 31, w = tid >> 5;
    const float scale = 0.125f;

    const int lrow = tid >> 1;
    const int lhalf = (tid & 1) * 64;
    const int gcol = h * DHEAD + (lhalf >> 1);

    const int kb_lo = max(0, q0 - (WINDOW - 1)) >> 6;
    const int nch = qt - kb_lo + 1;

    // prologue: Q + first K/V chunk
    {
        size_t g = ((size_t)(b * SEQ + q0 + lrow)) * DMODEL + gcol;
        uint32_t so = lrow * AT_RS + lhalf;
#pragma unroll
        for (int i = 0; i < 4; i++) {
            CP_ASYNC16(sb + AT_SQH + so + i * 16, Qh + g + i * 8);
            CP_ASYNC16(sb + AT_SQL + so + i * 16, Ql + g + i * 8);
        }
        size_t gk = ((size_t)(b * SEQ + kb_lo * 64 + lrow)) * DMODEL + gcol;
        uint32_t s0 = sb + AT_ST0;
#pragma unroll
        for (int i = 0; i < 4; i++) {
            CP_ASYNC16(s0 + 0 * AT_TILE + so + i * 16, Kh + gk + i * 8);
            CP_ASYNC16(s0 + 1 * AT_TILE + so + i * 16, Vh + gk + i * 8);
        }
        CP_COMMIT();
    }

    float m0 = -1e30f, m1 = -1e30f, l0 = 0.f, l1 = 0.f;
    float oacc[8][4];
#pragma unroll
    for (int t = 0; t < 8; t++)
#pragma unroll
        for (int e = 0; e < 4; e++) oacc[t][e] = 0.f;

    const int r0g = q0 + w * 16 + (lane >> 2);
    const int r1g = r0g + 8;

    for (int i = 0; i < nch; i++) {
        const int kb = kb_lo + i;
        if (i + 1 < nch) {
            size_t gk = ((size_t)(b * SEQ + (kb + 1) * 64 + lrow)) * DMODEL + gcol;
            uint32_t s0 = sb + AT_ST0 + ((i + 1) & 1) * AT_STB;
            uint32_t so = lrow * AT_RS + lhalf;
#pragma unroll
            for (int u = 0; u < 4; u++) {
                CP_ASYNC16(s0 + 0 * AT_TILE + so + u * 16, Kh + gk + u * 8);
                CP_ASYNC16(s0 + 1 * AT_TILE + so + u * 16, Vh + gk + u * 8);
            }
            CP_COMMIT();
            CP_WAIT(1);
        } else {
            CP_WAIT(0);
        }
        __syncthreads();

        const uint32_t s0  = sb + AT_ST0 + (i & 1) * AT_STB;
        const uint32_t sKh = s0;
        const uint32_t sVh = s0 + AT_TILE;

        // ---- S = Q K^T (2-pass: Qhi*K + Qlo*K) ----
        float sacc[8][4];
#pragma unroll
        for (int t = 0; t < 8; t++)
#pragma unroll
            for (int e = 0; e < 4; e++) sacc[t][e] = 0.f;

#pragma unroll
        for (int ks = 0; ks < 4; ks++) {
            const uint32_t kbb = ks * 32;
            uint32_t aro = (w * 16 + (lane & 15)) * AT_RS + kbb + (lane >> 4) * 16;
            uint32_t ah[4], al[4];
            LDSM_X4(ah[0], ah[1], ah[2], ah[3], sb + AT_SQH + aro);
            LDSM_X4(al[0], al[1], al[2], al[3], sb + AT_SQL + aro);
#pragma unroll
            for (int np = 0; np < 4; np++) {
                uint32_t ro = (np * 16 + (lane & 7) + ((lane >> 4) & 1) * 8) * AT_RS
                              + kbb + ((lane >> 3) & 1) * 16;
                uint32_t bh[4];
                LDSM_X4(bh[0], bh[1], bh[2], bh[3], sKh + ro);
                MMA16816(sacc[2*np],   ah[0], ah[1], ah[2], ah[3], bh[0], bh[1]);
                MMA16816(sacc[2*np],   al[0], al[1], al[2], al[3], bh[0], bh[1]);
                MMA16816(sacc[2*np+1], ah[0], ah[1], ah[2], ah[3], bh[2], bh[3]);
                MMA16816(sacc[2*np+1], al[0], al[1], al[2], al[3], bh[2], bh[3]);
            }
        }

        // ---- mask + online softmax ----
        const int kbase = kb * 64;
        float cmax0 = -1e30f, cmax1 = -1e30f;
#pragma unroll
        for (int t = 0; t < 8; t++) {
            const int c0 = kbase + t * 8 + 2 * (lane & 3);
            int d00 = r0g - c0, d01 = r0g - (c0 + 1);
            int d10 = r1g - c0, d11 = r1g - (c0 + 1);
            sacc[t][0] = (d00 >= 0 && d00 < WINDOW) ? sacc[t][0] * scale : -1e30f;
            sacc[t][1] = (d01 >= 0 && d01 < WINDOW) ? sacc[t][1] * scale : -1e30f;
            sacc[t][2] = (d10 >= 0 && d10 < WINDOW) ? sacc[t][2] * scale : -1e30f;
            sacc[t][3] = (d11 >= 0 && d11 < WINDOW) ? sacc[t][3] * scale : -1e30f;
            cmax0 = fmaxf(cmax0, fmaxf(sacc[t][0], sacc[t][1]));
            cmax1 = fmaxf(cmax1, fmaxf(sacc[t][2], sacc[t][3]));
        }
        cmax0 = fmaxf(cmax0, __shfl_xor_sync(0xffffffffu, cmax0, 1));
        cmax0 = fmaxf(cmax0, __shfl_xor_sync(0xffffffffu, cmax0, 2));
        cmax1 = fmaxf(cmax1, __shfl_xor_sync(0xffffffffu, cmax1, 1));
        cmax1 = fmaxf(cmax1, __shfl_xor_sync(0xffffffffu, cmax1, 2));

        float mn0 = fmaxf(m0, cmax0), mn1 = fmaxf(m1, cmax1);
        float a0 = __expf(m0 - mn0), a1 = __expf(m1 - mn1);
        float rs0 = 0.f, rs1 = 0.f;
#pragma unroll
        for (int t = 0; t < 8; t++) {
            sacc[t][0] = __expf(sacc[t][0] - mn0);
            sacc[t][1] = __expf(sacc[t][1] - mn0);
            sacc[t][2] = __expf(sacc[t][2] - mn1);
            sacc[t][3] = __expf(sacc[t][3] - mn1);
            rs0 += sacc[t][0] + sacc[t][1];
            rs1 += sacc[t][2] + sacc[t][3];
        }
        rs0 += __shfl_xor_sync(0xffffffffu, rs0, 1);
        rs0 += __shfl_xor_sync(0xffffffffu, rs0, 2);
        rs1 += __shfl_xor_sync(0xffffffffu, rs1, 1);
        rs1 += __shfl_xor_sync(0xffffffffu, rs1, 2);
        l0 = l0 * a0 + rs0;  m0 = mn0;
        l1 = l1 * a1 + rs1;  m1 = mn1;
#pragma unroll
        for (int t = 0; t < 8; t++) {
            oacc[t][0] *= a0; oacc[t][1] *= a0;
            oacc[t][2] *= a1; oacc[t][3] *= a1;
        }

        // ---- PV (2-pass: Phi*V + Plo*V; V fragments via ldmatrix.trans) ----
#pragma unroll
        for (int ks = 0; ks < 4; ks++) {
            uint32_t aph[4], apl[4];
            split2h(sacc[2*ks][0],   sacc[2*ks][1],   aph[0], apl[0]);
            split2h(sacc[2*ks][2],   sacc[2*ks][3],   aph[1], apl[1]);
            split2h(sacc[2*ks+1][0], sacc[2*ks+1][1], aph[2], apl[2]);
            split2h(sacc[2*ks+1][2], sacc[2*ks+1][3], aph[3], apl[3]);
#pragma unroll
            for (int np = 0; np < 4; np++) {
                uint32_t vro = (ks * 16 + (lane & 7) + ((lane >> 3) & 1) * 8) * AT_RS
                               + np * 32 + (lane >> 4) * 16;
                uint32_t vh[4];
                LDSM_X4_T(vh[0], vh[1], vh[2], vh[3], sVh + vro);
                MMA16816(oacc[2*np],   aph[0], aph[1], aph[2], aph[3], vh[0], vh[1]);
                MMA16816(oacc[2*np],   apl[0], apl[1], apl[2], apl[3], vh[0], vh[1]);
                MMA16816(oacc[2*np+1], aph[0], aph[1], aph[2], aph[3], vh[2], vh[3]);
                MMA16816(oacc[2*np+1], apl[0], apl[1], apl[2], apl[3], vh[2], vh[3]);
            }
        }
        __syncthreads();
    }

    // ---- epilogue: divide by l, split to fp16 hi/lo, store ----
    const float inv0 = 1.f / l0, inv1 = 1.f / l1;
    const size_t row0 = (size_t)(b * SEQ + r0g) * DMODEL;
    const size_t row1 = (size_t)(b * SEQ + r1g) * DMODEL;
#pragma unroll
    for (int t = 0; t < 8; t++) {
        const int c = h * DHEAD + t * 8 + 2 * (lane & 3);
        uint32_t h0, lo0, h1, lo1;
        split2h(oacc[t][0] * inv0, oacc[t][1] * inv0, h0, lo0);
        split2h(oacc[t][2] * inv1, oacc[t][3] * inv1, h1, lo1);
        *(uint32_t*)&Oh[row0 + c] = h0;
        *(uint32_t*)&Ol[row0 + c] = lo0;
        *(uint32_t*)&Oh[row1 + c] = h1;
        *(uint32_t*)&Ol[row1 + c] = lo1;
    }
}

// ---------------------------------------------------------------------------
// Launch
// ---------------------------------------------------------------------------
extern "C" void kernel_launch(void* const* d_in, const int* in_sizes, int n_in,
                              void* d_out, int out_size)
{
    const float* X  = (const float*)d_in[0];
    const float* Wq = (const float*)d_in[1];
    const float* bq = (const float*)d_in[2];
    const float* Wk = (const float*)d_in[3];
    const float* bk = (const float*)d_in[4];
    const float* Wv = (const float*)d_in[5];
    const float* bv = (const float*)d_in[6];
    const float* Wo = (const float*)d_in[7];
    const float* bo = (const float*)d_in[8];
    float* out = (float*)d_out;

    __half *xhi, *qhi, *qlo, *khi, *vhi, *aohi, *aolo, *wthi, *wtlo;
    cudaGetSymbolAddress((void**)&xhi,  g_xhi);
    cudaGetSymbolAddress((void**)&qhi,  g_qhi);
    cudaGetSymbolAddress((void**)&qlo,  g_qlo);
    cudaGetSymbolAddress((void**)&khi,  g_khi);
    cudaGetSymbolAddress((void**)&vhi,  g_vhi);
    cudaGetSymbolAddress((void**)&aohi, g_aohi);
    cudaGetSymbolAddress((void**)&aolo, g_aolo);
    cudaGetSymbolAddress((void**)&wthi, g_wthi);
    cudaGetSymbolAddress((void**)&wtlo, g_wtlo);

    cudaFuncSetAttribute(attn_tc,  cudaFuncAttributeMaxDynamicSharedMemorySize, AT_SMEM);
    cudaFuncSetAttribute(gemm_qkv, cudaFuncAttributeMaxDynamicSharedMemorySize, Q_SMEM_B);
    cudaFuncSetAttribute(gemm_o,   cudaFuncAttributeMaxDynamicSharedMemorySize, O_SMEM_B);

    // 1. convert X -> fp16
    cvt_kernel<<<(MROWS * DMODEL / 4 + 255) / 256, 256>>>(X, xhi, MROWS * DMODEL / 4);

    // 2. all 4 weight transposes in one launch
    transpose_split4<<<dim3(32, 32, 4), dim3(32, 8)>>>(Wq, Wk, Wv, Wo, wthi, wtlo);

    // 3. fused Q/K/V projections (1-pass fp16)
    gemm_qkv<<<dim3(DMODEL / 128, MROWS / 128, 3), 256, Q_SMEM_B>>>(
        xhi, wthi, bq, bk, bv, qhi, qlo, khi, vhi, MROWS, DMODEL, DMODEL);

    // 4. tensor-core banded attention (2-pass)
    attn_tc<<<dim3(SEQ / 64, NHEADS, BATCH), 128, AT_SMEM>>>(qhi, qlo, khi, vhi, aohi, aolo);

    // 5. O projection (3-pass fp16) -> fp32 output
    gemm_o<<<dim3(DMODEL / 128, MROWS / 128), 256, O_SMEM_B>>>(
        aohi, aolo, wthi + 3 * DD, wtlo, bo, out, MROWS, DMODEL, DMODEL);
}

// round 7
// speedup vs baseline: 6.6550x; 1.1539x over previous
#include <cuda_runtime.h>
#include <cuda_fp16.h>
#include <cstdint>
#include <math.h>

// ---------------------------------------------------------------------------
// Problem constants (B=2, S=2048, D=1024, H=16)
// ---------------------------------------------------------------------------
#define BATCH   2
#define SEQ     2048
#define DMODEL  1024
#define NHEADS  16
#define DHEAD   64
#define WINDOW  256
#define MROWS   (BATCH * SEQ)   // 4096
#define DD      (DMODEL * DMODEL)

// ---------------------------------------------------------------------------
// Scratch (__device__ globals; allocation-free rule)
// ---------------------------------------------------------------------------
__device__ __half g_xhi [MROWS * DMODEL];
__device__ __half g_qhi [MROWS * DMODEL];
__device__ __half g_khi [MROWS * DMODEL];
__device__ __half g_vhi [MROWS * DMODEL];
__device__ __half g_aohi[MROWS * DMODEL];
__device__ __half g_aolo[MROWS * DMODEL];
__device__ __half g_wthi[4 * DD];   // transposed weights [N][K], fp16

// ---------------------------------------------------------------------------
// PTX helpers — base sm_100 ISA only (mma.sync / ldmatrix / cp.async)
// ---------------------------------------------------------------------------
__device__ __forceinline__ uint32_t smem_u32(const void* p) {
    uint32_t a;
    asm("{ .reg .u64 t; cvta.to.shared.u64 t, %1; cvt.u32.u64 %0, t; }" : "=r"(a) : "l"(p));
    return a;
}

#define CP_ASYNC16(dst, src) \
    asm volatile("cp.async.cg.shared.global [%0], [%1], 16;" :: "r"(dst), "l"(src))
#define CP_COMMIT() asm volatile("cp.async.commit_group;" ::: "memory")
#define CP_WAIT(n)  asm volatile("cp.async.wait_group %0;" :: "n"(n) : "memory")

#define LDSM_X4(r0, r1, r2, r3, addr) \
    asm volatile("ldmatrix.sync.aligned.m8n8.x4.shared.b16 {%0,%1,%2,%3}, [%4];" \
        : "=r"(r0), "=r"(r1), "=r"(r2), "=r"(r3) : "r"(addr))

#define LDSM_X4_T(r0, r1, r2, r3, addr) \
    asm volatile("ldmatrix.sync.aligned.m8n8.x4.trans.shared.b16 {%0,%1,%2,%3}, [%4];" \
        : "=r"(r0), "=r"(r1), "=r"(r2), "=r"(r3) : "r"(addr))

#define MMA16816(d, a0, a1, a2, a3, b0, b1) \
    asm volatile("mma.sync.aligned.m16n8k16.row.col.f32.f16.f16.f32 " \
        "{%0,%1,%2,%3}, {%4,%5,%6,%7}, {%8,%9}, {%0,%1,%2,%3};" \
        : "+f"((d)[0]), "+f"((d)[1]), "+f"((d)[2]), "+f"((d)[3]) \
        : "r"(a0), "r"(a1), "r"(a2), "r"(a3), "r"(b0), "r"(b1))

// split a float pair into packed fp16x2 hi and lo (residual)
__device__ __forceinline__ void split2h(float x, float y, uint32_t& hi, uint32_t& lo) {
    __half hx = __float2half_rn(x), hy = __float2half_rn(y);
    __half2 h2(hx, hy);
    float rx = x - __half2float(hx), ry = y - __half2float(hy);
    __half2 l2(__float2half_rn(rx), __float2half_rn(ry));
    hi = *(uint32_t*)&h2;
    lo = *(uint32_t*)&l2;
}
__device__ __forceinline__ uint32_t pack2h(float x, float y) {
    __half2 h2(__float2half_rn(x), __float2half_rn(y));
    return *(uint32_t*)&h2;
}

// ---------------------------------------------------------------------------
// fp32 -> fp16 convert (X)
// ---------------------------------------------------------------------------
__global__ __launch_bounds__(256) void cvt_kernel(
    const float* __restrict__ in, __half* __restrict__ hi, int n4)
{
    int i = blockIdx.x * blockDim.x + threadIdx.x;
    if (i >= n4) return;
    float4 v = ((const float4*)in)[i];
    ((uint32_t*)hi)[2*i]   = pack2h(v.x, v.y);
    ((uint32_t*)hi)[2*i+1] = pack2h(v.z, v.w);
}

// ---------------------------------------------------------------------------
// All 4 weights: [K x N] fp32 -> transposed fp16 [N x K].
// grid (32, 32, 4), block (32, 8)
// ---------------------------------------------------------------------------
__global__ __launch_bounds__(256) void transpose_cvt4(
    const float* __restrict__ w0, const float* __restrict__ w1,
    const float* __restrict__ w2, const float* __restrict__ w3,
    __half* __restrict__ hi)
{
    __shared__ float t[32][33];
    const int z = blockIdx.z;
    const float* in = (z == 0) ? w0 : (z == 1) ? w1 : (z == 2) ? w2 : w3;
    __half* oh = hi + (size_t)z * DD;
    int bx = blockIdx.x * 32, by = blockIdx.y * 32;
    int tx = threadIdx.x, ty = threadIdx.y;
#pragma unroll
    for (int j = ty; j < 32; j += 8)
        t[j][tx] = in[(size_t)(by + j) * DMODEL + bx + tx];
    __syncthreads();
#pragma unroll
    for (int j = ty; j < 32; j += 8) {
        float v = t[tx][j];                 // = in[by+tx][bx+j]
        oh[(size_t)(bx + j) * DMODEL + by + tx] = __float2half_rn(v);
    }
}

// ---------------------------------------------------------------------------
// QKV GEMM (1-pass fp16): C = Ah[M,K] @ Bh^T + bias -> fp16
// grid (N/128, M/128, 3): z selects W/bias/output. 4-stage cp.async pipeline.
// ---------------------------------------------------------------------------
#define G_RS       80          // row stride bytes (32 fp16 = 64B + 16B pad)
#define G_TILE_B   (128 * G_RS)          // 10240
#define Q_STAGE_B  (2 * G_TILE_B)        // Ah, Bh
#define Q_SMEM_B   (4 * Q_STAGE_B)       // 81920

__global__ __launch_bounds__(256, 2) void gemm_qkv(
    const __half* __restrict__ Ahi, const __half* __restrict__ Wt,
    const float* __restrict__ bq, const float* __restrict__ bk,
    const float* __restrict__ bv,
    __half* __restrict__ Qhi, __half* __restrict__ Khi, __half* __restrict__ Vhi,
    int M, int N, int K)
{
    extern __shared__ char smem[];
    const uint32_t sb = smem_u32(smem);
    const int z = blockIdx.z;
    const __half* Bh = Wt + (size_t)z * DD;
    const float* bias = (z == 0) ? bq : (z == 1) ? bk : bv;
    __half* Chi = (z == 0) ? Qhi : (z == 1) ? Khi : Vhi;

    const int tid = threadIdx.x, lane = tid & 31, wid = tid >> 5;
    const int brow = blockIdx.y * 128, bcol = blockIdx.x * 128;
    const int wm0 = (wid & 1) * 64;
    const int wn0 = (wid >> 1) * 32;

    float acc[4][4][4];
#pragma unroll
    for (int mi = 0; mi < 4; mi++)
#pragma unroll
        for (int ni = 0; ni < 4; ni++)
#pragma unroll
            for (int e = 0; e < 4; e++) acc[mi][ni][e] = 0.f;

    const int r0l = tid >> 2, c16a = (tid & 3) * 8;
    const int r1l = (tid + 256) >> 2;
    const int nchunks = K / 32;

    auto issue_load = [&](int st, int kt) {
        uint32_t s0 = sb + st * Q_STAGE_B;
#pragma unroll
        for (int u = 0; u < 2; u++) {
            int row = u ? r1l : r0l;
            uint32_t so = row * G_RS + c16a * 2;
            CP_ASYNC16(s0 + 0 * G_TILE_B + so, Ahi + (size_t)(brow + row) * K + kt + c16a);
            CP_ASYNC16(s0 + 1 * G_TILE_B + so, Bh  + (size_t)(bcol + row) * K + kt + c16a);
        }
    };

    issue_load(0, 0);  CP_COMMIT();
    issue_load(1, 32); CP_COMMIT();
    issue_load(2, 64); CP_COMMIT();

    for (int ch = 0; ch < nchunks; ch++) {
        if (ch + 3 < nchunks) {
            issue_load((ch + 3) & 3, (ch + 3) * 32);
            CP_COMMIT();
        }
        const int nf = nchunks - 1 - ch;
        if (nf >= 3)      CP_WAIT(3);
        else if (nf == 2) CP_WAIT(2);
        else if (nf == 1) CP_WAIT(1);
        else              CP_WAIT(0);
        __syncthreads();

        const uint32_t s0  = sb + (ch & 3) * Q_STAGE_B;
        const uint32_t sAh = s0;
        const uint32_t sBh = s0 + G_TILE_B;

#pragma unroll
        for (int ks = 0; ks < 2; ks++) {
            const uint32_t kb = ks * 32;
            uint32_t bh[4][2];
#pragma unroll
            for (int np = 0; np < 2; np++) {
                uint32_t ro = (wn0 + np * 16 + (lane & 7) + ((lane >> 4) & 1) * 8) * G_RS
                              + kb + ((lane >> 3) & 1) * 16;
                LDSM_X4(bh[np*2][0], bh[np*2][1], bh[np*2+1][0], bh[np*2+1][1], sBh + ro);
            }
#pragma unroll
            for (int mi = 0; mi < 4; mi++) {
                uint32_t ro = (wm0 + mi * 16 + (lane & 15)) * G_RS + kb + (lane >> 4) * 16;
                uint32_t ah[4];
                LDSM_X4(ah[0], ah[1], ah[2], ah[3], sAh + ro);
#pragma unroll
                for (int ni = 0; ni < 4; ni++)
                    MMA16816(acc[mi][ni], ah[0], ah[1], ah[2], ah[3], bh[ni][0], bh[ni][1]);
            }
        }
        __syncthreads();
    }

    // epilogue: fp16 out
#pragma unroll
    for (int mi = 0; mi < 4; mi++) {
#pragma unroll
        for (int ni = 0; ni < 4; ni++) {
            int r = brow + wm0 + mi * 16 + (lane >> 2);
            int c = bcol + wn0 + ni * 8 + (lane & 3) * 2;
            float bx = bias[c], by = bias[c + 1];
            *(uint32_t*)&Chi[(size_t)r * N + c] =
                pack2h(acc[mi][ni][0] + bx, acc[mi][ni][1] + by);
            *(uint32_t*)&Chi[(size_t)(r + 8) * N + c] =
                pack2h(acc[mi][ni][2] + bx, acc[mi][ni][3] + by);
        }
    }
}

// ---------------------------------------------------------------------------
// O-projection GEMM (2-pass: (Ahi+Alo) @ Bh^T): fp32 output.
// 128x128 CTA tile, BK=32, 3-stage cp.async pipeline (3 tiles/stage).
// ---------------------------------------------------------------------------
#define O_STAGE_B (3 * G_TILE_B)
#define O_SMEM_B  (3 * O_STAGE_B)    // 92160

__global__ __launch_bounds__(256, 2) void gemm_o(
    const __half* __restrict__ Ahi, const __half* __restrict__ Alo,
    const __half* __restrict__ Bhi,
    const float* __restrict__ bias, float* __restrict__ C,
    int M, int N, int K)
{
    extern __shared__ char smem[];
    const uint32_t sb = smem_u32(smem);
    const int tid = threadIdx.x, lane = tid & 31, wid = tid >> 5;
    const int brow = blockIdx.y * 128, bcol = blockIdx.x * 128;
    const int wm0 = (wid & 1) * 64;
    const int wn0 = (wid >> 1) * 32;

    float acc[4][4][4];
#pragma unroll
    for (int mi = 0; mi < 4; mi++)
#pragma unroll
        for (int ni = 0; ni < 4; ni++)
#pragma unroll
            for (int e = 0; e < 4; e++) acc[mi][ni][e] = 0.f;

    const int r0l = tid >> 2, c16a = (tid & 3) * 8;
    const int r1l = (tid + 256) >> 2;
    const int nchunks = K / 32;

    auto issue_load = [&](int st, int kt) {
        uint32_t s0 = sb + st * O_STAGE_B;
#pragma unroll
        for (int u = 0; u < 2; u++) {
            int row = u ? r1l : r0l;
            uint32_t so = row * G_RS + c16a * 2;
            CP_ASYNC16(s0 + 0 * G_TILE_B + so, Ahi + (size_t)(brow + row) * K + kt + c16a);
            CP_ASYNC16(s0 + 1 * G_TILE_B + so, Alo + (size_t)(brow + row) * K + kt + c16a);
            CP_ASYNC16(s0 + 2 * G_TILE_B + so, Bhi + (size_t)(bcol + row) * K + kt + c16a);
        }
    };

    issue_load(0, 0);  CP_COMMIT();
    issue_load(1, 32); CP_COMMIT();

    for (int ch = 0; ch < nchunks; ch++) {
        if (ch + 2 < nchunks) {
            issue_load((ch + 2) % 3, (ch + 2) * 32);
            CP_COMMIT();
            CP_WAIT(2);
        } else if (ch + 1 < nchunks) {
            CP_WAIT(1);
        } else {
            CP_WAIT(0);
        }
        __syncthreads();

        const uint32_t s0  = sb + (ch % 3) * O_STAGE_B;
        const uint32_t sAh = s0;
        const uint32_t sAl = s0 + G_TILE_B;
        const uint32_t sBh = s0 + 2 * G_TILE_B;

#pragma unroll
        for (int ks = 0; ks < 2; ks++) {
            const uint32_t kb = ks * 32;
            uint32_t bh[4][2];
#pragma unroll
            for (int np = 0; np < 2; np++) {
                uint32_t ro = (wn0 + np * 16 + (lane & 7) + ((lane >> 4) & 1) * 8) * G_RS
                              + kb + ((lane >> 3) & 1) * 16;
                LDSM_X4(bh[np*2][0], bh[np*2][1], bh[np*2+1][0], bh[np*2+1][1], sBh + ro);
            }
#pragma unroll
            for (int mi = 0; mi < 4; mi++) {
                uint32_t ro = (wm0 + mi * 16 + (lane & 15)) * G_RS + kb + (lane >> 4) * 16;
                uint32_t ah[4], al[4];
                LDSM_X4(ah[0], ah[1], ah[2], ah[3], sAh + ro);
                LDSM_X4(al[0], al[1], al[2], al[3], sAl + ro);
#pragma unroll
                for (int ni = 0; ni < 4; ni++) {
                    MMA16816(acc[mi][ni], ah[0], ah[1], ah[2], ah[3], bh[ni][0], bh[ni][1]);
                    MMA16816(acc[mi][ni], al[0], al[1], al[2], al[3], bh[ni][0], bh[ni][1]);
                }
            }
        }
        __syncthreads();
    }

#pragma unroll
    for (int mi = 0; mi < 4; mi++) {
#pragma unroll
        for (int ni = 0; ni < 4; ni++) {
            int r = brow + wm0 + mi * 16 + (lane >> 2);
            int c = bcol + wn0 + ni * 8 + (lane & 3) * 2;
            float bx = bias[c], by = bias[c + 1];
            *(float2*)&C[(size_t)r * N + c] =
                make_float2(acc[mi][ni][0] + bx, acc[mi][ni][1] + by);
            *(float2*)&C[(size_t)(r + 8) * N + c] =
                make_float2(acc[mi][ni][2] + bx, acc[mi][ni][3] + by);
        }
    }
}

// ---------------------------------------------------------------------------
// Tensor-core banded attention (fp16, 1-pass QK and PV).
// grid = (S/64, H, B), block = 128 (4 warps x 16 q-rows).
// Q/K/V single fp16; output split hi/lo for the 2-pass O-projection.
// ---------------------------------------------------------------------------
#define AT_RS    144                 // smem row stride bytes (72 fp16)
#define AT_TILE  (64 * AT_RS)        // 9216 B
#define AT_SQH   0
#define AT_ST0   AT_TILE
#define AT_STB   (2 * AT_TILE)       // Kh, Vh per stage
#define AT_SMEM  (AT_TILE + 2 * AT_STB)   // 46080 B

__global__ __launch_bounds__(128) void attn_tc(
    const __half* __restrict__ Qh, const __half* __restrict__ Kh,
    const __half* __restrict__ Vh,
    __half* __restrict__ Oh, __half* __restrict__ Ol)
{
    extern __shared__ char smem[];
    const uint32_t sb = smem_u32(smem);
    const int qt = blockIdx.x, h = blockIdx.y, b = blockIdx.z;
    const int q0 = qt * 64;
    const int tid = threadIdx.x, lane = tid & 31, w = tid >> 5;
    const float scale = 0.125f;

    const int lrow = tid >> 1;
    const int lhalf = (tid & 1) * 64;
    const int gcol = h * DHEAD + (lhalf >> 1);

    const int kb_lo = max(0, q0 - (WINDOW - 1)) >> 6;
    const int nch = qt - kb_lo + 1;

    // prologue: Q + first K/V chunk
    {
        size_t g = ((size_t)(b * SEQ + q0 + lrow)) * DMODEL + gcol;
        uint32_t so = lrow * AT_RS + lhalf;
#pragma unroll
        for (int i = 0; i < 4; i++)
            CP_ASYNC16(sb + AT_SQH + so + i * 16, Qh + g + i * 8);
        size_t gk = ((size_t)(b * SEQ + kb_lo * 64 + lrow)) * DMODEL + gcol;
        uint32_t s0 = sb + AT_ST0;
#pragma unroll
        for (int i = 0; i < 4; i++) {
            CP_ASYNC16(s0 + 0 * AT_TILE + so + i * 16, Kh + gk + i * 8);
            CP_ASYNC16(s0 + 1 * AT_TILE + so + i * 16, Vh + gk + i * 8);
        }
        CP_COMMIT();
    }

    float m0 = -1e30f, m1 = -1e30f, l0 = 0.f, l1 = 0.f;
    float oacc[8][4];
#pragma unroll
    for (int t = 0; t < 8; t++)
#pragma unroll
        for (int e = 0; e < 4; e++) oacc[t][e] = 0.f;

    const int r0g = q0 + w * 16 + (lane >> 2);
    const int r1g = r0g + 8;

    for (int i = 0; i < nch; i++) {
        const int kb = kb_lo + i;
        if (i + 1 < nch) {
            size_t gk = ((size_t)(b * SEQ + (kb + 1) * 64 + lrow)) * DMODEL + gcol;
            uint32_t s0 = sb + AT_ST0 + ((i + 1) & 1) * AT_STB;
            uint32_t so = lrow * AT_RS + lhalf;
#pragma unroll
            for (int u = 0; u < 4; u++) {
                CP_ASYNC16(s0 + 0 * AT_TILE + so + u * 16, Kh + gk + u * 8);
                CP_ASYNC16(s0 + 1 * AT_TILE + so + u * 16, Vh + gk + u * 8);
            }
            CP_COMMIT();
            CP_WAIT(1);
        } else {
            CP_WAIT(0);
        }
        __syncthreads();

        const uint32_t s0  = sb + AT_ST0 + (i & 1) * AT_STB;
        const uint32_t sKh = s0;
        const uint32_t sVh = s0 + AT_TILE;

        // ---- S = Q K^T (1-pass) ----
        float sacc[8][4];
#pragma unroll
        for (int t = 0; t < 8; t++)
#pragma unroll
            for (int e = 0; e < 4; e++) sacc[t][e] = 0.f;

#pragma unroll
        for (int ks = 0; ks < 4; ks++) {
            const uint32_t kbb = ks * 32;
            uint32_t aro = (w * 16 + (lane & 15)) * AT_RS + kbb + (lane >> 4) * 16;
            uint32_t ah[4];
            LDSM_X4(ah[0], ah[1], ah[2], ah[3], sb + AT_SQH + aro);
#pragma unroll
            for (int np = 0; np < 4; np++) {
                uint32_t ro = (np * 16 + (lane & 7) + ((lane >> 4) & 1) * 8) * AT_RS
                              + kbb + ((lane >> 3) & 1) * 16;
                uint32_t bh[4];
                LDSM_X4(bh[0], bh[1], bh[2], bh[3], sKh + ro);
                MMA16816(sacc[2*np],   ah[0], ah[1], ah[2], ah[3], bh[0], bh[1]);
                MMA16816(sacc[2*np+1], ah[0], ah[1], ah[2], ah[3], bh[2], bh[3]);
            }
        }

        // ---- mask + online softmax ----
        const int kbase = kb * 64;
        float cmax0 = -1e30f, cmax1 = -1e30f;
#pragma unroll
        for (int t = 0; t < 8; t++) {
            const int c0 = kbase + t * 8 + 2 * (lane & 3);
            int d00 = r0g - c0, d01 = r0g - (c0 + 1);
            int d10 = r1g - c0, d11 = r1g - (c0 + 1);
            sacc[t][0] = (d00 >= 0 && d00 < WINDOW) ? sacc[t][0] * scale : -1e30f;
            sacc[t][1] = (d01 >= 0 && d01 < WINDOW) ? sacc[t][1] * scale : -1e30f;
            sacc[t][2] = (d10 >= 0 && d10 < WINDOW) ? sacc[t][2] * scale : -1e30f;
            sacc[t][3] = (d11 >= 0 && d11 < WINDOW) ? sacc[t][3] * scale : -1e30f;
            cmax0 = fmaxf(cmax0, fmaxf(sacc[t][0], sacc[t][1]));
            cmax1 = fmaxf(cmax1, fmaxf(sacc[t][2], sacc[t][3]));
        }
        cmax0 = fmaxf(cmax0, __shfl_xor_sync(0xffffffffu, cmax0, 1));
        cmax0 = fmaxf(cmax0, __shfl_xor_sync(0xffffffffu, cmax0, 2));
        cmax1 = fmaxf(cmax1, __shfl_xor_sync(0xffffffffu, cmax1, 1));
        cmax1 = fmaxf(cmax1, __shfl_xor_sync(0xffffffffu, cmax1, 2));

        float mn0 = fmaxf(m0, cmax0), mn1 = fmaxf(m1, cmax1);
        float a0 = __expf(m0 - mn0), a1 = __expf(m1 - mn1);
        float rs0 = 0.f, rs1 = 0.f;
#pragma unroll
        for (int t = 0; t < 8; t++) {
            sacc[t][0] = __expf(sacc[t][0] - mn0);
            sacc[t][1] = __expf(sacc[t][1] - mn0);
            sacc[t][2] = __expf(sacc[t][2] - mn1);
            sacc[t][3] = __expf(sacc[t][3] - mn1);
            rs0 += sacc[t][0] + sacc[t][1];
            rs1 += sacc[t][2] + sacc[t][3];
        }
        rs0 += __shfl_xor_sync(0xffffffffu, rs0, 1);
        rs0 += __shfl_xor_sync(0xffffffffu, rs0, 2);
        rs1 += __shfl_xor_sync(0xffffffffu, rs1, 1);
        rs1 += __shfl_xor_sync(0xffffffffu, rs1, 2);
        l0 = l0 * a0 + rs0;  m0 = mn0;
        l1 = l1 * a1 + rs1;  m1 = mn1;
#pragma unroll
        for (int t = 0; t < 8; t++) {
            oacc[t][0] *= a0; oacc[t][1] *= a0;
            oacc[t][2] *= a1; oacc[t][3] *= a1;
        }

        // ---- PV (1-pass: P rounded to fp16; V via ldmatrix.trans) ----
#pragma unroll
        for (int ks = 0; ks < 4; ks++) {
            uint32_t aph[4];
            aph[0] = pack2h(sacc[2*ks][0],   sacc[2*ks][1]);
            aph[1] = pack2h(sacc[2*ks][2],   sacc[2*ks][3]);
            aph[2] = pack2h(sacc[2*ks+1][0], sacc[2*ks+1][1]);
            aph[3] = pack2h(sacc[2*ks+1][2], sacc[2*ks+1][3]);
#pragma unroll
            for (int np = 0; np < 4; np++) {
                uint32_t vro = (ks * 16 + (lane & 7) + ((lane >> 3) & 1) * 8) * AT_RS
                               + np * 32 + (lane >> 4) * 16;
                uint32_t vh[4];
                LDSM_X4_T(vh[0], vh[1], vh[2], vh[3], sVh + vro);
                MMA16816(oacc[2*np],   aph[0], aph[1], aph[2], aph[3], vh[0], vh[1]);
                MMA16816(oacc[2*np+1], aph[0], aph[1], aph[2], aph[3], vh[2], vh[3]);
            }
        }
        __syncthreads();
    }

    // ---- epilogue: divide by l, split to fp16 hi/lo, store ----
    const float inv0 = 1.f / l0, inv1 = 1.f / l1;
    const size_t row0 = (size_t)(b * SEQ + r0g) * DMODEL;
    const size_t row1 = (size_t)(b * SEQ + r1g) * DMODEL;
#pragma unroll
    for (int t = 0; t < 8; t++) {
        const int c = h * DHEAD + t * 8 + 2 * (lane & 3);
        uint32_t h0, lo0, h1, lo1;
        split2h(oacc[t][0] * inv0, oacc[t][1] * inv0, h0, lo0);
        split2h(oacc[t][2] * inv1, oacc[t][3] * inv1, h1, lo1);
        *(uint32_t*)&Oh[row0 + c] = h0;
        *(uint32_t*)&Ol[row0 + c] = lo0;
        *(uint32_t*)&Oh[row1 + c] = h1;
        *(uint32_t*)&Ol[row1 + c] = lo1;
    }
}

// ---------------------------------------------------------------------------
// Launch
// ---------------------------------------------------------------------------
extern "C" void kernel_launch(void* const* d_in, const int* in_sizes, int n_in,
                              void* d_out, int out_size)
{
    const float* X  = (const float*)d_in[0];
    const float* Wq = (const float*)d_in[1];
    const float* bq = (const float*)d_in[2];
    const float* Wk = (const float*)d_in[3];
    const float* bk = (const float*)d_in[4];
    const float* Wv = (const float*)d_in[5];
    const float* bv = (const float*)d_in[6];
    const float* Wo = (const float*)d_in[7];
    const float* bo = (const float*)d_in[8];
    float* out = (float*)d_out;

    __half *xhi, *qhi, *khi, *vhi, *aohi, *aolo, *wthi;
    cudaGetSymbolAddress((void**)&xhi,  g_xhi);
    cudaGetSymbolAddress((void**)&qhi,  g_qhi);
    cudaGetSymbolAddress((void**)&khi,  g_khi);
    cudaGetSymbolAddress((void**)&vhi,  g_vhi);
    cudaGetSymbolAddress((void**)&aohi, g_aohi);
    cudaGetSymbolAddress((void**)&aolo, g_aolo);
    cudaGetSymbolAddress((void**)&wthi, g_wthi);

    cudaFuncSetAttribute(attn_tc,  cudaFuncAttributeMaxDynamicSharedMemorySize, AT_SMEM);
    cudaFuncSetAttribute(gemm_qkv, cudaFuncAttributeMaxDynamicSharedMemorySize, Q_SMEM_B);
    cudaFuncSetAttribute(gemm_o,   cudaFuncAttributeMaxDynamicSharedMemorySize, O_SMEM_B);

    // 1. convert X -> fp16
    cvt_kernel<<<(MROWS * DMODEL / 4 + 255) / 256, 256>>>(X, xhi, MROWS * DMODEL / 4);

    // 2. all 4 weight transposes in one launch
    transpose_cvt4<<<dim3(32, 32, 4), dim3(32, 8)>>>(Wq, Wk, Wv, Wo, wthi);

    // 3. fused Q/K/V projections (1-pass fp16)
    gemm_qkv<<<dim3(DMODEL / 128, MROWS / 128, 3), 256, Q_SMEM_B>>>(
        xhi, wthi, bq, bk, bv, qhi, khi, vhi, MROWS, DMODEL, DMODEL);

    // 4. tensor-core banded attention (1-pass QK/PV)
    attn_tc<<<dim3(SEQ / 64, NHEADS, BATCH), 128, AT_SMEM>>>(qhi, khi, vhi, aohi, aolo);

    // 5. O projection (2-pass) -> fp32 output
    gemm_o<<<dim3(DMODEL / 128, MROWS / 128), 256, O_SMEM_B>>>(
        aohi, aolo, wthi + 3 * DD, bo, out, MROWS, DMODEL, DMODEL);
}

// round 8
// speedup vs baseline: 7.9056x; 1.1879x over previous
#include <cuda_runtime.h>
#include <cuda_fp16.h>
#include <cstdint>
#include <math.h>

// ---------------------------------------------------------------------------
// Problem constants (B=2, S=2048, D=1024, H=16)
// ---------------------------------------------------------------------------
#define BATCH   2
#define SEQ     2048
#define DMODEL  1024
#define NHEADS  16
#define DHEAD   64
#define WINDOW  256
#define MROWS   (BATCH * SEQ)   // 4096
#define DD      (DMODEL * DMODEL)

// ---------------------------------------------------------------------------
// Scratch (__device__ globals; allocation-free rule)
// ---------------------------------------------------------------------------
__device__ __half g_xhi [MROWS * DMODEL];
__device__ __half g_qhi [MROWS * DMODEL];
__device__ __half g_khi [MROWS * DMODEL];
__device__ __half g_vhi [MROWS * DMODEL];
__device__ __half g_aohi[MROWS * DMODEL];
__device__ __half g_wthi[4 * DD];   // transposed weights [N][K], fp16

// ---------------------------------------------------------------------------
// PTX helpers — base sm_100 ISA only (mma.sync / ldmatrix / cp.async)
// ---------------------------------------------------------------------------
__device__ __forceinline__ uint32_t smem_u32(const void* p) {
    uint32_t a;
    asm("{ .reg .u64 t; cvta.to.shared.u64 t, %1; cvt.u32.u64 %0, t; }" : "=r"(a) : "l"(p));
    return a;
}

#define CP_ASYNC16(dst, src) \
    asm volatile("cp.async.cg.shared.global [%0], [%1], 16;" :: "r"(dst), "l"(src))
#define CP_COMMIT() asm volatile("cp.async.commit_group;" ::: "memory")
#define CP_WAIT(n)  asm volatile("cp.async.wait_group %0;" :: "n"(n) : "memory")

#define LDSM_X4(r0, r1, r2, r3, addr) \
    asm volatile("ldmatrix.sync.aligned.m8n8.x4.shared.b16 {%0,%1,%2,%3}, [%4];" \
        : "=r"(r0), "=r"(r1), "=r"(r2), "=r"(r3) : "r"(addr))

#define LDSM_X4_T(r0, r1, r2, r3, addr) \
    asm volatile("ldmatrix.sync.aligned.m8n8.x4.trans.shared.b16 {%0,%1,%2,%3}, [%4];" \
        : "=r"(r0), "=r"(r1), "=r"(r2), "=r"(r3) : "r"(addr))

#define MMA16816(d, a0, a1, a2, a3, b0, b1) \
    asm volatile("mma.sync.aligned.m16n8k16.row.col.f32.f16.f16.f32 " \
        "{%0,%1,%2,%3}, {%4,%5,%6,%7}, {%8,%9}, {%0,%1,%2,%3};" \
        : "+f"((d)[0]), "+f"((d)[1]), "+f"((d)[2]), "+f"((d)[3]) \
        : "r"(a0), "r"(a1), "r"(a2), "r"(a3), "r"(b0), "r"(b1))

__device__ __forceinline__ uint32_t pack2h(float x, float y) {
    __half2 h2(__float2half_rn(x), __float2half_rn(y));
    return *(uint32_t*)&h2;
}

// ---------------------------------------------------------------------------
// Prep: z=0..3 -> weight transpose+cvt ([KxN] fp32 -> [NxK] fp16);
//       z=4    -> X fp32 -> fp16 elementwise convert.
// grid (32, 32, 5), block (32, 8)
// ---------------------------------------------------------------------------
__global__ __launch_bounds__(256) void prep_kernel(
    const float* __restrict__ X,
    const float* __restrict__ w0, const float* __restrict__ w1,
    const float* __restrict__ w2, const float* __restrict__ w3,
    __half* __restrict__ xh, __half* __restrict__ hi)
{
    const int z = blockIdx.z;
    const int tx = threadIdx.x, ty = threadIdx.y;

    if (z == 4) {
        // X convert: 1M float4 items over 1024 blocks x 256 threads x 4 iters
        const int bid = blockIdx.y * 32 + blockIdx.x;
        const int tid = ty * 32 + tx;
#pragma unroll
        for (int it = 0; it < 4; it++) {
            int i = bid * 1024 + it * 256 + tid;
            float4 v = ((const float4*)X)[i];
            ((uint32_t*)xh)[2*i]   = pack2h(v.x, v.y);
            ((uint32_t*)xh)[2*i+1] = pack2h(v.z, v.w);
        }
        return;
    }

    __shared__ float t[32][33];
    const float* in = (z == 0) ? w0 : (z == 1) ? w1 : (z == 2) ? w2 : w3;
    __half* oh = hi + (size_t)z * DD;
    int bx = blockIdx.x * 32, by = blockIdx.y * 32;
#pragma unroll
    for (int j = ty; j < 32; j += 8)
        t[j][tx] = in[(size_t)(by + j) * DMODEL + bx + tx];
    __syncthreads();
#pragma unroll
    for (int j = ty; j < 32; j += 8) {
        float v = t[tx][j];                 // = in[by+tx][bx+j]
        oh[(size_t)(bx + j) * DMODEL + by + tx] = __float2half_rn(v);
    }
}

// ---------------------------------------------------------------------------
// QKV GEMM (1-pass fp16): C = Ah[M,K] @ Bh^T + bias -> fp16
// grid (N/128, M/128, 3): z selects W/bias/output. 4-stage cp.async pipeline.
// ---------------------------------------------------------------------------
#define G_RS       80          // row stride bytes (32 fp16 = 64B + 16B pad)
#define G_TILE_B   (128 * G_RS)          // 10240
#define Q_STAGE_B  (2 * G_TILE_B)        // Ah, Bh
#define Q_SMEM_B   (4 * Q_STAGE_B)       // 81920

__global__ __launch_bounds__(256, 2) void gemm_qkv(
    const __half* __restrict__ Ahi, const __half* __restrict__ Wt,
    const float* __restrict__ bq, const float* __restrict__ bk,
    const float* __restrict__ bv,
    __half* __restrict__ Qhi, __half* __restrict__ Khi, __half* __restrict__ Vhi,
    int M, int N, int K)
{
    extern __shared__ char smem[];
    const uint32_t sb = smem_u32(smem);
    const int z = blockIdx.z;
    const __half* Bh = Wt + (size_t)z * DD;
    const float* bias = (z == 0) ? bq : (z == 1) ? bk : bv;
    __half* Chi = (z == 0) ? Qhi : (z == 1) ? Khi : Vhi;

    const int tid = threadIdx.x, lane = tid & 31, wid = tid >> 5;
    const int brow = blockIdx.y * 128, bcol = blockIdx.x * 128;
    const int wm0 = (wid & 1) * 64;
    const int wn0 = (wid >> 1) * 32;

    float acc[4][4][4];
#pragma unroll
    for (int mi = 0; mi < 4; mi++)
#pragma unroll
        for (int ni = 0; ni < 4; ni++)
#pragma unroll
            for (int e = 0; e < 4; e++) acc[mi][ni][e] = 0.f;

    const int r0l = tid >> 2, c16a = (tid & 3) * 8;
    const int r1l = (tid + 256) >> 2;
    const int nchunks = K / 32;

    auto issue_load = [&](int st, int kt) {
        uint32_t s0 = sb + st * Q_STAGE_B;
#pragma unroll
        for (int u = 0; u < 2; u++) {
            int row = u ? r1l : r0l;
            uint32_t so = row * G_RS + c16a * 2;
            CP_ASYNC16(s0 + 0 * G_TILE_B + so, Ahi + (size_t)(brow + row) * K + kt + c16a);
            CP_ASYNC16(s0 + 1 * G_TILE_B + so, Bh  + (size_t)(bcol + row) * K + kt + c16a);
        }
    };

    issue_load(0, 0);  CP_COMMIT();
    issue_load(1, 32); CP_COMMIT();
    issue_load(2, 64); CP_COMMIT();

    for (int ch = 0; ch < nchunks; ch++) {
        if (ch + 3 < nchunks) {
            issue_load((ch + 3) & 3, (ch + 3) * 32);
            CP_COMMIT();
        }
        const int nf = nchunks - 1 - ch;
        if (nf >= 3)      CP_WAIT(3);
        else if (nf == 2) CP_WAIT(2);
        else if (nf == 1) CP_WAIT(1);
        else              CP_WAIT(0);
        __syncthreads();

        const uint32_t s0  = sb + (ch & 3) * Q_STAGE_B;
        const uint32_t sAh = s0;
        const uint32_t sBh = s0 + G_TILE_B;

#pragma unroll
        for (int ks = 0; ks < 2; ks++) {
            const uint32_t kb = ks * 32;
            uint32_t bh[4][2];
#pragma unroll
            for (int np = 0; np < 2; np++) {
                uint32_t ro = (wn0 + np * 16 + (lane & 7) + ((lane >> 4) & 1) * 8) * G_RS
                              + kb + ((lane >> 3) & 1) * 16;
                LDSM_X4(bh[np*2][0], bh[np*2][1], bh[np*2+1][0], bh[np*2+1][1], sBh + ro);
            }
#pragma unroll
            for (int mi = 0; mi < 4; mi++) {
                uint32_t ro = (wm0 + mi * 16 + (lane & 15)) * G_RS + kb + (lane >> 4) * 16;
                uint32_t ah[4];
                LDSM_X4(ah[0], ah[1], ah[2], ah[3], sAh + ro);
#pragma unroll
                for (int ni = 0; ni < 4; ni++)
                    MMA16816(acc[mi][ni], ah[0], ah[1], ah[2], ah[3], bh[ni][0], bh[ni][1]);
            }
        }
        __syncthreads();
    }

    // epilogue: fp16 out
#pragma unroll
    for (int mi = 0; mi < 4; mi++) {
#pragma unroll
        for (int ni = 0; ni < 4; ni++) {
            int r = brow + wm0 + mi * 16 + (lane >> 2);
            int c = bcol + wn0 + ni * 8 + (lane & 3) * 2;
            float bx = bias[c], by = bias[c + 1];
            *(uint32_t*)&Chi[(size_t)r * N + c] =
                pack2h(acc[mi][ni][0] + bx, acc[mi][ni][1] + by);
            *(uint32_t*)&Chi[(size_t)(r + 8) * N + c] =
                pack2h(acc[mi][ni][2] + bx, acc[mi][ni][3] + by);
        }
    }
}

// ---------------------------------------------------------------------------
// O-projection GEMM (1-pass fp16): C = Ah @ Bh^T + bias -> fp32.
// Same 4-stage / 2-tile pipeline as gemm_qkv.
// ---------------------------------------------------------------------------
__global__ __launch_bounds__(256, 2) void gemm_o(
    const __half* __restrict__ Ahi, const __half* __restrict__ Bhi,
    const float* __restrict__ bias, float* __restrict__ C,
    int M, int N, int K)
{
    extern __shared__ char smem[];
    const uint32_t sb = smem_u32(smem);
    const int tid = threadIdx.x, lane = tid & 31, wid = tid >> 5;
    const int brow = blockIdx.y * 128, bcol = blockIdx.x * 128;
    const int wm0 = (wid & 1) * 64;
    const int wn0 = (wid >> 1) * 32;

    float acc[4][4][4];
#pragma unroll
    for (int mi = 0; mi < 4; mi++)
#pragma unroll
        for (int ni = 0; ni < 4; ni++)
#pragma unroll
            for (int e = 0; e < 4; e++) acc[mi][ni][e] = 0.f;

    const int r0l = tid >> 2, c16a = (tid & 3) * 8;
    const int r1l = (tid + 256) >> 2;
    const int nchunks = K / 32;

    auto issue_load = [&](int st, int kt) {
        uint32_t s0 = sb + st * Q_STAGE_B;
#pragma unroll
        for (int u = 0; u < 2; u++) {
            int row = u ? r1l : r0l;
            uint32_t so = row * G_RS + c16a * 2;
            CP_ASYNC16(s0 + 0 * G_TILE_B + so, Ahi + (size_t)(brow + row) * K + kt + c16a);
            CP_ASYNC16(s0 + 1 * G_TILE_B + so, Bhi + (size_t)(bcol + row) * K + kt + c16a);
        }
    };

    issue_load(0, 0);  CP_COMMIT();
    issue_load(1, 32); CP_COMMIT();
    issue_load(2, 64); CP_COMMIT();

    for (int ch = 0; ch < nchunks; ch++) {
        if (ch + 3 < nchunks) {
            issue_load((ch + 3) & 3, (ch + 3) * 32);
            CP_COMMIT();
        }
        const int nf = nchunks - 1 - ch;
        if (nf >= 3)      CP_WAIT(3);
        else if (nf == 2) CP_WAIT(2);
        else if (nf == 1) CP_WAIT(1);
        else              CP_WAIT(0);
        __syncthreads();

        const uint32_t s0  = sb + (ch & 3) * Q_STAGE_B;
        const uint32_t sAh = s0;
        const uint32_t sBh = s0 + G_TILE_B;

#pragma unroll
        for (int ks = 0; ks < 2; ks++) {
            const uint32_t kb = ks * 32;
            uint32_t bh[4][2];
#pragma unroll
            for (int np = 0; np < 2; np++) {
                uint32_t ro = (wn0 + np * 16 + (lane & 7) + ((lane >> 4) & 1) * 8) * G_RS
                              + kb + ((lane >> 3) & 1) * 16;
                LDSM_X4(bh[np*2][0], bh[np*2][1], bh[np*2+1][0], bh[np*2+1][1], sBh + ro);
            }
#pragma unroll
            for (int mi = 0; mi < 4; mi++) {
                uint32_t ro = (wm0 + mi * 16 + (lane & 15)) * G_RS + kb + (lane >> 4) * 16;
                uint32_t ah[4];
                LDSM_X4(ah[0], ah[1], ah[2], ah[3], sAh + ro);
#pragma unroll
                for (int ni = 0; ni < 4; ni++)
                    MMA16816(acc[mi][ni], ah[0], ah[1], ah[2], ah[3], bh[ni][0], bh[ni][1]);
            }
        }
        __syncthreads();
    }

#pragma unroll
    for (int mi = 0; mi < 4; mi++) {
#pragma unroll
        for (int ni = 0; ni < 4; ni++) {
            int r = brow + wm0 + mi * 16 + (lane >> 2);
            int c = bcol + wn0 + ni * 8 + (lane & 3) * 2;
            float bx = bias[c], by = bias[c + 1];
            *(float2*)&C[(size_t)r * N + c] =
                make_float2(acc[mi][ni][0] + bx, acc[mi][ni][1] + by);
            *(float2*)&C[(size_t)(r + 8) * N + c] =
                make_float2(acc[mi][ni][2] + bx, acc[mi][ni][3] + by);
        }
    }
}

// ---------------------------------------------------------------------------
// Tensor-core banded attention (fp16, 1-pass QK and PV).
// grid = (S/64, H, B), block = 128 (4 warps x 16 q-rows).
// Plain fp16 output (O-projection is 1-pass now).
// ---------------------------------------------------------------------------
#define AT_RS    144                 // smem row stride bytes (72 fp16)
#define AT_TILE  (64 * AT_RS)        // 9216 B
#define AT_SQH   0
#define AT_ST0   AT_TILE
#define AT_STB   (2 * AT_TILE)       // Kh, Vh per stage
#define AT_SMEM  (AT_TILE + 2 * AT_STB)   // 46080 B

__global__ __launch_bounds__(128) void attn_tc(
    const __half* __restrict__ Qh, const __half* __restrict__ Kh,
    const __half* __restrict__ Vh, __half* __restrict__ Oh)
{
    extern __shared__ char smem[];
    const uint32_t sb = smem_u32(smem);
    const int qt = blockIdx.x, h = blockIdx.y, b = blockIdx.z;
    const int q0 = qt * 64;
    const int tid = threadIdx.x, lane = tid & 31, w = tid >> 5;
    const float scale = 0.125f;

    const int lrow = tid >> 1;
    const int lhalf = (tid & 1) * 64;
    const int gcol = h * DHEAD + (lhalf >> 1);

    const int kb_lo = max(0, q0 - (WINDOW - 1)) >> 6;
    const int nch = qt - kb_lo + 1;

    // prologue: Q + first K/V chunk
    {
        size_t g = ((size_t)(b * SEQ + q0 + lrow)) * DMODEL + gcol;
        uint32_t so = lrow * AT_RS + lhalf;
#pragma unroll
        for (int i = 0; i < 4; i++)
            CP_ASYNC16(sb + AT_SQH + so + i * 16, Qh + g + i * 8);
        size_t gk = ((size_t)(b * SEQ + kb_lo * 64 + lrow)) * DMODEL + gcol;
        uint32_t s0 = sb + AT_ST0;
#pragma unroll
        for (int i = 0; i < 4; i++) {
            CP_ASYNC16(s0 + 0 * AT_TILE + so + i * 16, Kh + gk + i * 8);
            CP_ASYNC16(s0 + 1 * AT_TILE + so + i * 16, Vh + gk + i * 8);
        }
        CP_COMMIT();
    }

    float m0 = -1e30f, m1 = -1e30f, l0 = 0.f, l1 = 0.f;
    float oacc[8][4];
#pragma unroll
    for (int t = 0; t < 8; t++)
#pragma unroll
        for (int e = 0; e < 4; e++) oacc[t][e] = 0.f;

    const int r0g = q0 + w * 16 + (lane >> 2);
    const int r1g = r0g + 8;

    for (int i = 0; i < nch; i++) {
        const int kb = kb_lo + i;
        if (i + 1 < nch) {
            size_t gk = ((size_t)(b * SEQ + (kb + 1) * 64 + lrow)) * DMODEL + gcol;
            uint32_t s0 = sb + AT_ST0 + ((i + 1) & 1) * AT_STB;
            uint32_t so = lrow * AT_RS + lhalf;
#pragma unroll
            for (int u = 0; u < 4; u++) {
                CP_ASYNC16(s0 + 0 * AT_TILE + so + u * 16, Kh + gk + u * 8);
                CP_ASYNC16(s0 + 1 * AT_TILE + so + u * 16, Vh + gk + u * 8);
            }
            CP_COMMIT();
            CP_WAIT(1);
        } else {
            CP_WAIT(0);
        }
        __syncthreads();

        const uint32_t s0  = sb + AT_ST0 + (i & 1) * AT_STB;
        const uint32_t sKh = s0;
        const uint32_t sVh = s0 + AT_TILE;

        // ---- S = Q K^T (1-pass) ----
        float sacc[8][4];
#pragma unroll
        for (int t = 0; t < 8; t++)
#pragma unroll
            for (int e = 0; e < 4; e++) sacc[t][e] = 0.f;

#pragma unroll
        for (int ks = 0; ks < 4; ks++) {
            const uint32_t kbb = ks * 32;
            uint32_t aro = (w * 16 + (lane & 15)) * AT_RS + kbb + (lane >> 4) * 16;
            uint32_t ah[4];
            LDSM_X4(ah[0], ah[1], ah[2], ah[3], sb + AT_SQH + aro);
#pragma unroll
            for (int np = 0; np < 4; np++) {
                uint32_t ro = (np * 16 + (lane & 7) + ((lane >> 4) & 1) * 8) * AT_RS
                              + kbb + ((lane >> 3) & 1) * 16;
                uint32_t bh[4];
                LDSM_X4(bh[0], bh[1], bh[2], bh[3], sKh + ro);
                MMA16816(sacc[2*np],   ah[0], ah[1], ah[2], ah[3], bh[0], bh[1]);
                MMA16816(sacc[2*np+1], ah[0], ah[1], ah[2], ah[3], bh[2], bh[3]);
            }
        }

        // ---- mask + online softmax ----
        const int kbase = kb * 64;
        float cmax0 = -1e30f, cmax1 = -1e30f;
#pragma unroll
        for (int t = 0; t < 8; t++) {
            const int c0 = kbase + t * 8 + 2 * (lane & 3);
            int d00 = r0g - c0, d01 = r0g - (c0 + 1);
            int d10 = r1g - c0, d11 = r1g - (c0 + 1);
            sacc[t][0] = (d00 >= 0 && d00 < WINDOW) ? sacc[t][0] * scale : -1e30f;
            sacc[t][1] = (d01 >= 0 && d01 < WINDOW) ? sacc[t][1] * scale : -1e30f;
            sacc[t][2] = (d10 >= 0 && d10 < WINDOW) ? sacc[t][2] * scale : -1e30f;
            sacc[t][3] = (d11 >= 0 && d11 < WINDOW) ? sacc[t][3] * scale : -1e30f;
            cmax0 = fmaxf(cmax0, fmaxf(sacc[t][0], sacc[t][1]));
            cmax1 = fmaxf(cmax1, fmaxf(sacc[t][2], sacc[t][3]));
        }
        cmax0 = fmaxf(cmax0, __shfl_xor_sync(0xffffffffu, cmax0, 1));
        cmax0 = fmaxf(cmax0, __shfl_xor_sync(0xffffffffu, cmax0, 2));
        cmax1 = fmaxf(cmax1, __shfl_xor_sync(0xffffffffu, cmax1, 1));
        cmax1 = fmaxf(cmax1, __shfl_xor_sync(0xffffffffu, cmax1, 2));

        float mn0 = fmaxf(m0, cmax0), mn1 = fmaxf(m1, cmax1);
        float a0 = __expf(m0 - mn0), a1 = __expf(m1 - mn1);
        float rs0 = 0.f, rs1 = 0.f;
#pragma unroll
        for (int t = 0; t < 8; t++) {
            sacc[t][0] = __expf(sacc[t][0] - mn0);
            sacc[t][1] = __expf(sacc[t][1] - mn0);
            sacc[t][2] = __expf(sacc[t][2] - mn1);
            sacc[t][3] = __expf(sacc[t][3] - mn1);
            rs0 += sacc[t][0] + sacc[t][1];
            rs1 += sacc[t][2] + sacc[t][3];
        }
        rs0 += __shfl_xor_sync(0xffffffffu, rs0, 1);
        rs0 += __shfl_xor_sync(0xffffffffu, rs0, 2);
        rs1 += __shfl_xor_sync(0xffffffffu, rs1, 1);
        rs1 += __shfl_xor_sync(0xffffffffu, rs1, 2);
        l0 = l0 * a0 + rs0;  m0 = mn0;
        l1 = l1 * a1 + rs1;  m1 = mn1;
#pragma unroll
        for (int t = 0; t < 8; t++) {
            oacc[t][0] *= a0; oacc[t][1] *= a0;
            oacc[t][2] *= a1; oacc[t][3] *= a1;
        }

        // ---- PV (1-pass: P rounded to fp16; V via ldmatrix.trans) ----
#pragma unroll
        for (int ks = 0; ks < 4; ks++) {
            uint32_t aph[4];
            aph[0] = pack2h(sacc[2*ks][0],   sacc[2*ks][1]);
            aph[1] = pack2h(sacc[2*ks][2],   sacc[2*ks][3]);
            aph[2] = pack2h(sacc[2*ks+1][0], sacc[2*ks+1][1]);
            aph[3] = pack2h(sacc[2*ks+1][2], sacc[2*ks+1][3]);
#pragma unroll
            for (int np = 0; np < 4; np++) {
                uint32_t vro = (ks * 16 + (lane & 7) + ((lane >> 3) & 1) * 8) * AT_RS
                               + np * 32 + (lane >> 4) * 16;
                uint32_t vh[4];
                LDSM_X4_T(vh[0], vh[1], vh[2], vh[3], sVh + vro);
                MMA16816(oacc[2*np],   aph[0], aph[1], aph[2], aph[3], vh[0], vh[1]);
                MMA16816(oacc[2*np+1], aph[0], aph[1], aph[2], aph[3], vh[2], vh[3]);
            }
        }
        __syncthreads();
    }

    // ---- epilogue: divide by l, plain fp16 store ----
    const float inv0 = 1.f / l0, inv1 = 1.f / l1;
    const size_t row0 = (size_t)(b * SEQ + r0g) * DMODEL;
    const size_t row1 = (size_t)(b * SEQ + r1g) * DMODEL;
#pragma unroll
    for (int t = 0; t < 8; t++) {
        const int c = h * DHEAD + t * 8 + 2 * (lane & 3);
        *(uint32_t*)&Oh[row0 + c] = pack2h(oacc[t][0] * inv0, oacc[t][1] * inv0);
        *(uint32_t*)&Oh[row1 + c] = pack2h(oacc[t][2] * inv1, oacc[t][3] * inv1);
    }
}

// ---------------------------------------------------------------------------
// Launch
// ---------------------------------------------------------------------------
extern "C" void kernel_launch(void* const* d_in, const int* in_sizes, int n_in,
                              void* d_out, int out_size)
{
    const float* X  = (const float*)d_in[0];
    const float* Wq = (const float*)d_in[1];
    const float* bq = (const float*)d_in[2];
    const float* Wk = (const float*)d_in[3];
    const float* bk = (const float*)d_in[4];
    const float* Wv = (const float*)d_in[5];
    const float* bv = (const float*)d_in[6];
    const float* Wo = (const float*)d_in[7];
    const float* bo = (const float*)d_in[8];
    float* out = (float*)d_out;

    __half *xhi, *qhi, *khi, *vhi, *aohi, *wthi;
    cudaGetSymbolAddress((void**)&xhi,  g_xhi);
    cudaGetSymbolAddress((void**)&qhi,  g_qhi);
    cudaGetSymbolAddress((void**)&khi,  g_khi);
    cudaGetSymbolAddress((void**)&vhi,  g_vhi);
    cudaGetSymbolAddress((void**)&aohi, g_aohi);
    cudaGetSymbolAddress((void**)&wthi, g_wthi);

    cudaFuncSetAttribute(attn_tc,  cudaFuncAttributeMaxDynamicSharedMemorySize, AT_SMEM);
    cudaFuncSetAttribute(gemm_qkv, cudaFuncAttributeMaxDynamicSharedMemorySize, Q_SMEM_B);
    cudaFuncSetAttribute(gemm_o,   cudaFuncAttributeMaxDynamicSharedMemorySize, Q_SMEM_B);

    // 1. prep: X convert + all 4 weight transposes in one launch
    prep_kernel<<<dim3(32, 32, 5), dim3(32, 8)>>>(X, Wq, Wk, Wv, Wo, xhi, wthi);

    // 2. fused Q/K/V projections (1-pass fp16)
    gemm_qkv<<<dim3(DMODEL / 128, MROWS / 128, 3), 256, Q_SMEM_B>>>(
        xhi, wthi, bq, bk, bv, qhi, khi, vhi, MROWS, DMODEL, DMODEL);

    // 3. tensor-core banded attention (1-pass QK/PV)
    attn_tc<<<dim3(SEQ / 64, NHEADS, BATCH), 128, AT_SMEM>>>(qhi, khi, vhi, aohi);

    // 4. O projection (1-pass) -> fp32 output
    gemm_o<<<dim3(DMODEL / 128, MROWS / 128), 256, Q_SMEM_B>>>(
        aohi, wthi + 3 * DD, bo, out, MROWS, DMODEL, DMODEL);
}

// round 9
// speedup vs baseline: 8.4511x; 1.0690x over previous
#include <cuda_runtime.h>
#include <cuda_fp16.h>
#include <cstdint>
#include <math.h>

// ---------------------------------------------------------------------------
// Problem constants (B=2, S=2048, D=1024, H=16)
// ---------------------------------------------------------------------------
#define BATCH   2
#define SEQ     2048
#define DMODEL  1024
#define NHEADS  16
#define DHEAD   64
#define WINDOW  256
#define MROWS   (BATCH * SEQ)   // 4096
#define DD      (DMODEL * DMODEL)

// ---------------------------------------------------------------------------
// Scratch (__device__ globals; allocation-free rule)
// ---------------------------------------------------------------------------
__device__ __half g_xhi [MROWS * DMODEL];
__device__ __half g_qhi [MROWS * DMODEL];
__device__ __half g_khi [MROWS * DMODEL];
__device__ __half g_vhi [MROWS * DMODEL];
__device__ __half g_aohi[MROWS * DMODEL];
__device__ __half g_wthi[4 * DD];   // transposed weights [N][K], fp16

// ---------------------------------------------------------------------------
// PTX helpers — base sm_100 ISA only (mma.sync / ldmatrix / cp.async)
// ---------------------------------------------------------------------------
__device__ __forceinline__ uint32_t smem_u32(const void* p) {
    uint32_t a;
    asm("{ .reg .u64 t; cvta.to.shared.u64 t, %1; cvt.u32.u64 %0, t; }" : "=r"(a) : "l"(p));
    return a;
}

#define CP_ASYNC16(dst, src) \
    asm volatile("cp.async.cg.shared.global [%0], [%1], 16;" :: "r"(dst), "l"(src))
#define CP_COMMIT() asm volatile("cp.async.commit_group;" ::: "memory")
#define CP_WAIT(n)  asm volatile("cp.async.wait_group %0;" :: "n"(n) : "memory")

#define LDSM_X4(r0, r1, r2, r3, addr) \
    asm volatile("ldmatrix.sync.aligned.m8n8.x4.shared.b16 {%0,%1,%2,%3}, [%4];" \
        : "=r"(r0), "=r"(r1), "=r"(r2), "=r"(r3) : "r"(addr))

#define LDSM_X4_T(r0, r1, r2, r3, addr) \
    asm volatile("ldmatrix.sync.aligned.m8n8.x4.trans.shared.b16 {%0,%1,%2,%3}, [%4];" \
        : "=r"(r0), "=r"(r1), "=r"(r2), "=r"(r3) : "r"(addr))

#define MMA16816(d, a0, a1, a2, a3, b0, b1) \
    asm volatile("mma.sync.aligned.m16n8k16.row.col.f32.f16.f16.f32 " \
        "{%0,%1,%2,%3}, {%4,%5,%6,%7}, {%8,%9}, {%0,%1,%2,%3};" \
        : "+f"((d)[0]), "+f"((d)[1]), "+f"((d)[2]), "+f"((d)[3]) \
        : "r"(a0), "r"(a1), "r"(a2), "r"(a3), "r"(b0), "r"(b1))

__device__ __forceinline__ uint32_t pack2h(float x, float y) {
    __half2 h2(__float2half_rn(x), __float2half_rn(y));
    return *(uint32_t*)&h2;
}

// ---------------------------------------------------------------------------
// Prep: z=0..3 -> weight transpose+cvt ([KxN] fp32 -> [NxK] fp16);
//       z=4    -> X fp32 -> fp16 elementwise convert.
// grid (32, 32, 5), block (32, 8)
// ---------------------------------------------------------------------------
__global__ __launch_bounds__(256) void prep_kernel(
    const float* __restrict__ X,
    const float* __restrict__ w0, const float* __restrict__ w1,
    const float* __restrict__ w2, const float* __restrict__ w3,
    __half* __restrict__ xh, __half* __restrict__ hi)
{
    const int z = blockIdx.z;
    const int tx = threadIdx.x, ty = threadIdx.y;

    if (z == 4) {
        const int bid = blockIdx.y * 32 + blockIdx.x;
        const int tid = ty * 32 + tx;
#pragma unroll
        for (int it = 0; it < 4; it++) {
            int i = bid * 1024 + it * 256 + tid;
            float4 v = ((const float4*)X)[i];
            ((uint32_t*)xh)[2*i]   = pack2h(v.x, v.y);
            ((uint32_t*)xh)[2*i+1] = pack2h(v.z, v.w);
        }
        return;
    }

    __shared__ float t[32][33];
    const float* in = (z == 0) ? w0 : (z == 1) ? w1 : (z == 2) ? w2 : w3;
    __half* oh = hi + (size_t)z * DD;
    int bx = blockIdx.x * 32, by = blockIdx.y * 32;
#pragma unroll
    for (int j = ty; j < 32; j += 8)
        t[j][tx] = in[(size_t)(by + j) * DMODEL + bx + tx];
    __syncthreads();
#pragma unroll
    for (int j = ty; j < 32; j += 8) {
        float v = t[tx][j];                 // = in[by+tx][bx+j]
        oh[(size_t)(bx + j) * DMODEL + by + tx] = __float2half_rn(v);
    }
}

// ---------------------------------------------------------------------------
// Shared GEMM mainloop structure (1-pass fp16, 128x128 tile, BK=32):
// 4-stage cp.async pipeline, ONE __syncthreads per chunk
// (issue ch+2 -> commit -> wait(2) -> sync -> compute; stage-overwrite race
//  is prevented by the previous iteration's barrier since NS=4 >= d+2 with d=2),
// batched fragment loads (all B for both k-steps, then all A per k-step).
// ---------------------------------------------------------------------------
#define G_RS       80          // row stride bytes (32 fp16 = 64B + 16B pad)
#define G_TILE_B   (128 * G_RS)          // 10240
#define Q_STAGE_B  (2 * G_TILE_B)        // Ah, Bh
#define Q_SMEM_B   (4 * Q_STAGE_B)       // 81920

// compute one 32-K chunk from stage base s0 into acc
#define GEMM_CHUNK(s0)                                                          \
    do {                                                                        \
        const uint32_t sAh = (s0), sBh = (s0) + G_TILE_B;                       \
        uint32_t bfr[2][4][2];                                                  \
        _Pragma("unroll")                                                       \
        for (int ks = 0; ks < 2; ks++) {                                        \
            const uint32_t kb = ks * 32;                                        \
            _Pragma("unroll")                                                   \
            for (int np = 0; np < 2; np++) {                                    \
                uint32_t ro = (wn0 + np * 16 + (lane & 7) + ((lane >> 4) & 1) * 8) * G_RS \
                              + kb + ((lane >> 3) & 1) * 16;                    \
                LDSM_X4(bfr[ks][np*2][0], bfr[ks][np*2][1],                     \
                        bfr[ks][np*2+1][0], bfr[ks][np*2+1][1], sBh + ro);      \
            }                                                                   \
        }                                                                       \
        _Pragma("unroll")                                                       \
        for (int ks = 0; ks < 2; ks++) {                                        \
            const uint32_t kb = ks * 32;                                        \
            uint32_t afr[4][4];                                                 \
            _Pragma("unroll")                                                   \
            for (int mi = 0; mi < 4; mi++) {                                    \
                uint32_t ro = (wm0 + mi * 16 + (lane & 15)) * G_RS + kb + (lane >> 4) * 16; \
                LDSM_X4(afr[mi][0], afr[mi][1], afr[mi][2], afr[mi][3], sAh + ro); \
            }                                                                   \
            _Pragma("unroll")                                                   \
            for (int mi = 0; mi < 4; mi++)                                      \
                _Pragma("unroll")                                               \
                for (int ni = 0; ni < 4; ni++)                                  \
                    MMA16816(acc[mi][ni], afr[mi][0], afr[mi][1], afr[mi][2],   \
                             afr[mi][3], bfr[ks][ni][0], bfr[ks][ni][1]);       \
        }                                                                       \
    } while (0)

// ---------------------------------------------------------------------------
// QKV GEMM: grid (N/128, M/128, 3); z selects W/bias/output; fp16 out.
// ---------------------------------------------------------------------------
__global__ __launch_bounds__(256, 2) void gemm_qkv(
    const __half* __restrict__ Ahi, const __half* __restrict__ Wt,
    const float* __restrict__ bq, const float* __restrict__ bk,
    const float* __restrict__ bv,
    __half* __restrict__ Qhi, __half* __restrict__ Khi, __half* __restrict__ Vhi,
    int M, int N, int K)
{
    extern __shared__ char smem[];
    const uint32_t sb = smem_u32(smem);
    const int z = blockIdx.z;
    const __half* Bh = Wt + (size_t)z * DD;
    const float* bias = (z == 0) ? bq : (z == 1) ? bk : bv;
    __half* Chi = (z == 0) ? Qhi : (z == 1) ? Khi : Vhi;

    const int tid = threadIdx.x, lane = tid & 31, wid = tid >> 5;
    const int brow = blockIdx.y * 128, bcol = blockIdx.x * 128;
    const int wm0 = (wid & 1) * 64;
    const int wn0 = (wid >> 1) * 32;

    float acc[4][4][4];
#pragma unroll
    for (int mi = 0; mi < 4; mi++)
#pragma unroll
        for (int ni = 0; ni < 4; ni++)
#pragma unroll
            for (int e = 0; e < 4; e++) acc[mi][ni][e] = 0.f;

    const int r0l = tid >> 2, c16a = (tid & 3) * 8;
    const int r1l = (tid + 256) >> 2;
    const int nchunks = K / 32;

    auto issue_load = [&](int st, int kt) {
        uint32_t s0 = sb + st * Q_STAGE_B;
#pragma unroll
        for (int u = 0; u < 2; u++) {
            int row = u ? r1l : r0l;
            uint32_t so = row * G_RS + c16a * 2;
            CP_ASYNC16(s0 + 0 * G_TILE_B + so, Ahi + (size_t)(brow + row) * K + kt + c16a);
            CP_ASYNC16(s0 + 1 * G_TILE_B + so, Bh  + (size_t)(bcol + row) * K + kt + c16a);
        }
    };

    issue_load(0, 0);  CP_COMMIT();
    issue_load(1, 32); CP_COMMIT();

    for (int ch = 0; ch < nchunks; ch++) {
        if (ch + 2 < nchunks) {
            issue_load((ch + 2) & 3, (ch + 2) * 32);
            CP_COMMIT();
            CP_WAIT(2);
        } else if (ch + 1 < nchunks) {
            CP_WAIT(1);
        } else {
            CP_WAIT(0);
        }
        __syncthreads();
        GEMM_CHUNK(sb + (ch & 3) * Q_STAGE_B);
    }

    // epilogue: fp16 out
#pragma unroll
    for (int mi = 0; mi < 4; mi++) {
#pragma unroll
        for (int ni = 0; ni < 4; ni++) {
            int r = brow + wm0 + mi * 16 + (lane >> 2);
            int c = bcol + wn0 + ni * 8 + (lane & 3) * 2;
            float bx = bias[c], by = bias[c + 1];
            *(uint32_t*)&Chi[(size_t)r * N + c] =
                pack2h(acc[mi][ni][0] + bx, acc[mi][ni][1] + by);
            *(uint32_t*)&Chi[(size_t)(r + 8) * N + c] =
                pack2h(acc[mi][ni][2] + bx, acc[mi][ni][3] + by);
        }
    }
}

// ---------------------------------------------------------------------------
// O-projection GEMM: fp32 out; same mainloop.
// ---------------------------------------------------------------------------
__global__ __launch_bounds__(256, 2) void gemm_o(
    const __half* __restrict__ Ahi, const __half* __restrict__ Bhi,
    const float* __restrict__ bias, float* __restrict__ C,
    int M, int N, int K)
{
    extern __shared__ char smem[];
    const uint32_t sb = smem_u32(smem);
    const int tid = threadIdx.x, lane = tid & 31, wid = tid >> 5;
    const int brow = blockIdx.y * 128, bcol = blockIdx.x * 128;
    const int wm0 = (wid & 1) * 64;
    const int wn0 = (wid >> 1) * 32;

    float acc[4][4][4];
#pragma unroll
    for (int mi = 0; mi < 4; mi++)
#pragma unroll
        for (int ni = 0; ni < 4; ni++)
#pragma unroll
            for (int e = 0; e < 4; e++) acc[mi][ni][e] = 0.f;

    const int r0l = tid >> 2, c16a = (tid & 3) * 8;
    const int r1l = (tid + 256) >> 2;
    const int nchunks = K / 32;

    auto issue_load = [&](int st, int kt) {
        uint32_t s0 = sb + st * Q_STAGE_B;
#pragma unroll
        for (int u = 0; u < 2; u++) {
            int row = u ? r1l : r0l;
            uint32_t so = row * G_RS + c16a * 2;
            CP_ASYNC16(s0 + 0 * G_TILE_B + so, Ahi + (size_t)(brow + row) * K + kt + c16a);
            CP_ASYNC16(s0 + 1 * G_TILE_B + so, Bhi + (size_t)(bcol + row) * K + kt + c16a);
        }
    };

    issue_load(0, 0);  CP_COMMIT();
    issue_load(1, 32); CP_COMMIT();

    for (int ch = 0; ch < nchunks; ch++) {
        if (ch + 2 < nchunks) {
            issue_load((ch + 2) & 3, (ch + 2) * 32);
            CP_COMMIT();
            CP_WAIT(2);
        } else if (ch + 1 < nchunks) {
            CP_WAIT(1);
        } else {
            CP_WAIT(0);
        }
        __syncthreads();
        GEMM_CHUNK(sb + (ch & 3) * Q_STAGE_B);
    }

#pragma unroll
    for (int mi = 0; mi < 4; mi++) {
#pragma unroll
        for (int ni = 0; ni < 4; ni++) {
            int r = brow + wm0 + mi * 16 + (lane >> 2);
            int c = bcol + wn0 + ni * 8 + (lane & 3) * 2;
            float bx = bias[c], by = bias[c + 1];
            *(float2*)&C[(size_t)r * N + c] =
                make_float2(acc[mi][ni][0] + bx, acc[mi][ni][1] + by);
            *(float2*)&C[(size_t)(r + 8) * N + c] =
                make_float2(acc[mi][ni][2] + bx, acc[mi][ni][3] + by);
        }
    }
}

// ---------------------------------------------------------------------------
// Tensor-core banded attention (fp16, 1-pass QK and PV).
// grid = (S/64, H, B), block = 128 (4 warps x 16 q-rows). fp16 output.
// ---------------------------------------------------------------------------
#define AT_RS    144                 // smem row stride bytes (72 fp16)
#define AT_TILE  (64 * AT_RS)        // 9216 B
#define AT_SQH   0
#define AT_ST0   AT_TILE
#define AT_STB   (2 * AT_TILE)       // Kh, Vh per stage
#define AT_SMEM  (AT_TILE + 2 * AT_STB)   // 46080 B

__global__ __launch_bounds__(128) void attn_tc(
    const __half* __restrict__ Qh, const __half* __restrict__ Kh,
    const __half* __restrict__ Vh, __half* __restrict__ Oh)
{
    extern __shared__ char smem[];
    const uint32_t sb = smem_u32(smem);
    const int qt = blockIdx.x, h = blockIdx.y, b = blockIdx.z;
    const int q0 = qt * 64;
    const int tid = threadIdx.x, lane = tid & 31, w = tid >> 5;
    const float scale = 0.125f;

    const int lrow = tid >> 1;
    const int lhalf = (tid & 1) * 64;
    const int gcol = h * DHEAD + (lhalf >> 1);

    const int kb_lo = max(0, q0 - (WINDOW - 1)) >> 6;
    const int nch = qt - kb_lo + 1;

    // prologue: Q + first K/V chunk
    {
        size_t g = ((size_t)(b * SEQ + q0 + lrow)) * DMODEL + gcol;
        uint32_t so = lrow * AT_RS + lhalf;
#pragma unroll
        for (int i = 0; i < 4; i++)
            CP_ASYNC16(sb + AT_SQH + so + i * 16, Qh + g + i * 8);
        size_t gk = ((size_t)(b * SEQ + kb_lo * 64 + lrow)) * DMODEL + gcol;
        uint32_t s0 = sb + AT_ST0;
#pragma unroll
        for (int i = 0; i < 4; i++) {
            CP_ASYNC16(s0 + 0 * AT_TILE + so + i * 16, Kh + gk + i * 8);
            CP_ASYNC16(s0 + 1 * AT_TILE + so + i * 16, Vh + gk + i * 8);
        }
        CP_COMMIT();
    }

    float m0 = -1e30f, m1 = -1e30f, l0 = 0.f, l1 = 0.f;
    float oacc[8][4];
#pragma unroll
    for (int t = 0; t < 8; t++)
#pragma unroll
        for (int e = 0; e < 4; e++) oacc[t][e] = 0.f;

    const int r0g = q0 + w * 16 + (lane >> 2);
    const int r1g = r0g + 8;

    for (int i = 0; i < nch; i++) {
        const int kb = kb_lo + i;
        if (i + 1 < nch) {
            size_t gk = ((size_t)(b * SEQ + (kb + 1) * 64 + lrow)) * DMODEL + gcol;
            uint32_t s0 = sb + AT_ST0 + ((i + 1) & 1) * AT_STB;
            uint32_t so = lrow * AT_RS + lhalf;
#pragma unroll
            for (int u = 0; u < 4; u++) {
                CP_ASYNC16(s0 + 0 * AT_TILE + so + u * 16, Kh + gk + u * 8);
                CP_ASYNC16(s0 + 1 * AT_TILE + so + u * 16, Vh + gk + u * 8);
            }
            CP_COMMIT();
            CP_WAIT(1);
        } else {
            CP_WAIT(0);
        }
        __syncthreads();

        const uint32_t s0  = sb + AT_ST0 + (i & 1) * AT_STB;
        const uint32_t sKh = s0;
        const uint32_t sVh = s0 + AT_TILE;

        // ---- S = Q K^T (1-pass) ----
        float sacc[8][4];
#pragma unroll
        for (int t = 0; t < 8; t++)
#pragma unroll
            for (int e = 0; e < 4; e++) sacc[t][e] = 0.f;

#pragma unroll
        for (int ks = 0; ks < 4; ks++) {
            const uint32_t kbb = ks * 32;
            uint32_t aro = (w * 16 + (lane & 15)) * AT_RS + kbb + (lane >> 4) * 16;
            uint32_t ah[4];
            LDSM_X4(ah[0], ah[1], ah[2], ah[3], sb + AT_SQH + aro);
#pragma unroll
            for (int np = 0; np < 4; np++) {
                uint32_t ro = (np * 16 + (lane & 7) + ((lane >> 4) & 1) * 8) * AT_RS
                              + kbb + ((lane >> 3) & 1) * 16;
                uint32_t bh[4];
                LDSM_X4(bh[0], bh[1], bh[2], bh[3], sKh + ro);
                MMA16816(sacc[2*np],   ah[0], ah[1], ah[2], ah[3], bh[0], bh[1]);
                MMA16816(sacc[2*np+1], ah[0], ah[1], ah[2], ah[3], bh[2], bh[3]);
            }
        }

        // ---- mask + online softmax ----
        const int kbase = kb * 64;
        float cmax0 = -1e30f, cmax1 = -1e30f;
#pragma unroll
        for (int t = 0; t < 8; t++) {
            const int c0 = kbase + t * 8 + 2 * (lane & 3);
            int d00 = r0g - c0, d01 = r0g - (c0 + 1);
            int d10 = r1g - c0, d11 = r1g - (c0 + 1);
            sacc[t][0] = (d00 >= 0 && d00 < WINDOW) ? sacc[t][0] * scale : -1e30f;
            sacc[t][1] = (d01 >= 0 && d01 < WINDOW) ? sacc[t][1] * scale : -1e30f;
            sacc[t][2] = (d10 >= 0 && d10 < WINDOW) ? sacc[t][2] * scale : -1e30f;
            sacc[t][3] = (d11 >= 0 && d11 < WINDOW) ? sacc[t][3] * scale : -1e30f;
            cmax0 = fmaxf(cmax0, fmaxf(sacc[t][0], sacc[t][1]));
            cmax1 = fmaxf(cmax1, fmaxf(sacc[t][2], sacc[t][3]));
        }
        cmax0 = fmaxf(cmax0, __shfl_xor_sync(0xffffffffu, cmax0, 1));
        cmax0 = fmaxf(cmax0, __shfl_xor_sync(0xffffffffu, cmax0, 2));
        cmax1 = fmaxf(cmax1, __shfl_xor_sync(0xffffffffu, cmax1, 1));
        cmax1 = fmaxf(cmax1, __shfl_xor_sync(0xffffffffu, cmax1, 2));

        float mn0 = fmaxf(m0, cmax0), mn1 = fmaxf(m1, cmax1);
        float a0 = __expf(m0 - mn0), a1 = __expf(m1 - mn1);
        float rs0 = 0.f, rs1 = 0.f;
#pragma unroll
        for (int t = 0; t < 8; t++) {
            sacc[t][0] = __expf(sacc[t][0] - mn0);
            sacc[t][1] = __expf(sacc[t][1] - mn0);
            sacc[t][2] = __expf(sacc[t][2] - mn1);
            sacc[t][3] = __expf(sacc[t][3] - mn1);
            rs0 += sacc[t][0] + sacc[t][1];
            rs1 += sacc[t][2] + sacc[t][3];
        }
        rs0 += __shfl_xor_sync(0xffffffffu, rs0, 1);
        rs0 += __shfl_xor_sync(0xffffffffu, rs0, 2);
        rs1 += __shfl_xor_sync(0xffffffffu, rs1, 1);
        rs1 += __shfl_xor_sync(0xffffffffu, rs1, 2);
        l0 = l0 * a0 + rs0;  m0 = mn0;
        l1 = l1 * a1 + rs1;  m1 = mn1;
#pragma unroll
        for (int t = 0; t < 8; t++) {
            oacc[t][0] *= a0; oacc[t][1] *= a0;
            oacc[t][2] *= a1; oacc[t][3] *= a1;
        }

        // ---- PV (1-pass: P rounded to fp16; V via ldmatrix.trans) ----
#pragma unroll
        for (int ks = 0; ks < 4; ks++) {
            uint32_t aph[4];
            aph[0] = pack2h(sacc[2*ks][0],   sacc[2*ks][1]);
            aph[1] = pack2h(sacc[2*ks][2],   sacc[2*ks][3]);
            aph[2] = pack2h(sacc[2*ks+1][0], sacc[2*ks+1][1]);
            aph[3] = pack2h(sacc[2*ks+1][2], sacc[2*ks+1][3]);
#pragma unroll
            for (int np = 0; np < 4; np++) {
                uint32_t vro = (ks * 16 + (lane & 7) + ((lane >> 3) & 1) * 8) * AT_RS
                               + np * 32 + (lane >> 4) * 16;
                uint32_t vh[4];
                LDSM_X4_T(vh[0], vh[1], vh[2], vh[3], sVh + vro);
                MMA16816(oacc[2*np],   aph[0], aph[1], aph[2], aph[3], vh[0], vh[1]);
                MMA16816(oacc[2*np+1], aph[0], aph[1], aph[2], aph[3], vh[2], vh[3]);
            }
        }
        __syncthreads();
    }

    // ---- epilogue: divide by l, plain fp16 store ----
    const float inv0 = 1.f / l0, inv1 = 1.f / l1;
    const size_t row0 = (size_t)(b * SEQ + r0g) * DMODEL;
    const size_t row1 = (size_t)(b * SEQ + r1g) * DMODEL;
#pragma unroll
    for (int t = 0; t < 8; t++) {
        const int c = h * DHEAD + t * 8 + 2 * (lane & 3);
        *(uint32_t*)&Oh[row0 + c] = pack2h(oacc[t][0] * inv0, oacc[t][1] * inv0);
        *(uint32_t*)&Oh[row1 + c] = pack2h(oacc[t][2] * inv1, oacc[t][3] * inv1);
    }
}

// ---------------------------------------------------------------------------
// Launch
// ---------------------------------------------------------------------------
extern "C" void kernel_launch(void* const* d_in, const int* in_sizes, int n_in,
                              void* d_out, int out_size)
{
    const float* X  = (const float*)d_in[0];
    const float* Wq = (const float*)d_in[1];
    const float* bq = (const float*)d_in[2];
    const float* Wk = (const float*)d_in[3];
    const float* bk = (const float*)d_in[4];
    const float* Wv = (const float*)d_in[5];
    const float* bv = (const float*)d_in[6];
    const float* Wo = (const float*)d_in[7];
    const float* bo = (const float*)d_in[8];
    float* out = (float*)d_out;

    __half *xhi, *qhi, *khi, *vhi, *aohi, *wthi;
    cudaGetSymbolAddress((void**)&xhi,  g_xhi);
    cudaGetSymbolAddress((void**)&qhi,  g_qhi);
    cudaGetSymbolAddress((void**)&khi,  g_khi);
    cudaGetSymbolAddress((void**)&vhi,  g_vhi);
    cudaGetSymbolAddress((void**)&aohi, g_aohi);
    cudaGetSymbolAddress((void**)&wthi, g_wthi);

    cudaFuncSetAttribute(attn_tc,  cudaFuncAttributeMaxDynamicSharedMemorySize, AT_SMEM);
    cudaFuncSetAttribute(gemm_qkv, cudaFuncAttributeMaxDynamicSharedMemorySize, Q_SMEM_B);
    cudaFuncSetAttribute(gemm_o,   cudaFuncAttributeMaxDynamicSharedMemorySize, Q_SMEM_B);

    // 1. prep: X convert + all 4 weight transposes in one launch
    prep_kernel<<<dim3(32, 32, 5), dim3(32, 8)>>>(X, Wq, Wk, Wv, Wo, xhi, wthi);

    // 2. fused Q/K/V projections (1-pass fp16)
    gemm_qkv<<<dim3(DMODEL / 128, MROWS / 128, 3), 256, Q_SMEM_B>>>(
        xhi, wthi, bq, bk, bv, qhi, khi, vhi, MROWS, DMODEL, DMODEL);

    // 3. tensor-core banded attention (1-pass QK/PV)
    attn_tc<<<dim3(SEQ / 64, NHEADS, BATCH), 128, AT_SMEM>>>(qhi, khi, vhi, aohi);

    // 4. O projection (1-pass) -> fp32 output
    gemm_o<<<dim3(DMODEL / 128, MROWS / 128), 256, Q_SMEM_B>>>(
        aohi, wthi + 3 * DD, bo, out, MROWS, DMODEL, DMODEL);
}